// round 6
// baseline (speedup 1.0000x reference)
#include <cuda_runtime.h>
#include <cuda_bf16.h>
#include <math.h>
#include <cstdint>

#define Bb 2
#define Nn 160
#define Cc 256
#define Hh 8
#define Dd 32
#define ROWS (Bb*Nn*Nn)   // 51200
#define GK 256            // inner K of all GEMMs

// ---------------- scratch (__device__ globals; no allocation allowed) ----------------
__device__ float g_qkv[(size_t)ROWS*768];
__device__ float g_proj[(size_t)ROWS*Cc];
__device__ float g_x1[(size_t)ROWS*Cc];
__device__ __nv_bfloat16 g_Ah[(size_t)ROWS*GK];
__device__ __nv_bfloat16 g_Al[(size_t)ROWS*GK];
__device__ __nv_bfloat16 g_Bt[(size_t)768*2*GK];   // [Nc, 2K]: cols [0,K)=hi, [K,2K)=lo

__device__ __forceinline__ uint32_t smem_u32(const void* p) {
    uint32_t a;
    asm("{ .reg .u64 t; cvta.to.shared.u64 t, %1; cvt.u32.u64 %0, t; }" : "=r"(a) : "l"(p));
    return a;
}
#define CP16(d, s) asm volatile("cp.async.cg.shared.global [%0], [%1], 16;" :: "r"(d), "l"(s))
#define CP_COMMIT  asm volatile("cp.async.commit_group;" ::: "memory")

__device__ __forceinline__ uint32_t bpack(__nv_bfloat16 a, __nv_bfloat16 b) {
    __nv_bfloat162 t(a, b);
    return *reinterpret_cast<uint32_t*>(&t);
}

// ---------------- split kernels: fp32 -> bf16 hi/lo ----------------
__global__ __launch_bounds__(256) void splitA(const float4* __restrict__ X,
                                              __nv_bfloat16* __restrict__ Ah,
                                              __nv_bfloat16* __restrict__ Al, int n4) {
    int i = blockIdx.x * blockDim.x + threadIdx.x;
    if (i >= n4) return;
    float4 x = X[i];
    __nv_bfloat16 h0 = __float2bfloat16(x.x), h1 = __float2bfloat16(x.y);
    __nv_bfloat16 h2 = __float2bfloat16(x.z), h3 = __float2bfloat16(x.w);
    __nv_bfloat16 l0 = __float2bfloat16(x.x - __bfloat162float(h0));
    __nv_bfloat16 l1 = __float2bfloat16(x.y - __bfloat162float(h1));
    __nv_bfloat16 l2 = __float2bfloat16(x.z - __bfloat162float(h2));
    __nv_bfloat16 l3 = __float2bfloat16(x.w - __bfloat162float(h3));
    reinterpret_cast<__nv_bfloat162*>(Ah)[i * 2 + 0] = __nv_bfloat162(h0, h1);
    reinterpret_cast<__nv_bfloat162*>(Ah)[i * 2 + 1] = __nv_bfloat162(h2, h3);
    reinterpret_cast<__nv_bfloat162*>(Al)[i * 2 + 0] = __nv_bfloat162(l0, l1);
    reinterpret_cast<__nv_bfloat162*>(Al)[i * 2 + 1] = __nv_bfloat162(l2, l3);
}

// W [K, Nc] row-major -> Bt [Nc, 2K]: Bt[n, k] = hi(W[k,n]), Bt[n, K+k] = lo(W[k,n])
__global__ __launch_bounds__(256) void splitB(const float* __restrict__ W,
                                              __nv_bfloat16* __restrict__ Bt, int Nc) {
    int idx = blockIdx.x * blockDim.x + threadIdx.x;
    if (idx >= GK * Nc) return;
    int k = idx / Nc, n = idx % Nc;
    float x = W[idx];
    __nv_bfloat16 h = __float2bfloat16(x);
    Bt[(size_t)n * (2 * GK) + k]      = h;
    Bt[(size_t)n * (2 * GK) + GK + k] = __float2bfloat16(x - __bfloat162float(h));
}

// ---------------- bf16 mma.sync GEMM: C[M,Nc] = A @ W (fp32 via 3-split) ----------------
#define SSTR 40   // smem row stride in bf16 elems

__global__ __launch_bounds__(256) void gemm_mma(const __nv_bfloat16* __restrict__ Ah,
                                                const __nv_bfloat16* __restrict__ Al,
                                                const __nv_bfloat16* __restrict__ Bt,
                                                float* __restrict__ C, int Nc) {
    __shared__ __align__(16) __nv_bfloat16 As[2][128 * SSTR];
    __shared__ __align__(16) __nv_bfloat16 Bs[2][128 * SSTR];

    const int tid = threadIdx.x;
    const int wid = tid >> 5, l = tid & 31;
    const int wm = (wid & 3) * 32;
    const int wn = (wid >> 2) * 64;
    const int bm = blockIdx.y * 128, bn = blockIdx.x * 128;

    float acc[2][8][4];
#pragma unroll
    for (int mt = 0; mt < 2; mt++)
#pragma unroll
        for (int nt = 0; nt < 8; nt++)
#pragma unroll
            for (int r = 0; r < 4; r++) acc[mt][nt][r] = 0.f;

    auto load_chunk = [&](int c, int st) {
        const int blk = c >> 3;                 // 0: Ah*Bh  1: Ah*Bl  2: Al*Bh
        const int k0 = (c & 7) * 32;
        const __nv_bfloat16* Ap = (blk < 2 ? Ah : Al);
        const __nv_bfloat16* Bp = Bt + (blk == 1 ? GK : 0);
#pragma unroll
        for (int w = 0; w < 2; w++) {
            int idx = tid + w * 256;
            int row = idx >> 2, seg = (idx & 3) * 8;
            CP16(smem_u32(&As[st][row * SSTR + seg]),
                 Ap + (size_t)(bm + row) * GK + k0 + seg);
            CP16(smem_u32(&Bs[st][row * SSTR + seg]),
                 Bp + (size_t)(bn + row) * (2 * GK) + k0 + seg);
        }
        CP_COMMIT;
    };

    load_chunk(0, 0);

    for (int c = 0; c < 24; c++) {
        const int st = c & 1;
        if (c + 1 < 24) {
            load_chunk(c + 1, st ^ 1);
            asm volatile("cp.async.wait_group 1;" ::: "memory");
        } else {
            asm volatile("cp.async.wait_group 0;" ::: "memory");
        }
        __syncthreads();

        const uint32_t aBase = smem_u32(&As[st][0]);
        const uint32_t bBase = smem_u32(&Bs[st][0]);
#pragma unroll
        for (int ks = 0; ks < 32; ks += 16) {
            uint32_t a[2][4];
#pragma unroll
            for (int mt = 0; mt < 2; mt++) {
                uint32_t addr = aBase +
                    (((wm + mt * 16 + (l & 15)) * SSTR) + ks + ((l >> 4) << 3)) * 2;
                asm volatile("ldmatrix.sync.aligned.m8n8.x4.shared.b16 {%0,%1,%2,%3}, [%4];"
                             : "=r"(a[mt][0]), "=r"(a[mt][1]), "=r"(a[mt][2]), "=r"(a[mt][3])
                             : "r"(addr));
            }
            uint32_t b[8][2];
#pragma unroll
            for (int p = 0; p < 4; p++) {
                uint32_t addr = bBase +
                    (((wn + p * 16 + (l & 7) + ((l >> 4) << 3)) * SSTR) +
                     ks + (((l >> 3) & 1) << 3)) * 2;
                asm volatile("ldmatrix.sync.aligned.m8n8.x4.shared.b16 {%0,%1,%2,%3}, [%4];"
                             : "=r"(b[p * 2][0]), "=r"(b[p * 2][1]),
                               "=r"(b[p * 2 + 1][0]), "=r"(b[p * 2 + 1][1])
                             : "r"(addr));
            }
#pragma unroll
            for (int mt = 0; mt < 2; mt++)
#pragma unroll
                for (int nt = 0; nt < 8; nt++)
                    asm volatile(
                        "mma.sync.aligned.m16n8k16.row.col.f32.bf16.bf16.f32 "
                        "{%0,%1,%2,%3}, {%4,%5,%6,%7}, {%8,%9}, {%0,%1,%2,%3};"
                        : "+f"(acc[mt][nt][0]), "+f"(acc[mt][nt][1]),
                          "+f"(acc[mt][nt][2]), "+f"(acc[mt][nt][3])
                        : "r"(a[mt][0]), "r"(a[mt][1]), "r"(a[mt][2]), "r"(a[mt][3]),
                          "r"(b[nt][0]), "r"(b[nt][1]));
        }
        __syncthreads();
    }

#pragma unroll
    for (int mt = 0; mt < 2; mt++) {
        const int row = bm + wm + mt * 16 + (l >> 2);
#pragma unroll
        for (int nt = 0; nt < 8; nt++) {
            const int col = bn + wn + nt * 8 + (l & 3) * 2;
            *reinterpret_cast<float2*>(C + (size_t)row * Nc + col) =
                make_float2(acc[mt][nt][0], acc[mt][nt][1]);
            *reinterpret_cast<float2*>(C + (size_t)(row + 8) * Nc + col) =
                make_float2(acc[mt][nt][2], acc[mt][nt][3]);
        }
    }
}

// ---------------- Fused attention per (b, m, h): d-split thread pairs ----------------
// 320 threads: thread t -> row i = t>>1, d-half = t&1 (16 of 32 dims).
// Full dot recovered with one shfl_xor within the lane pair.
__global__ __launch_bounds__(2*Nn, 4) void attn_kernel(const float* __restrict__ qkv,
                                                  const float* __restrict__ map,
                                                  const float* __restrict__ bw,
                                                  const float* __restrict__ bb,
                                                  __nv_bfloat16* __restrict__ Ah,
                                                  __nv_bfloat16* __restrict__ Al,
                                                  int si, int sj) {
    const int h = blockIdx.x;
    const int m = blockIdx.y;
    const int b = blockIdx.z;
    const int t = threadIdx.x;
    const int i = t >> 1;
    const int half = t & 1;

    __shared__ float4 ks[Nn][9];   // [row][8 float4 = 32 dims], +1 pad
    __shared__ float4 vs[Nn][9];

    const size_t rowbase = ((size_t)b * Nn + m) * Nn;
    const float scale = 0.17677669529663687f;

    // each thread loads its half-row of K/V and its half of Q
    const float4* qp = reinterpret_cast<const float4*>(qkv + (rowbase + i) * 768 + h * Dd + half * 16);
    const float4* kp = reinterpret_cast<const float4*>(qkv + (rowbase + i) * 768 + 256 + h * Dd + half * 16);
    const float4* vp = reinterpret_cast<const float4*>(qkv + (rowbase + i) * 768 + 512 + h * Dd + half * 16);

    float4 q4[4];
#pragma unroll
    for (int c = 0; c < 4; c++) {
        ks[i][half * 4 + c] = kp[c];
        vs[i][half * 4 + c] = vp[c];
        float4 tq = qp[c];
        tq.x *= scale; tq.y *= scale; tq.z *= scale; tq.w *= scale;
        q4[c] = tq;
    }
    __syncthreads();

    const float wv = bw[h];
    const float bv = bb[h];
    const float* mp = map + (size_t)b * Nn * Nn + (size_t)i * si;

    float mi = -INFINITY, li = 0.f;
    float4 acc4[4];
#pragma unroll
    for (int c = 0; c < 4; c++) acc4[c] = make_float4(0.f, 0.f, 0.f, 0.f);

    for (int j = 0; j < Nn; j++) {
        float s0 = 0.f, s1 = 0.f;
#pragma unroll
        for (int c = 0; c < 4; c += 2) {
            float4 k0 = ks[j][half * 4 + c];
            float4 k1 = ks[j][half * 4 + c + 1];
            s0 += q4[c].x * k0.x + q4[c].y * k0.y + q4[c].z * k0.z + q4[c].w * k0.w;
            s1 += q4[c + 1].x * k1.x + q4[c + 1].y * k1.y + q4[c + 1].z * k1.z + q4[c + 1].w * k1.w;
        }
        float s = s0 + s1;
        s += __shfl_xor_sync(0xffffffffu, s, 1);   // combine the two d-halves
        s += mp[(size_t)j * sj] * wv + bv;

        if (s > mi) {
            float f = __expf(mi - s);
            li *= f;
#pragma unroll
            for (int c = 0; c < 4; c++) {
                acc4[c].x *= f; acc4[c].y *= f; acc4[c].z *= f; acc4[c].w *= f;
            }
            mi = s;
        }
        float p = __expf(s - mi);
        li += p;
#pragma unroll
        for (int c = 0; c < 4; c++) {
            float4 vv = vs[j][half * 4 + c];
            acc4[c].x += p * vv.x; acc4[c].y += p * vv.y;
            acc4[c].z += p * vv.z; acc4[c].w += p * vv.w;
        }
    }

    const float inv = 1.f / li;
    uint32_t wh[8], wl[8];
#pragma unroll
    for (int c = 0; c < 4; c++) {
        float o0 = acc4[c].x * inv, o1 = acc4[c].y * inv;
        float o2 = acc4[c].z * inv, o3 = acc4[c].w * inv;
        __nv_bfloat16 h0 = __float2bfloat16(o0), h1 = __float2bfloat16(o1);
        __nv_bfloat16 h2 = __float2bfloat16(o2), h3 = __float2bfloat16(o3);
        wh[c * 2 + 0] = bpack(h0, h1);
        wh[c * 2 + 1] = bpack(h2, h3);
        wl[c * 2 + 0] = bpack(__float2bfloat16(o0 - __bfloat162float(h0)),
                              __float2bfloat16(o1 - __bfloat162float(h1)));
        wl[c * 2 + 1] = bpack(__float2bfloat16(o2 - __bfloat162float(h2)),
                              __float2bfloat16(o3 - __bfloat162float(h3)));
    }
    uint4* ahp = reinterpret_cast<uint4*>(Ah + (rowbase + i) * GK + h * Dd + half * 16);
    uint4* alp = reinterpret_cast<uint4*>(Al + (rowbase + i) * GK + h * Dd + half * 16);
#pragma unroll
    for (int c = 0; c < 2; c++) {
        ahp[c] = make_uint4(wh[c * 4], wh[c * 4 + 1], wh[c * 4 + 2], wh[c * 4 + 3]);
        alp[c] = make_uint4(wl[c * 4], wl[c * 4 + 1], wl[c * 4 + 2], wl[c * 4 + 3]);
    }
}

// ---------------- Residual + LayerNorm; transposed write; optional bf16 hi/lo emit ----------------
__global__ __launch_bounds__(Cc) void ln_kernel(const float* __restrict__ xin,
                                                const float* __restrict__ proj,
                                                const float* __restrict__ g,
                                                const float* __restrict__ bt,
                                                float* __restrict__ out,
                                                __nv_bfloat16* __restrict__ Ah,
                                                __nv_bfloat16* __restrict__ Al) {
    const int r = blockIdx.x;
    const int c = threadIdx.x;
    const float v = xin[(size_t)r * Cc + c] + proj[(size_t)r * Cc + c];

    float s = v, s2 = v * v;
#pragma unroll
    for (int o = 16; o > 0; o >>= 1) {
        s  += __shfl_down_sync(0xffffffffu, s, o);
        s2 += __shfl_down_sync(0xffffffffu, s2, o);
    }
    __shared__ float ws[8], ws2[8];
    const int w = c >> 5, l = c & 31;
    if (l == 0) { ws[w] = s; ws2[w] = s2; }
    __syncthreads();
    if (w == 0) {
        s  = (l < 8) ? ws[l]  : 0.f;
        s2 = (l < 8) ? ws2[l] : 0.f;
#pragma unroll
        for (int o = 4; o > 0; o >>= 1) {
            s  += __shfl_down_sync(0xffffffffu, s, o);
            s2 += __shfl_down_sync(0xffffffffu, s2, o);
        }
        if (l == 0) { ws[0] = s; ws2[0] = s2; }
    }
    __syncthreads();
    const float mean = ws[0] * (1.f / Cc);
    const float var  = ws2[0] * (1.f / Cc) - mean * mean;
    const float rs   = rsqrtf(var + 1e-5f);

    const int bidx = r / (Nn * Nn);
    const int rem  = r % (Nn * Nn);
    const int mm   = rem / Nn;
    const int ii   = rem % Nn;
    const size_t rt = ((size_t)bidx * Nn + ii) * Nn + mm;
    const float y = (v - mean) * rs * g[c] + bt[c];
    out[rt * Cc + c] = y;
    if (Ah) {
        __nv_bfloat16 hh = __float2bfloat16(y);
        Ah[rt * GK + c] = hh;
        Al[rt * GK + c] = __float2bfloat16(y - __bfloat162float(hh));
    }
}

extern "C" void kernel_launch(void* const* d_in, const int* in_sizes, int n_in,
                              void* d_out, int out_size) {
    const float* pair      = (const float*)d_in[0];
    const float* bulk      = (const float*)d_in[1];
    const float* row_qkv_w = (const float*)d_in[2];
    const float* row_out_w = (const float*)d_in[3];
    const float* row_ln_g  = (const float*)d_in[4];
    const float* row_ln_b  = (const float*)d_in[5];
    const float* row_bw    = (const float*)d_in[6];
    const float* row_bb    = (const float*)d_in[7];
    const float* col_qkv_w = (const float*)d_in[8];
    const float* col_out_w = (const float*)d_in[9];
    const float* col_ln_g  = (const float*)d_in[10];
    const float* col_ln_b  = (const float*)d_in[11];
    const float* col_bw    = (const float*)d_in[12];
    const float* col_bb    = (const float*)d_in[13];
    float* out = (float*)d_out;

    float *qkv, *proj, *x1;
    __nv_bfloat16 *Ah, *Al, *Bt;
    cudaGetSymbolAddress((void**)&qkv,  g_qkv);
    cudaGetSymbolAddress((void**)&proj, g_proj);
    cudaGetSymbolAddress((void**)&x1,   g_x1);
    cudaGetSymbolAddress((void**)&Ah,   g_Ah);
    cudaGetSymbolAddress((void**)&Al,   g_Al);
    cudaGetSymbolAddress((void**)&Bt,   g_Bt);

    const int n4 = ROWS * GK / 4;
    const int gsplitA = (n4 + 255) / 256;
    dim3 gq(768 / 128, ROWS / 128);
    dim3 gp(256 / 128, ROWS / 128);
    dim3 ga(Hh, Nn, Bb);

    // ---- pass 1 (row attention) ----
    splitB<<<(GK * 768 + 255) / 256, 256>>>(row_qkv_w, Bt, 768);
    splitA<<<gsplitA, 256>>>((const float4*)pair, Ah, Al, n4);
    gemm_mma<<<gq, 256>>>(Ah, Al, Bt, qkv, 768);
    attn_kernel<<<ga, 2*Nn>>>(qkv, bulk, row_bw, row_bb, Ah, Al, Nn, 1);
    splitB<<<(GK * 256 + 255) / 256, 256>>>(row_out_w, Bt, 256);
    gemm_mma<<<gp, 256>>>(Ah, Al, Bt, proj, 256);
    ln_kernel<<<ROWS, Cc>>>(pair, proj, row_ln_g, row_ln_b, x1, Ah, Al);

    // ---- pass 2 (column attention on transposed x) ----
    splitB<<<(GK * 768 + 255) / 256, 256>>>(col_qkv_w, Bt, 768);
    gemm_mma<<<gq, 256>>>(Ah, Al, Bt, qkv, 768);
    attn_kernel<<<ga, 2*Nn>>>(qkv, bulk, col_bw, col_bb, Ah, Al, 1, Nn);
    splitB<<<(GK * 256 + 255) / 256, 256>>>(col_out_w, Bt, 256);
    gemm_mma<<<gp, 256>>>(Ah, Al, Bt, proj, 256);
    ln_kernel<<<ROWS, Cc>>>(x1, proj, col_ln_g, col_ln_b, out, nullptr, nullptr);
}

// round 7
// speedup vs baseline: 1.0449x; 1.0449x over previous
#include <cuda_runtime.h>
#include <cuda_bf16.h>
#include <math.h>
#include <cstdint>

#define Bb 2
#define Nn 160
#define Cc 256
#define Hh 8
#define Dd 32
#define ROWS (Bb*Nn*Nn)   // 51200
#define GK 256            // inner K of all GEMMs

// ---------------- scratch (__device__ globals; no allocation allowed) ----------------
__device__ float g_qkv[(size_t)ROWS*768];
__device__ float g_proj[(size_t)ROWS*Cc];
__device__ float g_x1[(size_t)ROWS*Cc];
__device__ __nv_bfloat16 g_Ah[(size_t)ROWS*GK];
__device__ __nv_bfloat16 g_Al[(size_t)ROWS*GK];
__device__ __nv_bfloat16 g_Bt[(size_t)768*2*GK];   // [Nc, 2K]: cols [0,K)=hi, [K,2K)=lo

__device__ __forceinline__ uint32_t smem_u32(const void* p) {
    uint32_t a;
    asm("{ .reg .u64 t; cvta.to.shared.u64 t, %1; cvt.u32.u64 %0, t; }" : "=r"(a) : "l"(p));
    return a;
}
#define CP16(d, s) asm volatile("cp.async.cg.shared.global [%0], [%1], 16;" :: "r"(d), "l"(s))
#define CP_COMMIT  asm volatile("cp.async.commit_group;" ::: "memory")

__device__ __forceinline__ uint32_t bpack(__nv_bfloat16 a, __nv_bfloat16 b) {
    __nv_bfloat162 t(a, b);
    return *reinterpret_cast<uint32_t*>(&t);
}

// ---------------- split kernels: fp32 -> bf16 hi/lo ----------------
__global__ __launch_bounds__(256) void splitA(const float4* __restrict__ X,
                                              __nv_bfloat16* __restrict__ Ah,
                                              __nv_bfloat16* __restrict__ Al, int n4) {
    int i = blockIdx.x * blockDim.x + threadIdx.x;
    if (i >= n4) return;
    float4 x = X[i];
    __nv_bfloat16 h0 = __float2bfloat16(x.x), h1 = __float2bfloat16(x.y);
    __nv_bfloat16 h2 = __float2bfloat16(x.z), h3 = __float2bfloat16(x.w);
    __nv_bfloat16 l0 = __float2bfloat16(x.x - __bfloat162float(h0));
    __nv_bfloat16 l1 = __float2bfloat16(x.y - __bfloat162float(h1));
    __nv_bfloat16 l2 = __float2bfloat16(x.z - __bfloat162float(h2));
    __nv_bfloat16 l3 = __float2bfloat16(x.w - __bfloat162float(h3));
    reinterpret_cast<__nv_bfloat162*>(Ah)[i * 2 + 0] = __nv_bfloat162(h0, h1);
    reinterpret_cast<__nv_bfloat162*>(Ah)[i * 2 + 1] = __nv_bfloat162(h2, h3);
    reinterpret_cast<__nv_bfloat162*>(Al)[i * 2 + 0] = __nv_bfloat162(l0, l1);
    reinterpret_cast<__nv_bfloat162*>(Al)[i * 2 + 1] = __nv_bfloat162(l2, l3);
}

// W [K, Nc] row-major -> Bt [Nc, 2K]: Bt[n, k] = hi(W[k,n]), Bt[n, K+k] = lo(W[k,n])
__global__ __launch_bounds__(256) void splitB(const float* __restrict__ W,
                                              __nv_bfloat16* __restrict__ Bt, int Nc) {
    int idx = blockIdx.x * blockDim.x + threadIdx.x;
    if (idx >= GK * Nc) return;
    int k = idx / Nc, n = idx % Nc;
    float x = W[idx];
    __nv_bfloat16 h = __float2bfloat16(x);
    Bt[(size_t)n * (2 * GK) + k]      = h;
    Bt[(size_t)n * (2 * GK) + GK + k] = __float2bfloat16(x - __bfloat162float(h));
}

// ---------------- bf16 mma.sync GEMM: C[M,Nc] = A @ W (fp32 via 3-split) ----------------
#define SSTR 40   // smem row stride in bf16 elems

__global__ __launch_bounds__(256) void gemm_mma(const __nv_bfloat16* __restrict__ Ah,
                                                const __nv_bfloat16* __restrict__ Al,
                                                const __nv_bfloat16* __restrict__ Bt,
                                                float* __restrict__ C, int Nc) {
    __shared__ __align__(16) __nv_bfloat16 As[2][128 * SSTR];
    __shared__ __align__(16) __nv_bfloat16 Bs[2][128 * SSTR];

    const int tid = threadIdx.x;
    const int wid = tid >> 5, l = tid & 31;
    const int wm = (wid & 3) * 32;
    const int wn = (wid >> 2) * 64;
    const int bm = blockIdx.y * 128, bn = blockIdx.x * 128;

    float acc[2][8][4];
#pragma unroll
    for (int mt = 0; mt < 2; mt++)
#pragma unroll
        for (int nt = 0; nt < 8; nt++)
#pragma unroll
            for (int r = 0; r < 4; r++) acc[mt][nt][r] = 0.f;

    auto load_chunk = [&](int c, int st) {
        const int blk = c >> 3;                 // 0: Ah*Bh  1: Ah*Bl  2: Al*Bh
        const int k0 = (c & 7) * 32;
        const __nv_bfloat16* Ap = (blk < 2 ? Ah : Al);
        const __nv_bfloat16* Bp = Bt + (blk == 1 ? GK : 0);
#pragma unroll
        for (int w = 0; w < 2; w++) {
            int idx = tid + w * 256;
            int row = idx >> 2, seg = (idx & 3) * 8;
            CP16(smem_u32(&As[st][row * SSTR + seg]),
                 Ap + (size_t)(bm + row) * GK + k0 + seg);
            CP16(smem_u32(&Bs[st][row * SSTR + seg]),
                 Bp + (size_t)(bn + row) * (2 * GK) + k0 + seg);
        }
        CP_COMMIT;
    };

    load_chunk(0, 0);

    for (int c = 0; c < 24; c++) {
        const int st = c & 1;
        if (c + 1 < 24) {
            load_chunk(c + 1, st ^ 1);
            asm volatile("cp.async.wait_group 1;" ::: "memory");
        } else {
            asm volatile("cp.async.wait_group 0;" ::: "memory");
        }
        __syncthreads();

        const uint32_t aBase = smem_u32(&As[st][0]);
        const uint32_t bBase = smem_u32(&Bs[st][0]);
#pragma unroll
        for (int ks = 0; ks < 32; ks += 16) {
            uint32_t a[2][4];
#pragma unroll
            for (int mt = 0; mt < 2; mt++) {
                uint32_t addr = aBase +
                    (((wm + mt * 16 + (l & 15)) * SSTR) + ks + ((l >> 4) << 3)) * 2;
                asm volatile("ldmatrix.sync.aligned.m8n8.x4.shared.b16 {%0,%1,%2,%3}, [%4];"
                             : "=r"(a[mt][0]), "=r"(a[mt][1]), "=r"(a[mt][2]), "=r"(a[mt][3])
                             : "r"(addr));
            }
            uint32_t b[8][2];
#pragma unroll
            for (int p = 0; p < 4; p++) {
                uint32_t addr = bBase +
                    (((wn + p * 16 + (l & 7) + ((l >> 4) << 3)) * SSTR) +
                     ks + (((l >> 3) & 1) << 3)) * 2;
                asm volatile("ldmatrix.sync.aligned.m8n8.x4.shared.b16 {%0,%1,%2,%3}, [%4];"
                             : "=r"(b[p * 2][0]), "=r"(b[p * 2][1]),
                               "=r"(b[p * 2 + 1][0]), "=r"(b[p * 2 + 1][1])
                             : "r"(addr));
            }
#pragma unroll
            for (int mt = 0; mt < 2; mt++)
#pragma unroll
                for (int nt = 0; nt < 8; nt++)
                    asm volatile(
                        "mma.sync.aligned.m16n8k16.row.col.f32.bf16.bf16.f32 "
                        "{%0,%1,%2,%3}, {%4,%5,%6,%7}, {%8,%9}, {%0,%1,%2,%3};"
                        : "+f"(acc[mt][nt][0]), "+f"(acc[mt][nt][1]),
                          "+f"(acc[mt][nt][2]), "+f"(acc[mt][nt][3])
                        : "r"(a[mt][0]), "r"(a[mt][1]), "r"(a[mt][2]), "r"(a[mt][3]),
                          "r"(b[nt][0]), "r"(b[nt][1]));
        }
        __syncthreads();
    }

#pragma unroll
    for (int mt = 0; mt < 2; mt++) {
        const int row = bm + wm + mt * 16 + (l >> 2);
#pragma unroll
        for (int nt = 0; nt < 8; nt++) {
            const int col = bn + wn + nt * 8 + (l & 3) * 2;
            *reinterpret_cast<float2*>(C + (size_t)row * Nc + col) =
                make_float2(acc[mt][nt][0], acc[mt][nt][1]);
            *reinterpret_cast<float2*>(C + (size_t)(row + 8) * Nc + col) =
                make_float2(acc[mt][nt][2], acc[mt][nt][3]);
        }
    }
}

// ---------------- Fused attention: 2 heads per block, thread i = row i ----------------
// dynamic smem: ks[2][Nn][9] float4 then vs[2][Nn][9] float4  (92160 B)
#define KSTRIDE 9
#define ATTN_SMEM (2 * Nn * KSTRIDE * 16 * 2)

__global__ __launch_bounds__(Nn, 2) void attn_kernel(const float* __restrict__ qkv,
                                                  const float* __restrict__ map,
                                                  const float* __restrict__ bw,
                                                  const float* __restrict__ bb,
                                                  __nv_bfloat16* __restrict__ Ah,
                                                  __nv_bfloat16* __restrict__ Al,
                                                  int si, int sj) {
    extern __shared__ float4 smemv[];
    float4* ks = smemv;                       // [2][Nn][KSTRIDE]
    float4* vs = smemv + 2 * Nn * KSTRIDE;    // [2][Nn][KSTRIDE]

    const int h0 = blockIdx.x * 2;
    const int m = blockIdx.y;
    const int b = blockIdx.z;
    const int i = threadIdx.x;

    const size_t rowbase = ((size_t)b * Nn + m) * Nn;
    const float scale = 0.17677669529663687f;
    const float* rowp = qkv + (rowbase + i) * 768;

    float4 q4[2][8];
#pragma unroll
    for (int e = 0; e < 2; e++) {
        const float4* qp = reinterpret_cast<const float4*>(rowp + (h0 + e) * Dd);
        const float4* kp = reinterpret_cast<const float4*>(rowp + 256 + (h0 + e) * Dd);
        const float4* vp = reinterpret_cast<const float4*>(rowp + 512 + (h0 + e) * Dd);
#pragma unroll
        for (int c = 0; c < 8; c++) {
            ks[(e * Nn + i) * KSTRIDE + c] = kp[c];
            vs[(e * Nn + i) * KSTRIDE + c] = vp[c];
            float4 t = qp[c];
            t.x *= scale; t.y *= scale; t.z *= scale; t.w *= scale;
            q4[e][c] = t;
        }
    }
    __syncthreads();

    const float wv0 = bw[h0],     bv0 = bb[h0];
    const float wv1 = bw[h0 + 1], bv1 = bb[h0 + 1];
    const float* mp = map + (size_t)b * Nn * Nn + (size_t)i * si;

    float mi0 = -INFINITY, li0 = 0.f, mi1 = -INFINITY, li1 = 0.f;
    float4 acc0[8], acc1[8];
#pragma unroll
    for (int c = 0; c < 8; c++) {
        acc0[c] = make_float4(0.f, 0.f, 0.f, 0.f);
        acc1[c] = make_float4(0.f, 0.f, 0.f, 0.f);
    }

    for (int j = 0; j < Nn; j++) {
        const float mval = __ldg(&mp[(size_t)j * sj]);
        const float4* k0 = &ks[(0 * Nn + j) * KSTRIDE];
        const float4* k1 = &ks[(1 * Nn + j) * KSTRIDE];
        float s0 = 0.f, s1 = 0.f;
#pragma unroll
        for (int c = 0; c < 8; c++) {
            float4 ka = k0[c], kb = k1[c];
            s0 += q4[0][c].x * ka.x + q4[0][c].y * ka.y + q4[0][c].z * ka.z + q4[0][c].w * ka.w;
            s1 += q4[1][c].x * kb.x + q4[1][c].y * kb.y + q4[1][c].z * kb.z + q4[1][c].w * kb.w;
        }
        s0 += mval * wv0 + bv0;
        s1 += mval * wv1 + bv1;

        if (s0 > mi0) {
            float f = __expf(mi0 - s0);
            li0 *= f;
#pragma unroll
            for (int c = 0; c < 8; c++) {
                acc0[c].x *= f; acc0[c].y *= f; acc0[c].z *= f; acc0[c].w *= f;
            }
            mi0 = s0;
        }
        if (s1 > mi1) {
            float f = __expf(mi1 - s1);
            li1 *= f;
#pragma unroll
            for (int c = 0; c < 8; c++) {
                acc1[c].x *= f; acc1[c].y *= f; acc1[c].z *= f; acc1[c].w *= f;
            }
            mi1 = s1;
        }
        float p0 = __expf(s0 - mi0);
        float p1 = __expf(s1 - mi1);
        li0 += p0; li1 += p1;
        const float4* v0 = &vs[(0 * Nn + j) * KSTRIDE];
        const float4* v1 = &vs[(1 * Nn + j) * KSTRIDE];
#pragma unroll
        for (int c = 0; c < 8; c++) {
            float4 va = v0[c], vb = v1[c];
            acc0[c].x += p0 * va.x; acc0[c].y += p0 * va.y;
            acc0[c].z += p0 * va.z; acc0[c].w += p0 * va.w;
            acc1[c].x += p1 * vb.x; acc1[c].y += p1 * vb.y;
            acc1[c].z += p1 * vb.z; acc1[c].w += p1 * vb.w;
        }
    }

#pragma unroll
    for (int e = 0; e < 2; e++) {
        const float inv = e ? (1.f / li1) : (1.f / li0);
        const float4* ac = e ? acc1 : acc0;
        uint32_t wh[16], wl[16];
#pragma unroll
        for (int c = 0; c < 8; c++) {
            float o0 = ac[c].x * inv, o1 = ac[c].y * inv;
            float o2 = ac[c].z * inv, o3 = ac[c].w * inv;
            __nv_bfloat16 h0b = __float2bfloat16(o0), h1b = __float2bfloat16(o1);
            __nv_bfloat16 h2b = __float2bfloat16(o2), h3b = __float2bfloat16(o3);
            wh[c * 2 + 0] = bpack(h0b, h1b);
            wh[c * 2 + 1] = bpack(h2b, h3b);
            wl[c * 2 + 0] = bpack(__float2bfloat16(o0 - __bfloat162float(h0b)),
                                  __float2bfloat16(o1 - __bfloat162float(h1b)));
            wl[c * 2 + 1] = bpack(__float2bfloat16(o2 - __bfloat162float(h2b)),
                                  __float2bfloat16(o3 - __bfloat162float(h3b)));
        }
        uint4* ahp = reinterpret_cast<uint4*>(Ah + (rowbase + i) * GK + (h0 + e) * Dd);
        uint4* alp = reinterpret_cast<uint4*>(Al + (rowbase + i) * GK + (h0 + e) * Dd);
#pragma unroll
        for (int c = 0; c < 4; c++) {
            ahp[c] = make_uint4(wh[c * 4], wh[c * 4 + 1], wh[c * 4 + 2], wh[c * 4 + 3]);
            alp[c] = make_uint4(wl[c * 4], wl[c * 4 + 1], wl[c * 4 + 2], wl[c * 4 + 3]);
        }
    }
}

// ---------------- Residual + LayerNorm; transposed write; optional bf16 hi/lo emit ----------------
__global__ __launch_bounds__(Cc) void ln_kernel(const float* __restrict__ xin,
                                                const float* __restrict__ proj,
                                                const float* __restrict__ g,
                                                const float* __restrict__ bt,
                                                float* __restrict__ out,
                                                __nv_bfloat16* __restrict__ Ah,
                                                __nv_bfloat16* __restrict__ Al) {
    const int r = blockIdx.x;
    const int c = threadIdx.x;
    const float v = xin[(size_t)r * Cc + c] + proj[(size_t)r * Cc + c];

    float s = v, s2 = v * v;
#pragma unroll
    for (int o = 16; o > 0; o >>= 1) {
        s  += __shfl_down_sync(0xffffffffu, s, o);
        s2 += __shfl_down_sync(0xffffffffu, s2, o);
    }
    __shared__ float ws[8], ws2[8];
    const int w = c >> 5, l = c & 31;
    if (l == 0) { ws[w] = s; ws2[w] = s2; }
    __syncthreads();
    if (w == 0) {
        s  = (l < 8) ? ws[l]  : 0.f;
        s2 = (l < 8) ? ws2[l] : 0.f;
#pragma unroll
        for (int o = 4; o > 0; o >>= 1) {
            s  += __shfl_down_sync(0xffffffffu, s, o);
            s2 += __shfl_down_sync(0xffffffffu, s2, o);
        }
        if (l == 0) { ws[0] = s; ws2[0] = s2; }
    }
    __syncthreads();
    const float mean = ws[0] * (1.f / Cc);
    const float var  = ws2[0] * (1.f / Cc) - mean * mean;
    const float rs   = rsqrtf(var + 1e-5f);

    const int bidx = r / (Nn * Nn);
    const int rem  = r % (Nn * Nn);
    const int mm   = rem / Nn;
    const int ii   = rem % Nn;
    const size_t rt = ((size_t)bidx * Nn + ii) * Nn + mm;
    const float y = (v - mean) * rs * g[c] + bt[c];
    out[rt * Cc + c] = y;
    if (Ah) {
        __nv_bfloat16 hh = __float2bfloat16(y);
        Ah[rt * GK + c] = hh;
        Al[rt * GK + c] = __float2bfloat16(y - __bfloat162float(hh));
    }
}

extern "C" void kernel_launch(void* const* d_in, const int* in_sizes, int n_in,
                              void* d_out, int out_size) {
    const float* pair      = (const float*)d_in[0];
    const float* bulk      = (const float*)d_in[1];
    const float* row_qkv_w = (const float*)d_in[2];
    const float* row_out_w = (const float*)d_in[3];
    const float* row_ln_g  = (const float*)d_in[4];
    const float* row_ln_b  = (const float*)d_in[5];
    const float* row_bw    = (const float*)d_in[6];
    const float* row_bb    = (const float*)d_in[7];
    const float* col_qkv_w = (const float*)d_in[8];
    const float* col_out_w = (const float*)d_in[9];
    const float* col_ln_g  = (const float*)d_in[10];
    const float* col_ln_b  = (const float*)d_in[11];
    const float* col_bw    = (const float*)d_in[12];
    const float* col_bb    = (const float*)d_in[13];
    float* out = (float*)d_out;

    float *qkv, *proj, *x1;
    __nv_bfloat16 *Ah, *Al, *Bt;
    cudaGetSymbolAddress((void**)&qkv,  g_qkv);
    cudaGetSymbolAddress((void**)&proj, g_proj);
    cudaGetSymbolAddress((void**)&x1,   g_x1);
    cudaGetSymbolAddress((void**)&Ah,   g_Ah);
    cudaGetSymbolAddress((void**)&Al,   g_Al);
    cudaGetSymbolAddress((void**)&Bt,   g_Bt);

    cudaFuncSetAttribute(attn_kernel, cudaFuncAttributeMaxDynamicSharedMemorySize, ATTN_SMEM);

    const int n4 = ROWS * GK / 4;
    const int gsplitA = (n4 + 255) / 256;
    dim3 gq(768 / 128, ROWS / 128);
    dim3 gp(256 / 128, ROWS / 128);
    dim3 ga(Hh / 2, Nn, Bb);

    // ---- pass 1 (row attention) ----
    splitB<<<(GK * 768 + 255) / 256, 256>>>(row_qkv_w, Bt, 768);
    splitA<<<gsplitA, 256>>>((const float4*)pair, Ah, Al, n4);
    gemm_mma<<<gq, 256>>>(Ah, Al, Bt, qkv, 768);
    attn_kernel<<<ga, Nn, ATTN_SMEM>>>(qkv, bulk, row_bw, row_bb, Ah, Al, Nn, 1);
    splitB<<<(GK * 256 + 255) / 256, 256>>>(row_out_w, Bt, 256);
    gemm_mma<<<gp, 256>>>(Ah, Al, Bt, proj, 256);
    ln_kernel<<<ROWS, Cc>>>(pair, proj, row_ln_g, row_ln_b, x1, Ah, Al);

    // ---- pass 2 (column attention on transposed x) ----
    splitB<<<(GK * 768 + 255) / 256, 256>>>(col_qkv_w, Bt, 768);
    gemm_mma<<<gq, 256>>>(Ah, Al, Bt, qkv, 768);
    attn_kernel<<<ga, Nn, ATTN_SMEM>>>(qkv, bulk, col_bw, col_bb, Ah, Al, 1, Nn);
    splitB<<<(GK * 256 + 255) / 256, 256>>>(col_out_w, Bt, 256);
    gemm_mma<<<gp, 256>>>(Ah, Al, Bt, proj, 256);
    ln_kernel<<<ROWS, Cc>>>(x1, proj, col_ln_g, col_ln_b, out, nullptr, nullptr);
}

// round 8
// speedup vs baseline: 1.1120x; 1.0643x over previous
#include <cuda_runtime.h>
#include <cuda_bf16.h>
#include <math.h>
#include <cstdint>

#define Bb 2
#define Nn 160
#define Cc 256
#define Hh 8
#define Dd 32
#define ROWS (Bb*Nn*Nn)   // 51200
#define GK 256            // inner K of all GEMMs

typedef unsigned long long ull;

// ---------------- scratch (__device__ globals; no allocation allowed) ----------------
__device__ float g_qkv[(size_t)ROWS*768];
__device__ float g_proj[(size_t)ROWS*Cc];
__device__ float g_x1[(size_t)ROWS*Cc];
__device__ float g_mapT[(size_t)Bb*Nn*Nn];
__device__ __nv_bfloat16 g_Ah[(size_t)ROWS*GK];
__device__ __nv_bfloat16 g_Al[(size_t)ROWS*GK];
__device__ __nv_bfloat16 g_Bt[(size_t)768*2*GK];   // [Nc, 2K]: cols [0,K)=hi, [K,2K)=lo

__device__ __forceinline__ uint32_t smem_u32(const void* p) {
    uint32_t a;
    asm("{ .reg .u64 t; cvta.to.shared.u64 t, %1; cvt.u32.u64 %0, t; }" : "=r"(a) : "l"(p));
    return a;
}
#define CP16(d, s) asm volatile("cp.async.cg.shared.global [%0], [%1], 16;" :: "r"(d), "l"(s))
#define CP_COMMIT  asm volatile("cp.async.commit_group;" ::: "memory")

__device__ __forceinline__ uint32_t bpack(__nv_bfloat16 a, __nv_bfloat16 b) {
    __nv_bfloat162 t(a, b);
    return *reinterpret_cast<uint32_t*>(&t);
}
__device__ __forceinline__ ull pack2(float x, float y) {
    float2 t = make_float2(x, y);
    return *reinterpret_cast<ull*>(&t);
}
__device__ __forceinline__ float2 unpack2(ull v) { return *reinterpret_cast<float2*>(&v); }
__device__ __forceinline__ void fma2(ull& d, ull a, ull b) {
    asm("fma.rn.f32x2 %0, %1, %2, %0;" : "+l"(d) : "l"(a), "l"(b));
}
__device__ __forceinline__ ull mul2(ull a, ull b) {
    ull r; asm("mul.rn.f32x2 %0, %1, %2;" : "=l"(r) : "l"(a), "l"(b)); return r;
}

// ---------------- map transpose: mapT[b,c,r] = map[b,r,c] ----------------
__global__ __launch_bounds__(256) void tmap_kernel(const float* __restrict__ m,
                                                   float* __restrict__ mt) {
    __shared__ float tile[32][33];
    const int b = blockIdx.z;
    const int x = blockIdx.x * 32 + threadIdx.x;
    const int ty = threadIdx.y;
#pragma unroll
    for (int dy = 0; dy < 32; dy += 8) {
        int y = blockIdx.y * 32 + ty + dy;
        tile[ty + dy][threadIdx.x] = m[(size_t)b * Nn * Nn + (size_t)y * Nn + x];
    }
    __syncthreads();
    const int xo = blockIdx.y * 32 + threadIdx.x;
#pragma unroll
    for (int dy = 0; dy < 32; dy += 8) {
        int yo = blockIdx.x * 32 + ty + dy;
        mt[(size_t)b * Nn * Nn + (size_t)yo * Nn + xo] = tile[threadIdx.x][ty + dy];
    }
}

// ---------------- split kernels: fp32 -> bf16 hi/lo ----------------
__global__ __launch_bounds__(256) void splitA(const float4* __restrict__ X,
                                              __nv_bfloat16* __restrict__ Ah,
                                              __nv_bfloat16* __restrict__ Al, int n4) {
    int i = blockIdx.x * blockDim.x + threadIdx.x;
    if (i >= n4) return;
    float4 x = X[i];
    __nv_bfloat16 h0 = __float2bfloat16(x.x), h1 = __float2bfloat16(x.y);
    __nv_bfloat16 h2 = __float2bfloat16(x.z), h3 = __float2bfloat16(x.w);
    __nv_bfloat16 l0 = __float2bfloat16(x.x - __bfloat162float(h0));
    __nv_bfloat16 l1 = __float2bfloat16(x.y - __bfloat162float(h1));
    __nv_bfloat16 l2 = __float2bfloat16(x.z - __bfloat162float(h2));
    __nv_bfloat16 l3 = __float2bfloat16(x.w - __bfloat162float(h3));
    reinterpret_cast<__nv_bfloat162*>(Ah)[i * 2 + 0] = __nv_bfloat162(h0, h1);
    reinterpret_cast<__nv_bfloat162*>(Ah)[i * 2 + 1] = __nv_bfloat162(h2, h3);
    reinterpret_cast<__nv_bfloat162*>(Al)[i * 2 + 0] = __nv_bfloat162(l0, l1);
    reinterpret_cast<__nv_bfloat162*>(Al)[i * 2 + 1] = __nv_bfloat162(l2, l3);
}

// W [K, Nc] row-major -> Bt [Nc, 2K]: Bt[n, k] = hi(W[k,n]), Bt[n, K+k] = lo(W[k,n])
__global__ __launch_bounds__(256) void splitB(const float* __restrict__ W,
                                              __nv_bfloat16* __restrict__ Bt, int Nc) {
    int idx = blockIdx.x * blockDim.x + threadIdx.x;
    if (idx >= GK * Nc) return;
    int k = idx / Nc, n = idx % Nc;
    float x = W[idx];
    __nv_bfloat16 h = __float2bfloat16(x);
    Bt[(size_t)n * (2 * GK) + k]      = h;
    Bt[(size_t)n * (2 * GK) + GK + k] = __float2bfloat16(x - __bfloat162float(h));
}

// ---------------- bf16 mma.sync GEMM: C[M,Nc] = A @ W (fp32 via 3-split) ----------------
#define SSTR 40   // smem row stride in bf16 elems

__global__ __launch_bounds__(256) void gemm_mma(const __nv_bfloat16* __restrict__ Ah,
                                                const __nv_bfloat16* __restrict__ Al,
                                                const __nv_bfloat16* __restrict__ Bt,
                                                float* __restrict__ C, int Nc) {
    __shared__ __align__(16) __nv_bfloat16 As[2][128 * SSTR];
    __shared__ __align__(16) __nv_bfloat16 Bs[2][128 * SSTR];

    const int tid = threadIdx.x;
    const int wid = tid >> 5, l = tid & 31;
    const int wm = (wid & 3) * 32;
    const int wn = (wid >> 2) * 64;
    const int bm = blockIdx.y * 128, bn = blockIdx.x * 128;

    float acc[2][8][4];
#pragma unroll
    for (int mt = 0; mt < 2; mt++)
#pragma unroll
        for (int nt = 0; nt < 8; nt++)
#pragma unroll
            for (int r = 0; r < 4; r++) acc[mt][nt][r] = 0.f;

    auto load_chunk = [&](int c, int st) {
        const int blk = c >> 3;                 // 0: Ah*Bh  1: Ah*Bl  2: Al*Bh
        const int k0 = (c & 7) * 32;
        const __nv_bfloat16* Ap = (blk < 2 ? Ah : Al);
        const __nv_bfloat16* Bp = Bt + (blk == 1 ? GK : 0);
#pragma unroll
        for (int w = 0; w < 2; w++) {
            int idx = tid + w * 256;
            int row = idx >> 2, seg = (idx & 3) * 8;
            CP16(smem_u32(&As[st][row * SSTR + seg]),
                 Ap + (size_t)(bm + row) * GK + k0 + seg);
            CP16(smem_u32(&Bs[st][row * SSTR + seg]),
                 Bp + (size_t)(bn + row) * (2 * GK) + k0 + seg);
        }
        CP_COMMIT;
    };

    load_chunk(0, 0);

    for (int c = 0; c < 24; c++) {
        const int st = c & 1;
        if (c + 1 < 24) {
            load_chunk(c + 1, st ^ 1);
            asm volatile("cp.async.wait_group 1;" ::: "memory");
        } else {
            asm volatile("cp.async.wait_group 0;" ::: "memory");
        }
        __syncthreads();

        const uint32_t aBase = smem_u32(&As[st][0]);
        const uint32_t bBase = smem_u32(&Bs[st][0]);
#pragma unroll
        for (int ks = 0; ks < 32; ks += 16) {
            uint32_t a[2][4];
#pragma unroll
            for (int mt = 0; mt < 2; mt++) {
                uint32_t addr = aBase +
                    (((wm + mt * 16 + (l & 15)) * SSTR) + ks + ((l >> 4) << 3)) * 2;
                asm volatile("ldmatrix.sync.aligned.m8n8.x4.shared.b16 {%0,%1,%2,%3}, [%4];"
                             : "=r"(a[mt][0]), "=r"(a[mt][1]), "=r"(a[mt][2]), "=r"(a[mt][3])
                             : "r"(addr));
            }
            uint32_t b[8][2];
#pragma unroll
            for (int p = 0; p < 4; p++) {
                uint32_t addr = bBase +
                    (((wn + p * 16 + (l & 7) + ((l >> 4) << 3)) * SSTR) +
                     ks + (((l >> 3) & 1) << 3)) * 2;
                asm volatile("ldmatrix.sync.aligned.m8n8.x4.shared.b16 {%0,%1,%2,%3}, [%4];"
                             : "=r"(b[p * 2][0]), "=r"(b[p * 2][1]),
                               "=r"(b[p * 2 + 1][0]), "=r"(b[p * 2 + 1][1])
                             : "r"(addr));
            }
#pragma unroll
            for (int mt = 0; mt < 2; mt++)
#pragma unroll
                for (int nt = 0; nt < 8; nt++)
                    asm volatile(
                        "mma.sync.aligned.m16n8k16.row.col.f32.bf16.bf16.f32 "
                        "{%0,%1,%2,%3}, {%4,%5,%6,%7}, {%8,%9}, {%0,%1,%2,%3};"
                        : "+f"(acc[mt][nt][0]), "+f"(acc[mt][nt][1]),
                          "+f"(acc[mt][nt][2]), "+f"(acc[mt][nt][3])
                        : "r"(a[mt][0]), "r"(a[mt][1]), "r"(a[mt][2]), "r"(a[mt][3]),
                          "r"(b[nt][0]), "r"(b[nt][1]));
        }
        __syncthreads();
    }

#pragma unroll
    for (int mt = 0; mt < 2; mt++) {
        const int row = bm + wm + mt * 16 + (l >> 2);
#pragma unroll
        for (int nt = 0; nt < 8; nt++) {
            const int col = bn + wn + nt * 8 + (l & 3) * 2;
            *reinterpret_cast<float2*>(C + (size_t)row * Nc + col) =
                make_float2(acc[mt][nt][0], acc[mt][nt][1]);
            *reinterpret_cast<float2*>(C + (size_t)(row + 8) * Nc + col) =
                make_float2(acc[mt][nt][2], acc[mt][nt][3]);
        }
    }
}

// ---------------- Fused attention: 2 heads per block, f32x2 packed math ----------------
// bias map MUST be laid out so that bias(i,j) = mp[i + j*Nn]  (coalesced over threads i)
#define KSTRIDE 9
#define ATTN_SMEM (2 * Nn * KSTRIDE * 16 * 2)

__global__ __launch_bounds__(Nn, 2) void attn_kernel(const float* __restrict__ qkv,
                                                  const float* __restrict__ map,
                                                  const float* __restrict__ bw,
                                                  const float* __restrict__ bb,
                                                  __nv_bfloat16* __restrict__ Ah,
                                                  __nv_bfloat16* __restrict__ Al) {
    extern __shared__ float4 smemv[];
    float4* ks = smemv;                       // [2][Nn][KSTRIDE]
    float4* vs = smemv + 2 * Nn * KSTRIDE;    // [2][Nn][KSTRIDE]

    const int h0 = blockIdx.x * 2;
    const int m = blockIdx.y;
    const int b = blockIdx.z;
    const int i = threadIdx.x;

    const size_t rowbase = ((size_t)b * Nn + m) * Nn;
    const float scale = 0.17677669529663687f;
    const float* rowp = qkv + (rowbase + i) * 768;

    ull q2[2][16];
#pragma unroll
    for (int e = 0; e < 2; e++) {
        const float4* qp = reinterpret_cast<const float4*>(rowp + (h0 + e) * Dd);
        const float4* kp = reinterpret_cast<const float4*>(rowp + 256 + (h0 + e) * Dd);
        const float4* vp = reinterpret_cast<const float4*>(rowp + 512 + (h0 + e) * Dd);
#pragma unroll
        for (int c = 0; c < 8; c++) {
            ks[(e * Nn + i) * KSTRIDE + c] = kp[c];
            vs[(e * Nn + i) * KSTRIDE + c] = vp[c];
            float4 t = qp[c];
            q2[e][c * 2 + 0] = pack2(t.x * scale, t.y * scale);
            q2[e][c * 2 + 1] = pack2(t.z * scale, t.w * scale);
        }
    }
    __syncthreads();

    const float wv0 = bw[h0],     bv0 = bb[h0];
    const float wv1 = bw[h0 + 1], bv1 = bb[h0 + 1];
    const float* mp = map + (size_t)b * Nn * Nn + i;

    float mi0 = -INFINITY, li0 = 0.f, mi1 = -INFINITY, li1 = 0.f;
    ull acc0[16], acc1[16];
#pragma unroll
    for (int c = 0; c < 16; c++) { acc0[c] = 0ull; acc1[c] = 0ull; }

    for (int j = 0; j < Nn; j++) {
        const float mval = __ldg(&mp[(size_t)j * Nn]);
        const float4* k0 = &ks[(0 * Nn + j) * KSTRIDE];
        const float4* k1 = &ks[(1 * Nn + j) * KSTRIDE];
        ull s0p = 0ull, s1p = 0ull;
#pragma unroll
        for (int c = 0; c < 8; c++) {
            float4 ka = k0[c], kb = k1[c];
            const ull* kap = reinterpret_cast<const ull*>(&ka);
            const ull* kbp = reinterpret_cast<const ull*>(&kb);
            fma2(s0p, q2[0][c * 2 + 0], kap[0]);
            fma2(s0p, q2[0][c * 2 + 1], kap[1]);
            fma2(s1p, q2[1][c * 2 + 0], kbp[0]);
            fma2(s1p, q2[1][c * 2 + 1], kbp[1]);
        }
        float2 sv0 = unpack2(s0p), sv1 = unpack2(s1p);
        float s0 = sv0.x + sv0.y + mval * wv0 + bv0;
        float s1 = sv1.x + sv1.y + mval * wv1 + bv1;

        if (s0 > mi0) {
            float f = __expf(mi0 - s0);
            li0 *= f;
            ull fp = pack2(f, f);
#pragma unroll
            for (int c = 0; c < 16; c++) acc0[c] = mul2(acc0[c], fp);
            mi0 = s0;
        }
        if (s1 > mi1) {
            float f = __expf(mi1 - s1);
            li1 *= f;
            ull fp = pack2(f, f);
#pragma unroll
            for (int c = 0; c < 16; c++) acc1[c] = mul2(acc1[c], fp);
            mi1 = s1;
        }
        float p0 = __expf(s0 - mi0);
        float p1 = __expf(s1 - mi1);
        li0 += p0; li1 += p1;
        const ull pp0 = pack2(p0, p0);
        const ull pp1 = pack2(p1, p1);
        const float4* v0 = &vs[(0 * Nn + j) * KSTRIDE];
        const float4* v1 = &vs[(1 * Nn + j) * KSTRIDE];
#pragma unroll
        for (int c = 0; c < 8; c++) {
            float4 va = v0[c], vb = v1[c];
            const ull* vap = reinterpret_cast<const ull*>(&va);
            const ull* vbp = reinterpret_cast<const ull*>(&vb);
            fma2(acc0[c * 2 + 0], pp0, vap[0]);
            fma2(acc0[c * 2 + 1], pp0, vap[1]);
            fma2(acc1[c * 2 + 0], pp1, vbp[0]);
            fma2(acc1[c * 2 + 1], pp1, vbp[1]);
        }
    }

#pragma unroll
    for (int e = 0; e < 2; e++) {
        const float inv = e ? (1.f / li1) : (1.f / li0);
        const ull* ac = e ? acc1 : acc0;
        uint32_t wh[16], wl[16];
#pragma unroll
        for (int c = 0; c < 8; c++) {
            float2 a0 = unpack2(ac[c * 2 + 0]);
            float2 a1 = unpack2(ac[c * 2 + 1]);
            float o0 = a0.x * inv, o1 = a0.y * inv;
            float o2 = a1.x * inv, o3 = a1.y * inv;
            __nv_bfloat16 h0b = __float2bfloat16(o0), h1b = __float2bfloat16(o1);
            __nv_bfloat16 h2b = __float2bfloat16(o2), h3b = __float2bfloat16(o3);
            wh[c * 2 + 0] = bpack(h0b, h1b);
            wh[c * 2 + 1] = bpack(h2b, h3b);
            wl[c * 2 + 0] = bpack(__float2bfloat16(o0 - __bfloat162float(h0b)),
                                  __float2bfloat16(o1 - __bfloat162float(h1b)));
            wl[c * 2 + 1] = bpack(__float2bfloat16(o2 - __bfloat162float(h2b)),
                                  __float2bfloat16(o3 - __bfloat162float(h3b)));
        }
        uint4* ahp = reinterpret_cast<uint4*>(Ah + (rowbase + i) * GK + (h0 + e) * Dd);
        uint4* alp = reinterpret_cast<uint4*>(Al + (rowbase + i) * GK + (h0 + e) * Dd);
#pragma unroll
        for (int c = 0; c < 4; c++) {
            ahp[c] = make_uint4(wh[c * 4], wh[c * 4 + 1], wh[c * 4 + 2], wh[c * 4 + 3]);
            alp[c] = make_uint4(wl[c * 4], wl[c * 4 + 1], wl[c * 4 + 2], wl[c * 4 + 3]);
        }
    }
}

// ---------------- Residual + LayerNorm; transposed write; optional bf16 hi/lo emit ----------------
__global__ __launch_bounds__(Cc) void ln_kernel(const float* __restrict__ xin,
                                                const float* __restrict__ proj,
                                                const float* __restrict__ g,
                                                const float* __restrict__ bt,
                                                float* __restrict__ out,
                                                __nv_bfloat16* __restrict__ Ah,
                                                __nv_bfloat16* __restrict__ Al) {
    const int r = blockIdx.x;
    const int c = threadIdx.x;
    const float v = xin[(size_t)r * Cc + c] + proj[(size_t)r * Cc + c];

    float s = v, s2 = v * v;
#pragma unroll
    for (int o = 16; o > 0; o >>= 1) {
        s  += __shfl_down_sync(0xffffffffu, s, o);
        s2 += __shfl_down_sync(0xffffffffu, s2, o);
    }
    __shared__ float ws[8], ws2[8];
    const int w = c >> 5, l = c & 31;
    if (l == 0) { ws[w] = s; ws2[w] = s2; }
    __syncthreads();
    if (w == 0) {
        s  = (l < 8) ? ws[l]  : 0.f;
        s2 = (l < 8) ? ws2[l] : 0.f;
#pragma unroll
        for (int o = 4; o > 0; o >>= 1) {
            s  += __shfl_down_sync(0xffffffffu, s, o);
            s2 += __shfl_down_sync(0xffffffffu, s2, o);
        }
        if (l == 0) { ws[0] = s; ws2[0] = s2; }
    }
    __syncthreads();
    const float mean = ws[0] * (1.f / Cc);
    const float var  = ws2[0] * (1.f / Cc) - mean * mean;
    const float rs   = rsqrtf(var + 1e-5f);

    const int bidx = r / (Nn * Nn);
    const int rem  = r % (Nn * Nn);
    const int mm   = rem / Nn;
    const int ii   = rem % Nn;
    const size_t rt = ((size_t)bidx * Nn + ii) * Nn + mm;
    const float y = (v - mean) * rs * g[c] + bt[c];
    out[rt * Cc + c] = y;
    if (Ah) {
        __nv_bfloat16 hh = __float2bfloat16(y);
        Ah[rt * GK + c] = hh;
        Al[rt * GK + c] = __float2bfloat16(y - __bfloat162float(hh));
    }
}

extern "C" void kernel_launch(void* const* d_in, const int* in_sizes, int n_in,
                              void* d_out, int out_size) {
    const float* pair      = (const float*)d_in[0];
    const float* bulk      = (const float*)d_in[1];
    const float* row_qkv_w = (const float*)d_in[2];
    const float* row_out_w = (const float*)d_in[3];
    const float* row_ln_g  = (const float*)d_in[4];
    const float* row_ln_b  = (const float*)d_in[5];
    const float* row_bw    = (const float*)d_in[6];
    const float* row_bb    = (const float*)d_in[7];
    const float* col_qkv_w = (const float*)d_in[8];
    const float* col_out_w = (const float*)d_in[9];
    const float* col_ln_g  = (const float*)d_in[10];
    const float* col_ln_b  = (const float*)d_in[11];
    const float* col_bw    = (const float*)d_in[12];
    const float* col_bb    = (const float*)d_in[13];
    float* out = (float*)d_out;

    float *qkv, *proj, *x1, *mapT;
    __nv_bfloat16 *Ah, *Al, *Bt;
    cudaGetSymbolAddress((void**)&qkv,  g_qkv);
    cudaGetSymbolAddress((void**)&proj, g_proj);
    cudaGetSymbolAddress((void**)&x1,   g_x1);
    cudaGetSymbolAddress((void**)&mapT, g_mapT);
    cudaGetSymbolAddress((void**)&Ah,   g_Ah);
    cudaGetSymbolAddress((void**)&Al,   g_Al);
    cudaGetSymbolAddress((void**)&Bt,   g_Bt);

    cudaFuncSetAttribute(attn_kernel, cudaFuncAttributeMaxDynamicSharedMemorySize, ATTN_SMEM);

    const int n4 = ROWS * GK / 4;
    const int gsplitA = (n4 + 255) / 256;
    dim3 gq(768 / 128, ROWS / 128);
    dim3 gp(256 / 128, ROWS / 128);
    dim3 ga(Hh / 2, Nn, Bb);
    dim3 gt(Nn / 32, Nn / 32, Bb);

    // transposed bias map for the row pass (coalesced bias reads in both passes)
    tmap_kernel<<<gt, dim3(32, 8)>>>(bulk, mapT);

    // ---- pass 1 (row attention): bias(i,j) = map[b,i,j] = mapT[b,j,i] ----
    splitB<<<(GK * 768 + 255) / 256, 256>>>(row_qkv_w, Bt, 768);
    splitA<<<gsplitA, 256>>>((const float4*)pair, Ah, Al, n4);
    gemm_mma<<<gq, 256>>>(Ah, Al, Bt, qkv, 768);
    attn_kernel<<<ga, Nn, ATTN_SMEM>>>(qkv, mapT, row_bw, row_bb, Ah, Al);
    splitB<<<(GK * 256 + 255) / 256, 256>>>(row_out_w, Bt, 256);
    gemm_mma<<<gp, 256>>>(Ah, Al, Bt, proj, 256);
    ln_kernel<<<ROWS, Cc>>>(pair, proj, row_ln_g, row_ln_b, x1, Ah, Al);

    // ---- pass 2 (column attention): bias(i,j) = map[b,j,i] (original layout) ----
    splitB<<<(GK * 768 + 255) / 256, 256>>>(col_qkv_w, Bt, 768);
    gemm_mma<<<gq, 256>>>(Ah, Al, Bt, qkv, 768);
    attn_kernel<<<ga, Nn, ATTN_SMEM>>>(qkv, bulk, col_bw, col_bb, Ah, Al);
    splitB<<<(GK * 256 + 255) / 256, 256>>>(col_out_w, Bt, 256);
    gemm_mma<<<gp, 256>>>(Ah, Al, Bt, proj, 256);
    ln_kernel<<<ROWS, Cc>>>(x1, proj, col_ln_g, col_ln_b, out, nullptr, nullptr);
}

// round 9
// speedup vs baseline: 1.1432x; 1.0280x over previous
#include <cuda_runtime.h>
#include <cuda_bf16.h>
#include <math.h>
#include <cstdint>

#define Bb 2
#define Nn 160
#define Cc 256
#define Hh 8
#define Dd 32
#define ROWS (Bb*Nn*Nn)   // 51200
#define GK 256            // inner K of all GEMMs

typedef unsigned long long ull;

// ---------------- scratch (__device__ globals; no allocation allowed) ----------------
__device__ float g_qkv[(size_t)ROWS*768];
__device__ float g_proj[(size_t)ROWS*Cc];
__device__ float g_x1[(size_t)ROWS*Cc];
__device__ float g_mapT[(size_t)Bb*Nn*Nn];
__device__ __nv_bfloat16 g_Ah[(size_t)ROWS*GK];
__device__ __nv_bfloat16 g_Al[(size_t)ROWS*GK];
__device__ __nv_bfloat16 g_Bt[(size_t)768*2*GK];   // [Nc, 2K]: cols [0,K)=hi, [K,2K)=lo

__device__ __forceinline__ uint32_t smem_u32(const void* p) {
    uint32_t a;
    asm("{ .reg .u64 t; cvta.to.shared.u64 t, %1; cvt.u32.u64 %0, t; }" : "=r"(a) : "l"(p));
    return a;
}
#define CP16(d, s) asm volatile("cp.async.cg.shared.global [%0], [%1], 16;" :: "r"(d), "l"(s))
#define CP_COMMIT  asm volatile("cp.async.commit_group;" ::: "memory")

__device__ __forceinline__ uint32_t bpack(__nv_bfloat16 a, __nv_bfloat16 b) {
    __nv_bfloat162 t(a, b);
    return *reinterpret_cast<uint32_t*>(&t);
}
__device__ __forceinline__ ull pack2(float x, float y) {
    float2 t = make_float2(x, y);
    return *reinterpret_cast<ull*>(&t);
}
__device__ __forceinline__ float2 unpack2(ull v) { return *reinterpret_cast<float2*>(&v); }
__device__ __forceinline__ void fma2(ull& d, ull a, ull b) {
    asm("fma.rn.f32x2 %0, %1, %2, %0;" : "+l"(d) : "l"(a), "l"(b));
}
__device__ __forceinline__ ull mul2(ull a, ull b) {
    ull r; asm("mul.rn.f32x2 %0, %1, %2;" : "=l"(r) : "l"(a), "l"(b)); return r;
}

// ---------------- map transpose: mapT[b,c,r] = map[b,r,c] ----------------
__global__ __launch_bounds__(256) void tmap_kernel(const float* __restrict__ m,
                                                   float* __restrict__ mt) {
    __shared__ float tile[32][33];
    const int b = blockIdx.z;
    const int x = blockIdx.x * 32 + threadIdx.x;
    const int ty = threadIdx.y;
#pragma unroll
    for (int dy = 0; dy < 32; dy += 8) {
        int y = blockIdx.y * 32 + ty + dy;
        tile[ty + dy][threadIdx.x] = m[(size_t)b * Nn * Nn + (size_t)y * Nn + x];
    }
    __syncthreads();
    const int xo = blockIdx.y * 32 + threadIdx.x;
#pragma unroll
    for (int dy = 0; dy < 32; dy += 8) {
        int yo = blockIdx.x * 32 + ty + dy;
        mt[(size_t)b * Nn * Nn + (size_t)yo * Nn + xo] = tile[threadIdx.x][ty + dy];
    }
}

// ---------------- split kernels: fp32 -> bf16 hi/lo ----------------
__global__ __launch_bounds__(256) void splitA(const float4* __restrict__ X,
                                              __nv_bfloat16* __restrict__ Ah,
                                              __nv_bfloat16* __restrict__ Al, int n4) {
    int i = blockIdx.x * blockDim.x + threadIdx.x;
    if (i >= n4) return;
    float4 x = X[i];
    __nv_bfloat16 h0 = __float2bfloat16(x.x), h1 = __float2bfloat16(x.y);
    __nv_bfloat16 h2 = __float2bfloat16(x.z), h3 = __float2bfloat16(x.w);
    __nv_bfloat16 l0 = __float2bfloat16(x.x - __bfloat162float(h0));
    __nv_bfloat16 l1 = __float2bfloat16(x.y - __bfloat162float(h1));
    __nv_bfloat16 l2 = __float2bfloat16(x.z - __bfloat162float(h2));
    __nv_bfloat16 l3 = __float2bfloat16(x.w - __bfloat162float(h3));
    reinterpret_cast<__nv_bfloat162*>(Ah)[i * 2 + 0] = __nv_bfloat162(h0, h1);
    reinterpret_cast<__nv_bfloat162*>(Ah)[i * 2 + 1] = __nv_bfloat162(h2, h3);
    reinterpret_cast<__nv_bfloat162*>(Al)[i * 2 + 0] = __nv_bfloat162(l0, l1);
    reinterpret_cast<__nv_bfloat162*>(Al)[i * 2 + 1] = __nv_bfloat162(l2, l3);
}

// W [K, Nc] row-major -> Bt [Nc, 2K]: Bt[n, k] = hi(W[k,n]), Bt[n, K+k] = lo(W[k,n])
__global__ __launch_bounds__(256) void splitB(const float* __restrict__ W,
                                              __nv_bfloat16* __restrict__ Bt, int Nc) {
    int idx = blockIdx.x * blockDim.x + threadIdx.x;
    if (idx >= GK * Nc) return;
    int k = idx / Nc, n = idx % Nc;
    float x = W[idx];
    __nv_bfloat16 h = __float2bfloat16(x);
    Bt[(size_t)n * (2 * GK) + k]      = h;
    Bt[(size_t)n * (2 * GK) + GK + k] = __float2bfloat16(x - __bfloat162float(h));
}

// ---------------- bf16 mma.sync GEMM, 3-stage cp.async pipeline ----------------
#define SSTR 40   // smem row stride in bf16 elems
#define GSTAGE 3
#define GTILE (128 * SSTR)                       // bf16 elems per operand stage
#define GSMEM (GSTAGE * GTILE * 2 * 2)           // bytes: 3 stages x (As+Bs)

__global__ __launch_bounds__(256) void gemm_mma(const __nv_bfloat16* __restrict__ Ah,
                                                const __nv_bfloat16* __restrict__ Al,
                                                const __nv_bfloat16* __restrict__ Bt,
                                                float* __restrict__ C, int Nc) {
    extern __shared__ __nv_bfloat16 gsm[];
    __nv_bfloat16* As = gsm;                     // [GSTAGE][GTILE]
    __nv_bfloat16* Bs = gsm + GSTAGE * GTILE;    // [GSTAGE][GTILE]

    const int tid = threadIdx.x;
    const int wid = tid >> 5, l = tid & 31;
    const int wm = (wid & 3) * 32;
    const int wn = (wid >> 2) * 64;
    const int bm = blockIdx.y * 128, bn = blockIdx.x * 128;

    float acc[2][8][4];
#pragma unroll
    for (int mt = 0; mt < 2; mt++)
#pragma unroll
        for (int nt = 0; nt < 8; nt++)
#pragma unroll
            for (int r = 0; r < 4; r++) acc[mt][nt][r] = 0.f;

    auto load_chunk = [&](int c, int st) {
        const int blk = c >> 3;                 // 0: Ah*Bh  1: Ah*Bl  2: Al*Bh
        const int k0 = (c & 7) * 32;
        const __nv_bfloat16* Ap = (blk < 2 ? Ah : Al);
        const __nv_bfloat16* Bp = Bt + (blk == 1 ? GK : 0);
#pragma unroll
        for (int w = 0; w < 2; w++) {
            int idx = tid + w * 256;
            int row = idx >> 2, seg = (idx & 3) * 8;
            CP16(smem_u32(&As[st * GTILE + row * SSTR + seg]),
                 Ap + (size_t)(bm + row) * GK + k0 + seg);
            CP16(smem_u32(&Bs[st * GTILE + row * SSTR + seg]),
                 Bp + (size_t)(bn + row) * (2 * GK) + k0 + seg);
        }
        CP_COMMIT;
    };

    load_chunk(0, 0);
    load_chunk(1, 1);

    int stage = 0;
    for (int c = 0; c < 24; c++) {
        if (c + 1 < 24) {
            asm volatile("cp.async.wait_group 1;" ::: "memory");
        } else {
            asm volatile("cp.async.wait_group 0;" ::: "memory");
        }
        __syncthreads();
        if (c + 2 < 24) {
            int st2 = stage + 2; if (st2 >= GSTAGE) st2 -= GSTAGE;
            load_chunk(c + 2, st2);
        }

        const uint32_t aBase = smem_u32(&As[stage * GTILE]);
        const uint32_t bBase = smem_u32(&Bs[stage * GTILE]);
#pragma unroll
        for (int ks = 0; ks < 32; ks += 16) {
            uint32_t a[2][4];
#pragma unroll
            for (int mt = 0; mt < 2; mt++) {
                uint32_t addr = aBase +
                    (((wm + mt * 16 + (l & 15)) * SSTR) + ks + ((l >> 4) << 3)) * 2;
                asm volatile("ldmatrix.sync.aligned.m8n8.x4.shared.b16 {%0,%1,%2,%3}, [%4];"
                             : "=r"(a[mt][0]), "=r"(a[mt][1]), "=r"(a[mt][2]), "=r"(a[mt][3])
                             : "r"(addr));
            }
            uint32_t b[8][2];
#pragma unroll
            for (int p = 0; p < 4; p++) {
                uint32_t addr = bBase +
                    (((wn + p * 16 + (l & 7) + ((l >> 4) << 3)) * SSTR) +
                     ks + (((l >> 3) & 1) << 3)) * 2;
                asm volatile("ldmatrix.sync.aligned.m8n8.x4.shared.b16 {%0,%1,%2,%3}, [%4];"
                             : "=r"(b[p * 2][0]), "=r"(b[p * 2][1]),
                               "=r"(b[p * 2 + 1][0]), "=r"(b[p * 2 + 1][1])
                             : "r"(addr));
            }
#pragma unroll
            for (int mt = 0; mt < 2; mt++)
#pragma unroll
                for (int nt = 0; nt < 8; nt++)
                    asm volatile(
                        "mma.sync.aligned.m16n8k16.row.col.f32.bf16.bf16.f32 "
                        "{%0,%1,%2,%3}, {%4,%5,%6,%7}, {%8,%9}, {%0,%1,%2,%3};"
                        : "+f"(acc[mt][nt][0]), "+f"(acc[mt][nt][1]),
                          "+f"(acc[mt][nt][2]), "+f"(acc[mt][nt][3])
                        : "r"(a[mt][0]), "r"(a[mt][1]), "r"(a[mt][2]), "r"(a[mt][3]),
                          "r"(b[nt][0]), "r"(b[nt][1]));
        }
        if (++stage >= GSTAGE) stage = 0;
    }

#pragma unroll
    for (int mt = 0; mt < 2; mt++) {
        const int row = bm + wm + mt * 16 + (l >> 2);
#pragma unroll
        for (int nt = 0; nt < 8; nt++) {
            const int col = bn + wn + nt * 8 + (l & 3) * 2;
            *reinterpret_cast<float2*>(C + (size_t)row * Nc + col) =
                make_float2(acc[mt][nt][0], acc[mt][nt][1]);
            *reinterpret_cast<float2*>(C + (size_t)(row + 8) * Nc + col) =
                make_float2(acc[mt][nt][2], acc[mt][nt][3]);
        }
    }
}

// ---------------- Fused attention: 2 heads per block, f32x2 packed math ----------------
// bias map laid out so bias(i,j) = mp[i + j*Nn]  (coalesced over threads i)
#define KSTRIDE 9
#define ATTN_SMEM (2 * Nn * KSTRIDE * 16 * 2)

__global__ __launch_bounds__(Nn, 2) void attn_kernel(const float* __restrict__ qkv,
                                                  const float* __restrict__ map,
                                                  const float* __restrict__ bw,
                                                  const float* __restrict__ bb,
                                                  __nv_bfloat16* __restrict__ Ah,
                                                  __nv_bfloat16* __restrict__ Al) {
    extern __shared__ float4 smemv[];
    float4* ks = smemv;                       // [2][Nn][KSTRIDE]
    float4* vs = smemv + 2 * Nn * KSTRIDE;    // [2][Nn][KSTRIDE]

    const int h0 = blockIdx.x * 2;
    const int m = blockIdx.y;
    const int b = blockIdx.z;
    const int i = threadIdx.x;

    const size_t rowbase = ((size_t)b * Nn + m) * Nn;
    const float scale = 0.17677669529663687f;
    const float* rowp = qkv + (rowbase + i) * 768;

    ull q2[2][16];
#pragma unroll
    for (int e = 0; e < 2; e++) {
        const float4* qp = reinterpret_cast<const float4*>(rowp + (h0 + e) * Dd);
        const float4* kp = reinterpret_cast<const float4*>(rowp + 256 + (h0 + e) * Dd);
        const float4* vp = reinterpret_cast<const float4*>(rowp + 512 + (h0 + e) * Dd);
#pragma unroll
        for (int c = 0; c < 8; c++) {
            ks[(e * Nn + i) * KSTRIDE + c] = kp[c];
            vs[(e * Nn + i) * KSTRIDE + c] = vp[c];
            float4 t = qp[c];
            q2[e][c * 2 + 0] = pack2(t.x * scale, t.y * scale);
            q2[e][c * 2 + 1] = pack2(t.z * scale, t.w * scale);
        }
    }
    __syncthreads();

    const float wv0 = bw[h0],     bv0 = bb[h0];
    const float wv1 = bw[h0 + 1], bv1 = bb[h0 + 1];
    const float* mp = map + (size_t)b * Nn * Nn + i;

    float mi0 = -INFINITY, li0 = 0.f, mi1 = -INFINITY, li1 = 0.f;
    ull acc0[16], acc1[16];
#pragma unroll
    for (int c = 0; c < 16; c++) { acc0[c] = 0ull; acc1[c] = 0ull; }

    for (int j = 0; j < Nn; j++) {
        const float mval = __ldg(&mp[(size_t)j * Nn]);
        const float4* k0 = &ks[(0 * Nn + j) * KSTRIDE];
        const float4* k1 = &ks[(1 * Nn + j) * KSTRIDE];
        ull s0p = 0ull, s1p = 0ull;
#pragma unroll
        for (int c = 0; c < 8; c++) {
            float4 ka = k0[c], kb = k1[c];
            const ull* kap = reinterpret_cast<const ull*>(&ka);
            const ull* kbp = reinterpret_cast<const ull*>(&kb);
            fma2(s0p, q2[0][c * 2 + 0], kap[0]);
            fma2(s0p, q2[0][c * 2 + 1], kap[1]);
            fma2(s1p, q2[1][c * 2 + 0], kbp[0]);
            fma2(s1p, q2[1][c * 2 + 1], kbp[1]);
        }
        float2 sv0 = unpack2(s0p), sv1 = unpack2(s1p);
        float s0 = sv0.x + sv0.y + mval * wv0 + bv0;
        float s1 = sv1.x + sv1.y + mval * wv1 + bv1;

        if (s0 > mi0) {
            float f = __expf(mi0 - s0);
            li0 *= f;
            ull fp = pack2(f, f);
#pragma unroll
            for (int c = 0; c < 16; c++) acc0[c] = mul2(acc0[c], fp);
            mi0 = s0;
        }
        if (s1 > mi1) {
            float f = __expf(mi1 - s1);
            li1 *= f;
            ull fp = pack2(f, f);
#pragma unroll
            for (int c = 0; c < 16; c++) acc1[c] = mul2(acc1[c], fp);
            mi1 = s1;
        }
        float p0 = __expf(s0 - mi0);
        float p1 = __expf(s1 - mi1);
        li0 += p0; li1 += p1;
        const ull pp0 = pack2(p0, p0);
        const ull pp1 = pack2(p1, p1);
        const float4* v0 = &vs[(0 * Nn + j) * KSTRIDE];
        const float4* v1 = &vs[(1 * Nn + j) * KSTRIDE];
#pragma unroll
        for (int c = 0; c < 8; c++) {
            float4 va = v0[c], vb = v1[c];
            const ull* vap = reinterpret_cast<const ull*>(&va);
            const ull* vbp = reinterpret_cast<const ull*>(&vb);
            fma2(acc0[c * 2 + 0], pp0, vap[0]);
            fma2(acc0[c * 2 + 1], pp0, vap[1]);
            fma2(acc1[c * 2 + 0], pp1, vbp[0]);
            fma2(acc1[c * 2 + 1], pp1, vbp[1]);
        }
    }

#pragma unroll
    for (int e = 0; e < 2; e++) {
        const float inv = e ? (1.f / li1) : (1.f / li0);
        const ull* ac = e ? acc1 : acc0;
        uint32_t wh[16], wl[16];
#pragma unroll
        for (int c = 0; c < 8; c++) {
            float2 a0 = unpack2(ac[c * 2 + 0]);
            float2 a1 = unpack2(ac[c * 2 + 1]);
            float o0 = a0.x * inv, o1 = a0.y * inv;
            float o2 = a1.x * inv, o3 = a1.y * inv;
            __nv_bfloat16 h0b = __float2bfloat16(o0), h1b = __float2bfloat16(o1);
            __nv_bfloat16 h2b = __float2bfloat16(o2), h3b = __float2bfloat16(o3);
            wh[c * 2 + 0] = bpack(h0b, h1b);
            wh[c * 2 + 1] = bpack(h2b, h3b);
            wl[c * 2 + 0] = bpack(__float2bfloat16(o0 - __bfloat162float(h0b)),
                                  __float2bfloat16(o1 - __bfloat162float(h1b)));
            wl[c * 2 + 1] = bpack(__float2bfloat16(o2 - __bfloat162float(h2b)),
                                  __float2bfloat16(o3 - __bfloat162float(h3b)));
        }
        uint4* ahp = reinterpret_cast<uint4*>(Ah + (rowbase + i) * GK + (h0 + e) * Dd);
        uint4* alp = reinterpret_cast<uint4*>(Al + (rowbase + i) * GK + (h0 + e) * Dd);
#pragma unroll
        for (int c = 0; c < 4; c++) {
            ahp[c] = make_uint4(wh[c * 4], wh[c * 4 + 1], wh[c * 4 + 2], wh[c * 4 + 3]);
            alp[c] = make_uint4(wl[c * 4], wl[c * 4 + 1], wl[c * 4 + 2], wl[c * 4 + 3]);
        }
    }
}

// ---------------- Residual + LayerNorm; transposed write; optional bf16 hi/lo emit ----------------
__global__ __launch_bounds__(Cc) void ln_kernel(const float* __restrict__ xin,
                                                const float* __restrict__ proj,
                                                const float* __restrict__ g,
                                                const float* __restrict__ bt,
                                                float* __restrict__ out,
                                                __nv_bfloat16* __restrict__ Ah,
                                                __nv_bfloat16* __restrict__ Al) {
    const int r = blockIdx.x;
    const int c = threadIdx.x;
    const float v = xin[(size_t)r * Cc + c] + proj[(size_t)r * Cc + c];

    float s = v, s2 = v * v;
#pragma unroll
    for (int o = 16; o > 0; o >>= 1) {
        s  += __shfl_down_sync(0xffffffffu, s, o);
        s2 += __shfl_down_sync(0xffffffffu, s2, o);
    }
    __shared__ float ws[8], ws2[8];
    const int w = c >> 5, l = c & 31;
    if (l == 0) { ws[w] = s; ws2[w] = s2; }
    __syncthreads();
    if (w == 0) {
        s  = (l < 8) ? ws[l]  : 0.f;
        s2 = (l < 8) ? ws2[l] : 0.f;
#pragma unroll
        for (int o = 4; o > 0; o >>= 1) {
            s  += __shfl_down_sync(0xffffffffu, s, o);
            s2 += __shfl_down_sync(0xffffffffu, s2, o);
        }
        if (l == 0) { ws[0] = s; ws2[0] = s2; }
    }
    __syncthreads();
    const float mean = ws[0] * (1.f / Cc);
    const float var  = ws2[0] * (1.f / Cc) - mean * mean;
    const float rs   = rsqrtf(var + 1e-5f);

    const int bidx = r / (Nn * Nn);
    const int rem  = r % (Nn * Nn);
    const int mm   = rem / Nn;
    const int ii   = rem % Nn;
    const size_t rt = ((size_t)bidx * Nn + ii) * Nn + mm;
    const float y = (v - mean) * rs * g[c] + bt[c];
    out[rt * Cc + c] = y;
    if (Ah) {
        __nv_bfloat16 hh = __float2bfloat16(y);
        Ah[rt * GK + c] = hh;
        Al[rt * GK + c] = __float2bfloat16(y - __bfloat162float(hh));
    }
}

extern "C" void kernel_launch(void* const* d_in, const int* in_sizes, int n_in,
                              void* d_out, int out_size) {
    const float* pair      = (const float*)d_in[0];
    const float* bulk      = (const float*)d_in[1];
    const float* row_qkv_w = (const float*)d_in[2];
    const float* row_out_w = (const float*)d_in[3];
    const float* row_ln_g  = (const float*)d_in[4];
    const float* row_ln_b  = (const float*)d_in[5];
    const float* row_bw    = (const float*)d_in[6];
    const float* row_bb    = (const float*)d_in[7];
    const float* col_qkv_w = (const float*)d_in[8];
    const float* col_out_w = (const float*)d_in[9];
    const float* col_ln_g  = (const float*)d_in[10];
    const float* col_ln_b  = (const float*)d_in[11];
    const float* col_bw    = (const float*)d_in[12];
    const float* col_bb    = (const float*)d_in[13];
    float* out = (float*)d_out;

    float *qkv, *proj, *x1, *mapT;
    __nv_bfloat16 *Ah, *Al, *Bt;
    cudaGetSymbolAddress((void**)&qkv,  g_qkv);
    cudaGetSymbolAddress((void**)&proj, g_proj);
    cudaGetSymbolAddress((void**)&x1,   g_x1);
    cudaGetSymbolAddress((void**)&mapT, g_mapT);
    cudaGetSymbolAddress((void**)&Ah,   g_Ah);
    cudaGetSymbolAddress((void**)&Al,   g_Al);
    cudaGetSymbolAddress((void**)&Bt,   g_Bt);

    cudaFuncSetAttribute(attn_kernel, cudaFuncAttributeMaxDynamicSharedMemorySize, ATTN_SMEM);
    cudaFuncSetAttribute(gemm_mma, cudaFuncAttributeMaxDynamicSharedMemorySize, GSMEM);

    const int n4 = ROWS * GK / 4;
    const int gsplitA = (n4 + 255) / 256;
    dim3 gq(768 / 128, ROWS / 128);
    dim3 gp(256 / 128, ROWS / 128);
    dim3 ga(Hh / 2, Nn, Bb);
    dim3 gt(Nn / 32, Nn / 32, Bb);

    // transposed bias map for the row pass (coalesced bias reads in both passes)
    tmap_kernel<<<gt, dim3(32, 8)>>>(bulk, mapT);

    // ---- pass 1 (row attention): bias(i,j) = map[b,i,j] = mapT[b,j,i] ----
    splitB<<<(GK * 768 + 255) / 256, 256>>>(row_qkv_w, Bt, 768);
    splitA<<<gsplitA, 256>>>((const float4*)pair, Ah, Al, n4);
    gemm_mma<<<gq, 256, GSMEM>>>(Ah, Al, Bt, qkv, 768);
    attn_kernel<<<ga, Nn, ATTN_SMEM>>>(qkv, mapT, row_bw, row_bb, Ah, Al);
    splitB<<<(GK * 256 + 255) / 256, 256>>>(row_out_w, Bt, 256);
    gemm_mma<<<gp, 256, GSMEM>>>(Ah, Al, Bt, proj, 256);
    ln_kernel<<<ROWS, Cc>>>(pair, proj, row_ln_g, row_ln_b, x1, Ah, Al);

    // ---- pass 2 (column attention): bias(i,j) = map[b,j,i] (original layout) ----
    splitB<<<(GK * 768 + 255) / 256, 256>>>(col_qkv_w, Bt, 768);
    gemm_mma<<<gq, 256, GSMEM>>>(Ah, Al, Bt, qkv, 768);
    attn_kernel<<<ga, Nn, ATTN_SMEM>>>(qkv, bulk, col_bw, col_bb, Ah, Al);
    splitB<<<(GK * 256 + 255) / 256, 256>>>(col_out_w, Bt, 256);
    gemm_mma<<<gp, 256, GSMEM>>>(Ah, Al, Bt, proj, 256);
    ln_kernel<<<ROWS, Cc>>>(x1, proj, col_ln_g, col_ln_b, out, nullptr, nullptr);
}

// round 10
// speedup vs baseline: 1.2321x; 1.0778x over previous
#include <cuda_runtime.h>
#include <cuda_bf16.h>
#include <math.h>
#include <cstdint>

#define Bb 2
#define Nn 160
#define Cc 256
#define Hh 8
#define Dd 32
#define ROWS (Bb*Nn*Nn)   // 51200
#define GK 256            // inner K of all GEMMs

typedef unsigned long long ull;

// ---------------- scratch (__device__ globals; no allocation allowed) ----------------
__device__ float g_qkv[(size_t)ROWS*768];
__device__ float g_proj[(size_t)ROWS*Cc];
__device__ float g_x1[(size_t)ROWS*Cc];
__device__ float g_mapT[(size_t)Bb*Nn*Nn];
__device__ __nv_bfloat16 g_Ah[(size_t)ROWS*GK];
__device__ __nv_bfloat16 g_Al[(size_t)ROWS*GK];
__device__ __nv_bfloat16 g_Bt[(size_t)768*2*GK];   // [Nc, 2K]: cols [0,K)=hi, [K,2K)=lo

__device__ __forceinline__ uint32_t smem_u32(const void* p) {
    uint32_t a;
    asm("{ .reg .u64 t; cvta.to.shared.u64 t, %1; cvt.u32.u64 %0, t; }" : "=r"(a) : "l"(p));
    return a;
}
#define CP16(d, s) asm volatile("cp.async.cg.shared.global [%0], [%1], 16;" :: "r"(d), "l"(s))
#define CP_COMMIT  asm volatile("cp.async.commit_group;" ::: "memory")

__device__ __forceinline__ uint32_t bpack(__nv_bfloat16 a, __nv_bfloat16 b) {
    __nv_bfloat162 t(a, b);
    return *reinterpret_cast<uint32_t*>(&t);
}
__device__ __forceinline__ ull pack2(float x, float y) {
    float2 t = make_float2(x, y);
    return *reinterpret_cast<ull*>(&t);
}
__device__ __forceinline__ float2 unpack2(ull v) { return *reinterpret_cast<float2*>(&v); }
__device__ __forceinline__ void fma2(ull& d, ull a, ull b) {
    asm("fma.rn.f32x2 %0, %1, %2, %0;" : "+l"(d) : "l"(a), "l"(b));
}
__device__ __forceinline__ ull mul2(ull a, ull b) {
    ull r; asm("mul.rn.f32x2 %0, %1, %2;" : "=l"(r) : "l"(a), "l"(b)); return r;
}

// ---------------- map transpose: mapT[b,c,r] = map[b,r,c] ----------------
__global__ __launch_bounds__(256) void tmap_kernel(const float* __restrict__ m,
                                                   float* __restrict__ mt) {
    __shared__ float tile[32][33];
    const int b = blockIdx.z;
    const int x = blockIdx.x * 32 + threadIdx.x;
    const int ty = threadIdx.y;
#pragma unroll
    for (int dy = 0; dy < 32; dy += 8) {
        int y = blockIdx.y * 32 + ty + dy;
        tile[ty + dy][threadIdx.x] = m[(size_t)b * Nn * Nn + (size_t)y * Nn + x];
    }
    __syncthreads();
    const int xo = blockIdx.y * 32 + threadIdx.x;
#pragma unroll
    for (int dy = 0; dy < 32; dy += 8) {
        int yo = blockIdx.x * 32 + ty + dy;
        mt[(size_t)b * Nn * Nn + (size_t)yo * Nn + xo] = tile[threadIdx.x][ty + dy];
    }
}

// ---------------- split kernels: fp32 -> bf16 hi/lo ----------------
__global__ __launch_bounds__(256) void splitA(const float4* __restrict__ X,
                                              __nv_bfloat16* __restrict__ Ah,
                                              __nv_bfloat16* __restrict__ Al, int n4) {
    int i = blockIdx.x * blockDim.x + threadIdx.x;
    if (i >= n4) return;
    float4 x = X[i];
    __nv_bfloat16 h0 = __float2bfloat16(x.x), h1 = __float2bfloat16(x.y);
    __nv_bfloat16 h2 = __float2bfloat16(x.z), h3 = __float2bfloat16(x.w);
    __nv_bfloat16 l0 = __float2bfloat16(x.x - __bfloat162float(h0));
    __nv_bfloat16 l1 = __float2bfloat16(x.y - __bfloat162float(h1));
    __nv_bfloat16 l2 = __float2bfloat16(x.z - __bfloat162float(h2));
    __nv_bfloat16 l3 = __float2bfloat16(x.w - __bfloat162float(h3));
    reinterpret_cast<__nv_bfloat162*>(Ah)[i * 2 + 0] = __nv_bfloat162(h0, h1);
    reinterpret_cast<__nv_bfloat162*>(Ah)[i * 2 + 1] = __nv_bfloat162(h2, h3);
    reinterpret_cast<__nv_bfloat162*>(Al)[i * 2 + 0] = __nv_bfloat162(l0, l1);
    reinterpret_cast<__nv_bfloat162*>(Al)[i * 2 + 1] = __nv_bfloat162(l2, l3);
}

// W [K, Nc] row-major -> Bt [Nc, 2K]: Bt[n, k] = hi(W[k,n]), Bt[n, K+k] = lo(W[k,n])
__global__ __launch_bounds__(256) void splitB(const float* __restrict__ W,
                                              __nv_bfloat16* __restrict__ Bt, int Nc) {
    int idx = blockIdx.x * blockDim.x + threadIdx.x;
    if (idx >= GK * Nc) return;
    int k = idx / Nc, n = idx % Nc;
    float x = W[idx];
    __nv_bfloat16 h = __float2bfloat16(x);
    Bt[(size_t)n * (2 * GK) + k]      = h;
    Bt[(size_t)n * (2 * GK) + GK + k] = __float2bfloat16(x - __bfloat162float(h));
}

// ---------------- bf16 mma.sync GEMM, k-chunk-major 3-split (shared tiles) ----------------
// Per 32-wide k chunk: load Ah, Al, Bh, Bl tiles ONCE; acc += Ah*Bh + Ah*Bl + Al*Bh.
#define SSTR 40                                   // smem row stride in bf16 elems (80B)
#define GTILE (128 * SSTR)                        // bf16 elems per tile
#define GSTAGE 2
#define NCHUNK (GK / 32)                          // 8
#define GSMEM (GSTAGE * 4 * GTILE * 2)            // bytes

__global__ __launch_bounds__(256, 2) void gemm_mma(const __nv_bfloat16* __restrict__ Ah,
                                                const __nv_bfloat16* __restrict__ Al,
                                                const __nv_bfloat16* __restrict__ Bt,
                                                float* __restrict__ C, int Nc) {
    extern __shared__ __nv_bfloat16 gsm[];
    // layout per stage: [Ah tile][Al tile][Bh tile][Bl tile]

    const int tid = threadIdx.x;
    const int wid = tid >> 5, l = tid & 31;
    const int wm = (wid & 3) * 32;
    const int wn = (wid >> 2) * 64;
    const int bm = blockIdx.y * 128, bn = blockIdx.x * 128;

    float acc[2][8][4];
#pragma unroll
    for (int mt = 0; mt < 2; mt++)
#pragma unroll
        for (int nt = 0; nt < 8; nt++)
#pragma unroll
            for (int r = 0; r < 4; r++) acc[mt][nt][r] = 0.f;

    auto load_chunk = [&](int c, int st) {
        const int k0 = c * 32;
        __nv_bfloat16* base = gsm + st * 4 * GTILE;
#pragma unroll
        for (int w = 0; w < 2; w++) {
            int idx = tid + w * 256;
            int row = idx >> 2, seg = (idx & 3) * 8;
            uint32_t soff = (uint32_t)(row * SSTR + seg);
            CP16(smem_u32(base + 0 * GTILE + soff),
                 Ah + (size_t)(bm + row) * GK + k0 + seg);
            CP16(smem_u32(base + 1 * GTILE + soff),
                 Al + (size_t)(bm + row) * GK + k0 + seg);
            CP16(smem_u32(base + 2 * GTILE + soff),
                 Bt + (size_t)(bn + row) * (2 * GK) + k0 + seg);
            CP16(smem_u32(base + 3 * GTILE + soff),
                 Bt + (size_t)(bn + row) * (2 * GK) + GK + k0 + seg);
        }
        CP_COMMIT;
    };

    load_chunk(0, 0);

    int st = 0;
    for (int c = 0; c < NCHUNK; c++) {
        asm volatile("cp.async.wait_group 0;" ::: "memory");
        __syncthreads();
        if (c + 1 < NCHUNK) load_chunk(c + 1, st ^ 1);

        const __nv_bfloat16* base = gsm + st * 4 * GTILE;
        const uint32_t aHb = smem_u32(base + 0 * GTILE);
        const uint32_t aLb = smem_u32(base + 1 * GTILE);
        const uint32_t bHb = smem_u32(base + 2 * GTILE);
        const uint32_t bLb = smem_u32(base + 3 * GTILE);

#pragma unroll
        for (int ks = 0; ks < 32; ks += 16) {
            uint32_t ah[2][4], al[2][4], bh[8][2], bl[8][2];
            uint32_t aoff[2], boff[4];
#pragma unroll
            for (int mt = 0; mt < 2; mt++)
                aoff[mt] = (((wm + mt * 16 + (l & 15)) * SSTR) + ks + ((l >> 4) << 3)) * 2;
#pragma unroll
            for (int p = 0; p < 4; p++)
                boff[p] = (((wn + p * 16 + (l & 7) + ((l >> 4) << 3)) * SSTR) +
                           ks + (((l >> 3) & 1) << 3)) * 2;

            // ---- Ah, Bh ----
#pragma unroll
            for (int mt = 0; mt < 2; mt++)
                asm volatile("ldmatrix.sync.aligned.m8n8.x4.shared.b16 {%0,%1,%2,%3}, [%4];"
                             : "=r"(ah[mt][0]), "=r"(ah[mt][1]), "=r"(ah[mt][2]), "=r"(ah[mt][3])
                             : "r"(aHb + aoff[mt]));
#pragma unroll
            for (int p = 0; p < 4; p++)
                asm volatile("ldmatrix.sync.aligned.m8n8.x4.shared.b16 {%0,%1,%2,%3}, [%4];"
                             : "=r"(bh[p * 2][0]), "=r"(bh[p * 2][1]),
                               "=r"(bh[p * 2 + 1][0]), "=r"(bh[p * 2 + 1][1])
                             : "r"(bHb + boff[p]));
#pragma unroll
            for (int mt = 0; mt < 2; mt++)
#pragma unroll
                for (int nt = 0; nt < 8; nt++)
                    asm volatile(
                        "mma.sync.aligned.m16n8k16.row.col.f32.bf16.bf16.f32 "
                        "{%0,%1,%2,%3}, {%4,%5,%6,%7}, {%8,%9}, {%0,%1,%2,%3};"
                        : "+f"(acc[mt][nt][0]), "+f"(acc[mt][nt][1]),
                          "+f"(acc[mt][nt][2]), "+f"(acc[mt][nt][3])
                        : "r"(ah[mt][0]), "r"(ah[mt][1]), "r"(ah[mt][2]), "r"(ah[mt][3]),
                          "r"(bh[nt][0]), "r"(bh[nt][1]));

            // ---- Ah, Bl ----
#pragma unroll
            for (int p = 0; p < 4; p++)
                asm volatile("ldmatrix.sync.aligned.m8n8.x4.shared.b16 {%0,%1,%2,%3}, [%4];"
                             : "=r"(bl[p * 2][0]), "=r"(bl[p * 2][1]),
                               "=r"(bl[p * 2 + 1][0]), "=r"(bl[p * 2 + 1][1])
                             : "r"(bLb + boff[p]));
#pragma unroll
            for (int mt = 0; mt < 2; mt++)
#pragma unroll
                for (int nt = 0; nt < 8; nt++)
                    asm volatile(
                        "mma.sync.aligned.m16n8k16.row.col.f32.bf16.bf16.f32 "
                        "{%0,%1,%2,%3}, {%4,%5,%6,%7}, {%8,%9}, {%0,%1,%2,%3};"
                        : "+f"(acc[mt][nt][0]), "+f"(acc[mt][nt][1]),
                          "+f"(acc[mt][nt][2]), "+f"(acc[mt][nt][3])
                        : "r"(ah[mt][0]), "r"(ah[mt][1]), "r"(ah[mt][2]), "r"(ah[mt][3]),
                          "r"(bl[nt][0]), "r"(bl[nt][1]));

            // ---- Al, Bh ----
#pragma unroll
            for (int mt = 0; mt < 2; mt++)
                asm volatile("ldmatrix.sync.aligned.m8n8.x4.shared.b16 {%0,%1,%2,%3}, [%4];"
                             : "=r"(al[mt][0]), "=r"(al[mt][1]), "=r"(al[mt][2]), "=r"(al[mt][3])
                             : "r"(aLb + aoff[mt]));
#pragma unroll
            for (int mt = 0; mt < 2; mt++)
#pragma unroll
                for (int nt = 0; nt < 8; nt++)
                    asm volatile(
                        "mma.sync.aligned.m16n8k16.row.col.f32.bf16.bf16.f32 "
                        "{%0,%1,%2,%3}, {%4,%5,%6,%7}, {%8,%9}, {%0,%1,%2,%3};"
                        : "+f"(acc[mt][nt][0]), "+f"(acc[mt][nt][1]),
                          "+f"(acc[mt][nt][2]), "+f"(acc[mt][nt][3])
                        : "r"(al[mt][0]), "r"(al[mt][1]), "r"(al[mt][2]), "r"(al[mt][3]),
                          "r"(bh[nt][0]), "r"(bh[nt][1]));
        }
        st ^= 1;
    }

#pragma unroll
    for (int mt = 0; mt < 2; mt++) {
        const int row = bm + wm + mt * 16 + (l >> 2);
#pragma unroll
        for (int nt = 0; nt < 8; nt++) {
            const int col = bn + wn + nt * 8 + (l & 3) * 2;
            *reinterpret_cast<float2*>(C + (size_t)row * Nc + col) =
                make_float2(acc[mt][nt][0], acc[mt][nt][1]);
            *reinterpret_cast<float2*>(C + (size_t)(row + 8) * Nc + col) =
                make_float2(acc[mt][nt][2], acc[mt][nt][3]);
        }
    }
}

// ---------------- Fused attention: 2 heads per block, f32x2 packed math ----------------
// bias map laid out so bias(i,j) = mp[i + j*Nn]  (coalesced over threads i)
#define KSTRIDE 9
#define ATTN_SMEM (2 * Nn * KSTRIDE * 16 * 2)

__global__ __launch_bounds__(Nn, 2) void attn_kernel(const float* __restrict__ qkv,
                                                  const float* __restrict__ map,
                                                  const float* __restrict__ bw,
                                                  const float* __restrict__ bb,
                                                  __nv_bfloat16* __restrict__ Ah,
                                                  __nv_bfloat16* __restrict__ Al) {
    extern __shared__ float4 smemv[];
    float4* ks = smemv;                       // [2][Nn][KSTRIDE]
    float4* vs = smemv + 2 * Nn * KSTRIDE;    // [2][Nn][KSTRIDE]

    const int h0 = blockIdx.x * 2;
    const int m = blockIdx.y;
    const int b = blockIdx.z;
    const int i = threadIdx.x;

    const size_t rowbase = ((size_t)b * Nn + m) * Nn;
    const float scale = 0.17677669529663687f;
    const float* rowp = qkv + (rowbase + i) * 768;

    ull q2[2][16];
#pragma unroll
    for (int e = 0; e < 2; e++) {
        const float4* qp = reinterpret_cast<const float4*>(rowp + (h0 + e) * Dd);
        const float4* kp = reinterpret_cast<const float4*>(rowp + 256 + (h0 + e) * Dd);
        const float4* vp = reinterpret_cast<const float4*>(rowp + 512 + (h0 + e) * Dd);
#pragma unroll
        for (int c = 0; c < 8; c++) {
            ks[(e * Nn + i) * KSTRIDE + c] = kp[c];
            vs[(e * Nn + i) * KSTRIDE + c] = vp[c];
            float4 t = qp[c];
            q2[e][c * 2 + 0] = pack2(t.x * scale, t.y * scale);
            q2[e][c * 2 + 1] = pack2(t.z * scale, t.w * scale);
        }
    }
    __syncthreads();

    const float wv0 = bw[h0],     bv0 = bb[h0];
    const float wv1 = bw[h0 + 1], bv1 = bb[h0 + 1];
    const float* mp = map + (size_t)b * Nn * Nn + i;

    float mi0 = -INFINITY, li0 = 0.f, mi1 = -INFINITY, li1 = 0.f;
    ull acc0[16], acc1[16];
#pragma unroll
    for (int c = 0; c < 16; c++) { acc0[c] = 0ull; acc1[c] = 0ull; }

    for (int j = 0; j < Nn; j++) {
        const float mval = __ldg(&mp[(size_t)j * Nn]);
        const float4* k0 = &ks[(0 * Nn + j) * KSTRIDE];
        const float4* k1 = &ks[(1 * Nn + j) * KSTRIDE];
        ull s0p = 0ull, s1p = 0ull;
#pragma unroll
        for (int c = 0; c < 8; c++) {
            float4 ka = k0[c], kb = k1[c];
            const ull* kap = reinterpret_cast<const ull*>(&ka);
            const ull* kbp = reinterpret_cast<const ull*>(&kb);
            fma2(s0p, q2[0][c * 2 + 0], kap[0]);
            fma2(s0p, q2[0][c * 2 + 1], kap[1]);
            fma2(s1p, q2[1][c * 2 + 0], kbp[0]);
            fma2(s1p, q2[1][c * 2 + 1], kbp[1]);
        }
        float2 sv0 = unpack2(s0p), sv1 = unpack2(s1p);
        float s0 = sv0.x + sv0.y + mval * wv0 + bv0;
        float s1 = sv1.x + sv1.y + mval * wv1 + bv1;

        if (s0 > mi0) {
            float f = __expf(mi0 - s0);
            li0 *= f;
            ull fp = pack2(f, f);
#pragma unroll
            for (int c = 0; c < 16; c++) acc0[c] = mul2(acc0[c], fp);
            mi0 = s0;
        }
        if (s1 > mi1) {
            float f = __expf(mi1 - s1);
            li1 *= f;
            ull fp = pack2(f, f);
#pragma unroll
            for (int c = 0; c < 16; c++) acc1[c] = mul2(acc1[c], fp);
            mi1 = s1;
        }
        float p0 = __expf(s0 - mi0);
        float p1 = __expf(s1 - mi1);
        li0 += p0; li1 += p1;
        const ull pp0 = pack2(p0, p0);
        const ull pp1 = pack2(p1, p1);
        const float4* v0 = &vs[(0 * Nn + j) * KSTRIDE];
        const float4* v1 = &vs[(1 * Nn + j) * KSTRIDE];
#pragma unroll
        for (int c = 0; c < 8; c++) {
            float4 va = v0[c], vb = v1[c];
            const ull* vap = reinterpret_cast<const ull*>(&va);
            const ull* vbp = reinterpret_cast<const ull*>(&vb);
            fma2(acc0[c * 2 + 0], pp0, vap[0]);
            fma2(acc0[c * 2 + 1], pp0, vap[1]);
            fma2(acc1[c * 2 + 0], pp1, vbp[0]);
            fma2(acc1[c * 2 + 1], pp1, vbp[1]);
        }
    }

#pragma unroll
    for (int e = 0; e < 2; e++) {
        const float inv = e ? (1.f / li1) : (1.f / li0);
        const ull* ac = e ? acc1 : acc0;
        uint32_t wh[16], wl[16];
#pragma unroll
        for (int c = 0; c < 8; c++) {
            float2 a0 = unpack2(ac[c * 2 + 0]);
            float2 a1 = unpack2(ac[c * 2 + 1]);
            float o0 = a0.x * inv, o1 = a0.y * inv;
            float o2 = a1.x * inv, o3 = a1.y * inv;
            __nv_bfloat16 h0b = __float2bfloat16(o0), h1b = __float2bfloat16(o1);
            __nv_bfloat16 h2b = __float2bfloat16(o2), h3b = __float2bfloat16(o3);
            wh[c * 2 + 0] = bpack(h0b, h1b);
            wh[c * 2 + 1] = bpack(h2b, h3b);
            wl[c * 2 + 0] = bpack(__float2bfloat16(o0 - __bfloat162float(h0b)),
                                  __float2bfloat16(o1 - __bfloat162float(h1b)));
            wl[c * 2 + 1] = bpack(__float2bfloat16(o2 - __bfloat162float(h2b)),
                                  __float2bfloat16(o3 - __bfloat162float(h3b)));
        }
        uint4* ahp = reinterpret_cast<uint4*>(Ah + (rowbase + i) * GK + (h0 + e) * Dd);
        uint4* alp = reinterpret_cast<uint4*>(Al + (rowbase + i) * GK + (h0 + e) * Dd);
#pragma unroll
        for (int c = 0; c < 4; c++) {
            ahp[c] = make_uint4(wh[c * 4], wh[c * 4 + 1], wh[c * 4 + 2], wh[c * 4 + 3]);
            alp[c] = make_uint4(wl[c * 4], wl[c * 4 + 1], wl[c * 4 + 2], wl[c * 4 + 3]);
        }
    }
}

// ---------------- Residual + LayerNorm; transposed write; optional bf16 hi/lo emit ----------------
__global__ __launch_bounds__(Cc) void ln_kernel(const float* __restrict__ xin,
                                                const float* __restrict__ proj,
                                                const float* __restrict__ g,
                                                const float* __restrict__ bt,
                                                float* __restrict__ out,
                                                __nv_bfloat16* __restrict__ Ah,
                                                __nv_bfloat16* __restrict__ Al) {
    const int r = blockIdx.x;
    const int c = threadIdx.x;
    const float v = xin[(size_t)r * Cc + c] + proj[(size_t)r * Cc + c];

    float s = v, s2 = v * v;
#pragma unroll
    for (int o = 16; o > 0; o >>= 1) {
        s  += __shfl_down_sync(0xffffffffu, s, o);
        s2 += __shfl_down_sync(0xffffffffu, s2, o);
    }
    __shared__ float ws[8], ws2[8];
    const int w = c >> 5, l = c & 31;
    if (l == 0) { ws[w] = s; ws2[w] = s2; }
    __syncthreads();
    if (w == 0) {
        s  = (l < 8) ? ws[l]  : 0.f;
        s2 = (l < 8) ? ws2[l] : 0.f;
#pragma unroll
        for (int o = 4; o > 0; o >>= 1) {
            s  += __shfl_down_sync(0xffffffffu, s, o);
            s2 += __shfl_down_sync(0xffffffffu, s2, o);
        }
        if (l == 0) { ws[0] = s; ws2[0] = s2; }
    }
    __syncthreads();
    const float mean = ws[0] * (1.f / Cc);
    const float var  = ws2[0] * (1.f / Cc) - mean * mean;
    const float rs   = rsqrtf(var + 1e-5f);

    const int bidx = r / (Nn * Nn);
    const int rem  = r % (Nn * Nn);
    const int mm   = rem / Nn;
    const int ii   = rem % Nn;
    const size_t rt = ((size_t)bidx * Nn + ii) * Nn + mm;
    const float y = (v - mean) * rs * g[c] + bt[c];
    out[rt * Cc + c] = y;
    if (Ah) {
        __nv_bfloat16 hh = __float2bfloat16(y);
        Ah[rt * GK + c] = hh;
        Al[rt * GK + c] = __float2bfloat16(y - __bfloat162float(hh));
    }
}

extern "C" void kernel_launch(void* const* d_in, const int* in_sizes, int n_in,
                              void* d_out, int out_size) {
    const float* pair      = (const float*)d_in[0];
    const float* bulk      = (const float*)d_in[1];
    const float* row_qkv_w = (const float*)d_in[2];
    const float* row_out_w = (const float*)d_in[3];
    const float* row_ln_g  = (const float*)d_in[4];
    const float* row_ln_b  = (const float*)d_in[5];
    const float* row_bw    = (const float*)d_in[6];
    const float* row_bb    = (const float*)d_in[7];
    const float* col_qkv_w = (const float*)d_in[8];
    const float* col_out_w = (const float*)d_in[9];
    const float* col_ln_g  = (const float*)d_in[10];
    const float* col_ln_b  = (const float*)d_in[11];
    const float* col_bw    = (const float*)d_in[12];
    const float* col_bb    = (const float*)d_in[13];
    float* out = (float*)d_out;

    float *qkv, *proj, *x1, *mapT;
    __nv_bfloat16 *Ah, *Al, *Bt;
    cudaGetSymbolAddress((void**)&qkv,  g_qkv);
    cudaGetSymbolAddress((void**)&proj, g_proj);
    cudaGetSymbolAddress((void**)&x1,   g_x1);
    cudaGetSymbolAddress((void**)&mapT, g_mapT);
    cudaGetSymbolAddress((void**)&Ah,   g_Ah);
    cudaGetSymbolAddress((void**)&Al,   g_Al);
    cudaGetSymbolAddress((void**)&Bt,   g_Bt);

    cudaFuncSetAttribute(attn_kernel, cudaFuncAttributeMaxDynamicSharedMemorySize, ATTN_SMEM);
    cudaFuncSetAttribute(gemm_mma, cudaFuncAttributeMaxDynamicSharedMemorySize, GSMEM);

    const int n4 = ROWS * GK / 4;
    const int gsplitA = (n4 + 255) / 256;
    dim3 gq(768 / 128, ROWS / 128);
    dim3 gp(256 / 128, ROWS / 128);
    dim3 ga(Hh / 2, Nn, Bb);
    dim3 gt(Nn / 32, Nn / 32, Bb);

    // transposed bias map for the row pass (coalesced bias reads in both passes)
    tmap_kernel<<<gt, dim3(32, 8)>>>(bulk, mapT);

    // ---- pass 1 (row attention): bias(i,j) = map[b,i,j] = mapT[b,j,i] ----
    splitB<<<(GK * 768 + 255) / 256, 256>>>(row_qkv_w, Bt, 768);
    splitA<<<gsplitA, 256>>>((const float4*)pair, Ah, Al, n4);
    gemm_mma<<<gq, 256, GSMEM>>>(Ah, Al, Bt, qkv, 768);
    attn_kernel<<<ga, Nn, ATTN_SMEM>>>(qkv, mapT, row_bw, row_bb, Ah, Al);
    splitB<<<(GK * 256 + 255) / 256, 256>>>(row_out_w, Bt, 256);
    gemm_mma<<<gp, 256, GSMEM>>>(Ah, Al, Bt, proj, 256);
    ln_kernel<<<ROWS, Cc>>>(pair, proj, row_ln_g, row_ln_b, x1, Ah, Al);

    // ---- pass 2 (column attention): bias(i,j) = map[b,j,i] (original layout) ----
    splitB<<<(GK * 768 + 255) / 256, 256>>>(col_qkv_w, Bt, 768);
    gemm_mma<<<gq, 256, GSMEM>>>(Ah, Al, Bt, qkv, 768);
    attn_kernel<<<ga, Nn, ATTN_SMEM>>>(qkv, bulk, col_bw, col_bb, Ah, Al);
    splitB<<<(GK * 256 + 255) / 256, 256>>>(col_out_w, Bt, 256);
    gemm_mma<<<gp, 256, GSMEM>>>(Ah, Al, Bt, proj, 256);
    ln_kernel<<<ROWS, Cc>>>(x1, proj, col_ln_g, col_ln_b, out, nullptr, nullptr);
}

// round 11
// speedup vs baseline: 1.2335x; 1.0012x over previous
#include <cuda_runtime.h>
#include <cuda_bf16.h>
#include <math.h>
#include <cstdint>

#define Bb 2
#define Nn 160
#define Cc 256
#define Hh 8
#define Dd 32
#define ROWS (Bb*Nn*Nn)   // 51200
#define GK 256            // inner K of all GEMMs

typedef unsigned long long ull;

// ---------------- scratch (__device__ globals; no allocation allowed) ----------------
__device__ float g_qkv[(size_t)ROWS*768];
__device__ float g_proj[(size_t)ROWS*Cc];
__device__ float g_x1[(size_t)ROWS*Cc];
__device__ float g_mapT[(size_t)Bb*Nn*Nn];
__device__ __nv_bfloat16 g_Ah[(size_t)ROWS*GK];
__device__ __nv_bfloat16 g_Al[(size_t)ROWS*GK];
__device__ __nv_bfloat16 g_Bt[(size_t)768*2*GK];   // [Nc, 2K]: cols [0,K)=hi, [K,2K)=lo

__device__ __forceinline__ uint32_t smem_u32(const void* p) {
    uint32_t a;
    asm("{ .reg .u64 t; cvta.to.shared.u64 t, %1; cvt.u32.u64 %0, t; }" : "=r"(a) : "l"(p));
    return a;
}
#define CP16(d, s) asm volatile("cp.async.cg.shared.global [%0], [%1], 16;" :: "r"(d), "l"(s))
#define CP_COMMIT  asm volatile("cp.async.commit_group;" ::: "memory")

__device__ __forceinline__ uint32_t bpack(__nv_bfloat16 a, __nv_bfloat16 b) {
    __nv_bfloat162 t(a, b);
    return *reinterpret_cast<uint32_t*>(&t);
}
__device__ __forceinline__ ull pack2(float x, float y) {
    float2 t = make_float2(x, y);
    return *reinterpret_cast<ull*>(&t);
}
__device__ __forceinline__ float2 unpack2(ull v) { return *reinterpret_cast<float2*>(&v); }
__device__ __forceinline__ void fma2(ull& d, ull a, ull b) {
    asm("fma.rn.f32x2 %0, %1, %2, %0;" : "+l"(d) : "l"(a), "l"(b));
}
__device__ __forceinline__ ull mul2(ull a, ull b) {
    ull r; asm("mul.rn.f32x2 %0, %1, %2;" : "=l"(r) : "l"(a), "l"(b)); return r;
}

// ---------------- map transpose: mapT[b,c,r] = map[b,r,c] ----------------
__global__ __launch_bounds__(256) void tmap_kernel(const float* __restrict__ m,
                                                   float* __restrict__ mt) {
    __shared__ float tile[32][33];
    const int b = blockIdx.z;
    const int x = blockIdx.x * 32 + threadIdx.x;
    const int ty = threadIdx.y;
#pragma unroll
    for (int dy = 0; dy < 32; dy += 8) {
        int y = blockIdx.y * 32 + ty + dy;
        tile[ty + dy][threadIdx.x] = m[(size_t)b * Nn * Nn + (size_t)y * Nn + x];
    }
    __syncthreads();
    const int xo = blockIdx.y * 32 + threadIdx.x;
#pragma unroll
    for (int dy = 0; dy < 32; dy += 8) {
        int yo = blockIdx.x * 32 + ty + dy;
        mt[(size_t)b * Nn * Nn + (size_t)yo * Nn + xo] = tile[threadIdx.x][ty + dy];
    }
}

// ---------------- split kernels: fp32 -> bf16 hi/lo ----------------
__global__ __launch_bounds__(256) void splitA(const float4* __restrict__ X,
                                              __nv_bfloat16* __restrict__ Ah,
                                              __nv_bfloat16* __restrict__ Al, int n4) {
    int i = blockIdx.x * blockDim.x + threadIdx.x;
    if (i >= n4) return;
    float4 x = X[i];
    __nv_bfloat16 h0 = __float2bfloat16(x.x), h1 = __float2bfloat16(x.y);
    __nv_bfloat16 h2 = __float2bfloat16(x.z), h3 = __float2bfloat16(x.w);
    __nv_bfloat16 l0 = __float2bfloat16(x.x - __bfloat162float(h0));
    __nv_bfloat16 l1 = __float2bfloat16(x.y - __bfloat162float(h1));
    __nv_bfloat16 l2 = __float2bfloat16(x.z - __bfloat162float(h2));
    __nv_bfloat16 l3 = __float2bfloat16(x.w - __bfloat162float(h3));
    reinterpret_cast<__nv_bfloat162*>(Ah)[i * 2 + 0] = __nv_bfloat162(h0, h1);
    reinterpret_cast<__nv_bfloat162*>(Ah)[i * 2 + 1] = __nv_bfloat162(h2, h3);
    reinterpret_cast<__nv_bfloat162*>(Al)[i * 2 + 0] = __nv_bfloat162(l0, l1);
    reinterpret_cast<__nv_bfloat162*>(Al)[i * 2 + 1] = __nv_bfloat162(l2, l3);
}

// W [K, Nc] row-major -> Bt [Nc, 2K]: Bt[n, k] = hi(W[k,n]), Bt[n, K+k] = lo(W[k,n])
__global__ __launch_bounds__(256) void splitB(const float* __restrict__ W,
                                              __nv_bfloat16* __restrict__ Bt, int Nc) {
    int idx = blockIdx.x * blockDim.x + threadIdx.x;
    if (idx >= GK * Nc) return;
    int k = idx / Nc, n = idx % Nc;
    float x = W[idx];
    __nv_bfloat16 h = __float2bfloat16(x);
    Bt[(size_t)n * (2 * GK) + k]      = h;
    Bt[(size_t)n * (2 * GK) + GK + k] = __float2bfloat16(x - __bfloat162float(h));
}

// ---------------- bf16 mma.sync GEMM, k-chunk-major 3-split (shared tiles) ----------------
#define SSTR 40
#define GTILE (128 * SSTR)
#define GSTAGE 2
#define NCHUNK (GK / 32)
#define GSMEM (GSTAGE * 4 * GTILE * 2)

__global__ __launch_bounds__(256, 2) void gemm_mma(const __nv_bfloat16* __restrict__ Ah,
                                                const __nv_bfloat16* __restrict__ Al,
                                                const __nv_bfloat16* __restrict__ Bt,
                                                float* __restrict__ C, int Nc) {
    extern __shared__ __nv_bfloat16 gsm[];

    const int tid = threadIdx.x;
    const int wid = tid >> 5, l = tid & 31;
    const int wm = (wid & 3) * 32;
    const int wn = (wid >> 2) * 64;
    const int bm = blockIdx.y * 128, bn = blockIdx.x * 128;

    float acc[2][8][4];
#pragma unroll
    for (int mt = 0; mt < 2; mt++)
#pragma unroll
        for (int nt = 0; nt < 8; nt++)
#pragma unroll
            for (int r = 0; r < 4; r++) acc[mt][nt][r] = 0.f;

    auto load_chunk = [&](int c, int st) {
        const int k0 = c * 32;
        __nv_bfloat16* base = gsm + st * 4 * GTILE;
#pragma unroll
        for (int w = 0; w < 2; w++) {
            int idx = tid + w * 256;
            int row = idx >> 2, seg = (idx & 3) * 8;
            uint32_t soff = (uint32_t)(row * SSTR + seg);
            CP16(smem_u32(base + 0 * GTILE + soff),
                 Ah + (size_t)(bm + row) * GK + k0 + seg);
            CP16(smem_u32(base + 1 * GTILE + soff),
                 Al + (size_t)(bm + row) * GK + k0 + seg);
            CP16(smem_u32(base + 2 * GTILE + soff),
                 Bt + (size_t)(bn + row) * (2 * GK) + k0 + seg);
            CP16(smem_u32(base + 3 * GTILE + soff),
                 Bt + (size_t)(bn + row) * (2 * GK) + GK + k0 + seg);
        }
        CP_COMMIT;
    };

    load_chunk(0, 0);

    int st = 0;
    for (int c = 0; c < NCHUNK; c++) {
        asm volatile("cp.async.wait_group 0;" ::: "memory");
        __syncthreads();
        if (c + 1 < NCHUNK) load_chunk(c + 1, st ^ 1);

        const __nv_bfloat16* base = gsm + st * 4 * GTILE;
        const uint32_t aHb = smem_u32(base + 0 * GTILE);
        const uint32_t aLb = smem_u32(base + 1 * GTILE);
        const uint32_t bHb = smem_u32(base + 2 * GTILE);
        const uint32_t bLb = smem_u32(base + 3 * GTILE);

#pragma unroll
        for (int ks = 0; ks < 32; ks += 16) {
            uint32_t ah[2][4], al[2][4], bh[8][2], bl[8][2];
            uint32_t aoff[2], boff[4];
#pragma unroll
            for (int mt = 0; mt < 2; mt++)
                aoff[mt] = (((wm + mt * 16 + (l & 15)) * SSTR) + ks + ((l >> 4) << 3)) * 2;
#pragma unroll
            for (int p = 0; p < 4; p++)
                boff[p] = (((wn + p * 16 + (l & 7) + ((l >> 4) << 3)) * SSTR) +
                           ks + (((l >> 3) & 1) << 3)) * 2;

#pragma unroll
            for (int mt = 0; mt < 2; mt++)
                asm volatile("ldmatrix.sync.aligned.m8n8.x4.shared.b16 {%0,%1,%2,%3}, [%4];"
                             : "=r"(ah[mt][0]), "=r"(ah[mt][1]), "=r"(ah[mt][2]), "=r"(ah[mt][3])
                             : "r"(aHb + aoff[mt]));
#pragma unroll
            for (int p = 0; p < 4; p++)
                asm volatile("ldmatrix.sync.aligned.m8n8.x4.shared.b16 {%0,%1,%2,%3}, [%4];"
                             : "=r"(bh[p * 2][0]), "=r"(bh[p * 2][1]),
                               "=r"(bh[p * 2 + 1][0]), "=r"(bh[p * 2 + 1][1])
                             : "r"(bHb + boff[p]));
#pragma unroll
            for (int mt = 0; mt < 2; mt++)
#pragma unroll
                for (int nt = 0; nt < 8; nt++)
                    asm volatile(
                        "mma.sync.aligned.m16n8k16.row.col.f32.bf16.bf16.f32 "
                        "{%0,%1,%2,%3}, {%4,%5,%6,%7}, {%8,%9}, {%0,%1,%2,%3};"
                        : "+f"(acc[mt][nt][0]), "+f"(acc[mt][nt][1]),
                          "+f"(acc[mt][nt][2]), "+f"(acc[mt][nt][3])
                        : "r"(ah[mt][0]), "r"(ah[mt][1]), "r"(ah[mt][2]), "r"(ah[mt][3]),
                          "r"(bh[nt][0]), "r"(bh[nt][1]));

#pragma unroll
            for (int p = 0; p < 4; p++)
                asm volatile("ldmatrix.sync.aligned.m8n8.x4.shared.b16 {%0,%1,%2,%3}, [%4];"
                             : "=r"(bl[p * 2][0]), "=r"(bl[p * 2][1]),
                               "=r"(bl[p * 2 + 1][0]), "=r"(bl[p * 2 + 1][1])
                             : "r"(bLb + boff[p]));
#pragma unroll
            for (int mt = 0; mt < 2; mt++)
#pragma unroll
                for (int nt = 0; nt < 8; nt++)
                    asm volatile(
                        "mma.sync.aligned.m16n8k16.row.col.f32.bf16.bf16.f32 "
                        "{%0,%1,%2,%3}, {%4,%5,%6,%7}, {%8,%9}, {%0,%1,%2,%3};"
                        : "+f"(acc[mt][nt][0]), "+f"(acc[mt][nt][1]),
                          "+f"(acc[mt][nt][2]), "+f"(acc[mt][nt][3])
                        : "r"(ah[mt][0]), "r"(ah[mt][1]), "r"(ah[mt][2]), "r"(ah[mt][3]),
                          "r"(bl[nt][0]), "r"(bl[nt][1]));

#pragma unroll
            for (int mt = 0; mt < 2; mt++)
                asm volatile("ldmatrix.sync.aligned.m8n8.x4.shared.b16 {%0,%1,%2,%3}, [%4];"
                             : "=r"(al[mt][0]), "=r"(al[mt][1]), "=r"(al[mt][2]), "=r"(al[mt][3])
                             : "r"(aLb + aoff[mt]));
#pragma unroll
            for (int mt = 0; mt < 2; mt++)
#pragma unroll
                for (int nt = 0; nt < 8; nt++)
                    asm volatile(
                        "mma.sync.aligned.m16n8k16.row.col.f32.bf16.bf16.f32 "
                        "{%0,%1,%2,%3}, {%4,%5,%6,%7}, {%8,%9}, {%0,%1,%2,%3};"
                        : "+f"(acc[mt][nt][0]), "+f"(acc[mt][nt][1]),
                          "+f"(acc[mt][nt][2]), "+f"(acc[mt][nt][3])
                        : "r"(al[mt][0]), "r"(al[mt][1]), "r"(al[mt][2]), "r"(al[mt][3]),
                          "r"(bh[nt][0]), "r"(bh[nt][1]));
        }
        st ^= 1;
    }

#pragma unroll
    for (int mt = 0; mt < 2; mt++) {
        const int row = bm + wm + mt * 16 + (l >> 2);
#pragma unroll
        for (int nt = 0; nt < 8; nt++) {
            const int col = bn + wn + nt * 8 + (l & 3) * 2;
            *reinterpret_cast<float2*>(C + (size_t)row * Nc + col) =
                make_float2(acc[mt][nt][0], acc[mt][nt][1]);
            *reinterpret_cast<float2*>(C + (size_t)(row + 8) * Nc + col) =
                make_float2(acc[mt][nt][2], acc[mt][nt][3]);
        }
    }
}

// ---------------- Fused attention: thread = (1 head, 2 rows), shared K/V regs ----------------
// block = 160 threads covering (b, m) x 2 heads; thread t: head e = t/80,
// rows r1 = t%80 and r2 = r1+80. Per j: 8 K-LDS + 8 V-LDS serve BOTH rows.
// bias map laid out so bias(i,j) = mp[i + j*Nn]  (coalesced over i)
#define KSTRIDE 9
#define ATTN_SMEM (2 * Nn * KSTRIDE * 16 * 2)

__global__ __launch_bounds__(Nn, 2) void attn_kernel(const float* __restrict__ qkv,
                                                  const float* __restrict__ map,
                                                  const float* __restrict__ bw,
                                                  const float* __restrict__ bb,
                                                  __nv_bfloat16* __restrict__ Ah,
                                                  __nv_bfloat16* __restrict__ Al) {
    extern __shared__ float4 smemv[];
    float4* ks = smemv;                       // [2][Nn][KSTRIDE]
    float4* vs = smemv + 2 * Nn * KSTRIDE;    // [2][Nn][KSTRIDE]

    const int h0 = blockIdx.x * 2;
    const int m = blockIdx.y;
    const int b = blockIdx.z;
    const int tid = threadIdx.x;

    const size_t rowbase = ((size_t)b * Nn + m) * Nn;
    const float scale = 0.17677669529663687f;

    // ---- K/V load phase: thread tid loads row tid for BOTH heads (coalesced) ----
    {
        const float* rowp = qkv + (rowbase + tid) * 768;
#pragma unroll
        for (int e = 0; e < 2; e++) {
            const float4* kp = reinterpret_cast<const float4*>(rowp + 256 + (h0 + e) * Dd);
            const float4* vp = reinterpret_cast<const float4*>(rowp + 512 + (h0 + e) * Dd);
#pragma unroll
            for (int c = 0; c < 8; c++) {
                ks[(e * Nn + tid) * KSTRIDE + c] = kp[c];
                vs[(e * Nn + tid) * KSTRIDE + c] = vp[c];
            }
        }
    }

    // ---- own work: head e, rows r1 / r2 ----
    const int e  = tid / 80;
    const int r1 = tid % 80;
    const int r2 = r1 + 80;
    const int hh = h0 + e;

    ull qa[16], qb[16];
    {
        const float4* qp1 = reinterpret_cast<const float4*>(qkv + (rowbase + r1) * 768 + hh * Dd);
        const float4* qp2 = reinterpret_cast<const float4*>(qkv + (rowbase + r2) * 768 + hh * Dd);
#pragma unroll
        for (int c = 0; c < 8; c++) {
            float4 t1 = qp1[c], t2 = qp2[c];
            qa[c * 2 + 0] = pack2(t1.x * scale, t1.y * scale);
            qa[c * 2 + 1] = pack2(t1.z * scale, t1.w * scale);
            qb[c * 2 + 0] = pack2(t2.x * scale, t2.y * scale);
            qb[c * 2 + 1] = pack2(t2.z * scale, t2.w * scale);
        }
    }
    __syncthreads();

    const float wv = bw[hh];
    const float bv = bb[hh];
    const float* mp1 = map + (size_t)b * Nn * Nn + r1;
    const float* mp2 = map + (size_t)b * Nn * Nn + r2;

    float mi1 = -INFINITY, li1 = 0.f, mi2 = -INFINITY, li2 = 0.f;
    ull a1[16], a2[16];
#pragma unroll
    for (int c = 0; c < 16; c++) { a1[c] = 0ull; a2[c] = 0ull; }

    for (int j = 0; j < Nn; j++) {
        const float mv1 = __ldg(&mp1[(size_t)j * Nn]);
        const float mv2 = __ldg(&mp2[(size_t)j * Nn]);
        const float4* kj = &ks[(e * Nn + j) * KSTRIDE];

        ull s1p = 0ull, s2p = 0ull;
#pragma unroll
        for (int c = 0; c < 8; c++) {
            float4 kk = kj[c];
            const ull* kp2 = reinterpret_cast<const ull*>(&kk);
            fma2(s1p, qa[c * 2 + 0], kp2[0]);
            fma2(s1p, qa[c * 2 + 1], kp2[1]);
            fma2(s2p, qb[c * 2 + 0], kp2[0]);
            fma2(s2p, qb[c * 2 + 1], kp2[1]);
        }
        float2 sv1 = unpack2(s1p), sv2 = unpack2(s2p);
        float s1 = sv1.x + sv1.y + mv1 * wv + bv;
        float s2 = sv2.x + sv2.y + mv2 * wv + bv;

        if (s1 > mi1) {
            float f = __expf(mi1 - s1);
            li1 *= f;
            ull fp = pack2(f, f);
#pragma unroll
            for (int c = 0; c < 16; c++) a1[c] = mul2(a1[c], fp);
            mi1 = s1;
        }
        if (s2 > mi2) {
            float f = __expf(mi2 - s2);
            li2 *= f;
            ull fp = pack2(f, f);
#pragma unroll
            for (int c = 0; c < 16; c++) a2[c] = mul2(a2[c], fp);
            mi2 = s2;
        }
        float p1 = __expf(s1 - mi1);
        float p2 = __expf(s2 - mi2);
        li1 += p1; li2 += p2;
        const ull pp1 = pack2(p1, p1);
        const ull pp2 = pack2(p2, p2);
        const float4* vj = &vs[(e * Nn + j) * KSTRIDE];
#pragma unroll
        for (int c = 0; c < 8; c++) {
            float4 vv = vj[c];
            const ull* vp2 = reinterpret_cast<const ull*>(&vv);
            fma2(a1[c * 2 + 0], pp1, vp2[0]);
            fma2(a1[c * 2 + 1], pp1, vp2[1]);
            fma2(a2[c * 2 + 0], pp2, vp2[0]);
            fma2(a2[c * 2 + 1], pp2, vp2[1]);
        }
    }

#pragma unroll
    for (int rr = 0; rr < 2; rr++) {
        const float inv = rr ? (1.f / li2) : (1.f / li1);
        const ull* ac = rr ? a2 : a1;
        const int row = rr ? r2 : r1;
        uint32_t wh[16], wl[16];
#pragma unroll
        for (int c = 0; c < 8; c++) {
            float2 x0 = unpack2(ac[c * 2 + 0]);
            float2 x1v = unpack2(ac[c * 2 + 1]);
            float o0 = x0.x * inv, o1 = x0.y * inv;
            float o2 = x1v.x * inv, o3 = x1v.y * inv;
            __nv_bfloat16 h0b = __float2bfloat16(o0), h1b = __float2bfloat16(o1);
            __nv_bfloat16 h2b = __float2bfloat16(o2), h3b = __float2bfloat16(o3);
            wh[c * 2 + 0] = bpack(h0b, h1b);
            wh[c * 2 + 1] = bpack(h2b, h3b);
            wl[c * 2 + 0] = bpack(__float2bfloat16(o0 - __bfloat162float(h0b)),
                                  __float2bfloat16(o1 - __bfloat162float(h1b)));
            wl[c * 2 + 1] = bpack(__float2bfloat16(o2 - __bfloat162float(h2b)),
                                  __float2bfloat16(o3 - __bfloat162float(h3b)));
        }
        uint4* ahp = reinterpret_cast<uint4*>(Ah + (rowbase + row) * GK + hh * Dd);
        uint4* alp = reinterpret_cast<uint4*>(Al + (rowbase + row) * GK + hh * Dd);
#pragma unroll
        for (int c = 0; c < 4; c++) {
            ahp[c] = make_uint4(wh[c * 4], wh[c * 4 + 1], wh[c * 4 + 2], wh[c * 4 + 3]);
            alp[c] = make_uint4(wl[c * 4], wl[c * 4 + 1], wl[c * 4 + 2], wl[c * 4 + 3]);
        }
    }
}

// ---------------- Residual + LayerNorm; transposed write; optional bf16 hi/lo emit ----------------
__global__ __launch_bounds__(Cc) void ln_kernel(const float* __restrict__ xin,
                                                const float* __restrict__ proj,
                                                const float* __restrict__ g,
                                                const float* __restrict__ bt,
                                                float* __restrict__ out,
                                                __nv_bfloat16* __restrict__ Ah,
                                                __nv_bfloat16* __restrict__ Al) {
    const int r = blockIdx.x;
    const int c = threadIdx.x;
    const float v = xin[(size_t)r * Cc + c] + proj[(size_t)r * Cc + c];

    float s = v, s2 = v * v;
#pragma unroll
    for (int o = 16; o > 0; o >>= 1) {
        s  += __shfl_down_sync(0xffffffffu, s, o);
        s2 += __shfl_down_sync(0xffffffffu, s2, o);
    }
    __shared__ float ws[8], ws2[8];
    const int w = c >> 5, l = c & 31;
    if (l == 0) { ws[w] = s; ws2[w] = s2; }
    __syncthreads();
    if (w == 0) {
        s  = (l < 8) ? ws[l]  : 0.f;
        s2 = (l < 8) ? ws2[l] : 0.f;
#pragma unroll
        for (int o = 4; o > 0; o >>= 1) {
            s  += __shfl_down_sync(0xffffffffu, s, o);
            s2 += __shfl_down_sync(0xffffffffu, s2, o);
        }
        if (l == 0) { ws[0] = s; ws2[0] = s2; }
    }
    __syncthreads();
    const float mean = ws[0] * (1.f / Cc);
    const float var  = ws2[0] * (1.f / Cc) - mean * mean;
    const float rs   = rsqrtf(var + 1e-5f);

    const int bidx = r / (Nn * Nn);
    const int rem  = r % (Nn * Nn);
    const int mm   = rem / Nn;
    const int ii   = rem % Nn;
    const size_t rt = ((size_t)bidx * Nn + ii) * Nn + mm;
    const float y = (v - mean) * rs * g[c] + bt[c];
    out[rt * Cc + c] = y;
    if (Ah) {
        __nv_bfloat16 hh = __float2bfloat16(y);
        Ah[rt * GK + c] = hh;
        Al[rt * GK + c] = __float2bfloat16(y - __bfloat162float(hh));
    }
}

extern "C" void kernel_launch(void* const* d_in, const int* in_sizes, int n_in,
                              void* d_out, int out_size) {
    const float* pair      = (const float*)d_in[0];
    const float* bulk      = (const float*)d_in[1];
    const float* row_qkv_w = (const float*)d_in[2];
    const float* row_out_w = (const float*)d_in[3];
    const float* row_ln_g  = (const float*)d_in[4];
    const float* row_ln_b  = (const float*)d_in[5];
    const float* row_bw    = (const float*)d_in[6];
    const float* row_bb    = (const float*)d_in[7];
    const float* col_qkv_w = (const float*)d_in[8];
    const float* col_out_w = (const float*)d_in[9];
    const float* col_ln_g  = (const float*)d_in[10];
    const float* col_ln_b  = (const float*)d_in[11];
    const float* col_bw    = (const float*)d_in[12];
    const float* col_bb    = (const float*)d_in[13];
    float* out = (float*)d_out;

    float *qkv, *proj, *x1, *mapT;
    __nv_bfloat16 *Ah, *Al, *Bt;
    cudaGetSymbolAddress((void**)&qkv,  g_qkv);
    cudaGetSymbolAddress((void**)&proj, g_proj);
    cudaGetSymbolAddress((void**)&x1,   g_x1);
    cudaGetSymbolAddress((void**)&mapT, g_mapT);
    cudaGetSymbolAddress((void**)&Ah,   g_Ah);
    cudaGetSymbolAddress((void**)&Al,   g_Al);
    cudaGetSymbolAddress((void**)&Bt,   g_Bt);

    cudaFuncSetAttribute(attn_kernel, cudaFuncAttributeMaxDynamicSharedMemorySize, ATTN_SMEM);
    cudaFuncSetAttribute(gemm_mma, cudaFuncAttributeMaxDynamicSharedMemorySize, GSMEM);

    const int n4 = ROWS * GK / 4;
    const int gsplitA = (n4 + 255) / 256;
    dim3 gq(768 / 128, ROWS / 128);
    dim3 gp(256 / 128, ROWS / 128);
    dim3 ga(Hh / 2, Nn, Bb);
    dim3 gt(Nn / 32, Nn / 32, Bb);

    // transposed bias map for the row pass (coalesced bias reads in both passes)
    tmap_kernel<<<gt, dim3(32, 8)>>>(bulk, mapT);

    // ---- pass 1 (row attention): bias(i,j) = map[b,i,j] = mapT[b,j,i] ----
    splitB<<<(GK * 768 + 255) / 256, 256>>>(row_qkv_w, Bt, 768);
    splitA<<<gsplitA, 256>>>((const float4*)pair, Ah, Al, n4);
    gemm_mma<<<gq, 256, GSMEM>>>(Ah, Al, Bt, qkv, 768);
    attn_kernel<<<ga, Nn, ATTN_SMEM>>>(qkv, mapT, row_bw, row_bb, Ah, Al);
    splitB<<<(GK * 256 + 255) / 256, 256>>>(row_out_w, Bt, 256);
    gemm_mma<<<gp, 256, GSMEM>>>(Ah, Al, Bt, proj, 256);
    ln_kernel<<<ROWS, Cc>>>(pair, proj, row_ln_g, row_ln_b, x1, Ah, Al);

    // ---- pass 2 (column attention): bias(i,j) = map[b,j,i] (original layout) ----
    splitB<<<(GK * 768 + 255) / 256, 256>>>(col_qkv_w, Bt, 768);
    gemm_mma<<<gq, 256, GSMEM>>>(Ah, Al, Bt, qkv, 768);
    attn_kernel<<<ga, Nn, ATTN_SMEM>>>(qkv, bulk, col_bw, col_bb, Ah, Al);
    splitB<<<(GK * 256 + 255) / 256, 256>>>(col_out_w, Bt, 256);
    gemm_mma<<<gp, 256, GSMEM>>>(Ah, Al, Bt, proj, 256);
    ln_kernel<<<ROWS, Cc>>>(x1, proj, col_ln_g, col_ln_b, out, nullptr, nullptr);
}

// round 12
// speedup vs baseline: 1.5251x; 1.2365x over previous
#include <cuda_runtime.h>
#include <cuda_bf16.h>
#include <math.h>
#include <cstdint>

#define Bb 2
#define Nn 160
#define Cc 256
#define Hh 8
#define Dd 32
#define ROWS (Bb*Nn*Nn)   // 51200
#define GK 256            // inner K of all GEMMs

typedef unsigned long long ull;

// ---------------- scratch (__device__ globals; no allocation allowed) ----------------
__device__ __nv_bfloat16 g_qkvh[(size_t)ROWS*768];
__device__ __nv_bfloat16 g_qkvl[(size_t)ROWS*768];
__device__ float g_proj[(size_t)ROWS*Cc];
__device__ float g_x1[(size_t)ROWS*Cc];
__device__ __nv_bfloat16 g_Ah[(size_t)ROWS*GK];
__device__ __nv_bfloat16 g_Al[(size_t)ROWS*GK];
__device__ __nv_bfloat16 g_Bt[(size_t)768*2*GK];   // [Nc, 2K]: cols [0,K)=hi, [K,2K)=lo

__device__ __forceinline__ uint32_t smem_u32(const void* p) {
    uint32_t a;
    asm("{ .reg .u64 t; cvta.to.shared.u64 t, %1; cvt.u32.u64 %0, t; }" : "=r"(a) : "l"(p));
    return a;
}
#define CP16(d, s) asm volatile("cp.async.cg.shared.global [%0], [%1], 16;" :: "r"(d), "l"(s))
#define CP_COMMIT  asm volatile("cp.async.commit_group;" ::: "memory")

__device__ __forceinline__ uint32_t bpack(__nv_bfloat16 a, __nv_bfloat16 b) {
    __nv_bfloat162 t(a, b);
    return *reinterpret_cast<uint32_t*>(&t);
}
// split (x,y) into packed bf16 hi and lo residual
__device__ __forceinline__ void split2(float x, float y, uint32_t& hi, uint32_t& lo) {
    __nv_bfloat16 hx = __float2bfloat16(x), hy = __float2bfloat16(y);
    hi = bpack(hx, hy);
    lo = bpack(__float2bfloat16(x - __bfloat162float(hx)),
               __float2bfloat16(y - __bfloat162float(hy)));
}

#define MMA16816(d, a, b) \
    asm volatile("mma.sync.aligned.m16n8k16.row.col.f32.bf16.bf16.f32 " \
                 "{%0,%1,%2,%3}, {%4,%5,%6,%7}, {%8,%9}, {%0,%1,%2,%3};" \
                 : "+f"((d)[0]), "+f"((d)[1]), "+f"((d)[2]), "+f"((d)[3]) \
                 : "r"((a)[0]), "r"((a)[1]), "r"((a)[2]), "r"((a)[3]), \
                   "r"((b)[0]), "r"((b)[1]))

#define LDSM_X4(r, addr) \
    asm volatile("ldmatrix.sync.aligned.m8n8.x4.shared.b16 {%0,%1,%2,%3}, [%4];" \
                 : "=r"((r)[0]), "=r"((r)[1]), "=r"((r)[2]), "=r"((r)[3]) : "r"(addr))
#define LDSM_X2(r0, r1, addr) \
    asm volatile("ldmatrix.sync.aligned.m8n8.x2.shared.b16 {%0,%1}, [%2];" \
                 : "=r"(r0), "=r"(r1) : "r"(addr))
#define LDSM_X4T(r, addr) \
    asm volatile("ldmatrix.sync.aligned.m8n8.x4.trans.shared.b16 {%0,%1,%2,%3}, [%4];" \
                 : "=r"((r)[0]), "=r"((r)[1]), "=r"((r)[2]), "=r"((r)[3]) : "r"(addr))

// ---------------- split kernels: fp32 -> bf16 hi/lo ----------------
__global__ __launch_bounds__(256) void splitA(const float4* __restrict__ X,
                                              __nv_bfloat16* __restrict__ Ah,
                                              __nv_bfloat16* __restrict__ Al, int n4) {
    int i = blockIdx.x * blockDim.x + threadIdx.x;
    if (i >= n4) return;
    float4 x = X[i];
    uint32_t h0, l0, h1, l1;
    split2(x.x, x.y, h0, l0);
    split2(x.z, x.w, h1, l1);
    reinterpret_cast<uint32_t*>(Ah)[i * 2 + 0] = h0;
    reinterpret_cast<uint32_t*>(Ah)[i * 2 + 1] = h1;
    reinterpret_cast<uint32_t*>(Al)[i * 2 + 0] = l0;
    reinterpret_cast<uint32_t*>(Al)[i * 2 + 1] = l1;
}

// W [K, Nc] row-major -> Bt [Nc, 2K]
__global__ __launch_bounds__(256) void splitB(const float* __restrict__ W,
                                              __nv_bfloat16* __restrict__ Bt, int Nc) {
    int idx = blockIdx.x * blockDim.x + threadIdx.x;
    if (idx >= GK * Nc) return;
    int k = idx / Nc, n = idx % Nc;
    float x = W[idx];
    __nv_bfloat16 h = __float2bfloat16(x);
    Bt[(size_t)n * (2 * GK) + k]      = h;
    Bt[(size_t)n * (2 * GK) + GK + k] = __float2bfloat16(x - __bfloat162float(h));
}

// ---------------- bf16 mma.sync GEMM, k-chunk-major 3-split ----------------
// Epilogue: if Cf != nullptr write fp32; else write bf16 hi/lo into Ch/Cl.
#define SSTR 40
#define GTILE (128 * SSTR)
#define GSTAGE 2
#define NCHUNK (GK / 32)
#define GSMEM (GSTAGE * 4 * GTILE * 2)

__global__ __launch_bounds__(256, 2) void gemm_mma(const __nv_bfloat16* __restrict__ Ah,
                                                const __nv_bfloat16* __restrict__ Al,
                                                const __nv_bfloat16* __restrict__ Bt,
                                                float* __restrict__ Cf,
                                                __nv_bfloat16* __restrict__ Ch,
                                                __nv_bfloat16* __restrict__ Cl, int Nc) {
    extern __shared__ __nv_bfloat16 gsm[];

    const int tid = threadIdx.x;
    const int wid = tid >> 5, l = tid & 31;
    const int wm = (wid & 3) * 32;
    const int wn = (wid >> 2) * 64;
    const int bm = blockIdx.y * 128, bn = blockIdx.x * 128;

    float acc[2][8][4];
#pragma unroll
    for (int mt = 0; mt < 2; mt++)
#pragma unroll
        for (int nt = 0; nt < 8; nt++)
#pragma unroll
            for (int r = 0; r < 4; r++) acc[mt][nt][r] = 0.f;

    auto load_chunk = [&](int c, int st) {
        const int k0 = c * 32;
        __nv_bfloat16* base = gsm + st * 4 * GTILE;
#pragma unroll
        for (int w = 0; w < 2; w++) {
            int idx = tid + w * 256;
            int row = idx >> 2, seg = (idx & 3) * 8;
            uint32_t soff = (uint32_t)(row * SSTR + seg);
            CP16(smem_u32(base + 0 * GTILE + soff),
                 Ah + (size_t)(bm + row) * GK + k0 + seg);
            CP16(smem_u32(base + 1 * GTILE + soff),
                 Al + (size_t)(bm + row) * GK + k0 + seg);
            CP16(smem_u32(base + 2 * GTILE + soff),
                 Bt + (size_t)(bn + row) * (2 * GK) + k0 + seg);
            CP16(smem_u32(base + 3 * GTILE + soff),
                 Bt + (size_t)(bn + row) * (2 * GK) + GK + k0 + seg);
        }
        CP_COMMIT;
    };

    load_chunk(0, 0);

    int st = 0;
    for (int c = 0; c < NCHUNK; c++) {
        asm volatile("cp.async.wait_group 0;" ::: "memory");
        __syncthreads();
        if (c + 1 < NCHUNK) load_chunk(c + 1, st ^ 1);

        const __nv_bfloat16* base = gsm + st * 4 * GTILE;
        const uint32_t aHb = smem_u32(base + 0 * GTILE);
        const uint32_t aLb = smem_u32(base + 1 * GTILE);
        const uint32_t bHb = smem_u32(base + 2 * GTILE);
        const uint32_t bLb = smem_u32(base + 3 * GTILE);

#pragma unroll
        for (int ks = 0; ks < 32; ks += 16) {
            uint32_t ah[2][4], al[2][4], bh[8][2], bl[8][2];
            uint32_t aoff[2], boff[4];
#pragma unroll
            for (int mt = 0; mt < 2; mt++)
                aoff[mt] = (((wm + mt * 16 + (l & 15)) * SSTR) + ks + ((l >> 4) << 3)) * 2;
#pragma unroll
            for (int p = 0; p < 4; p++)
                boff[p] = (((wn + p * 16 + (l & 7) + ((l >> 4) << 3)) * SSTR) +
                           ks + (((l >> 3) & 1) << 3)) * 2;

#pragma unroll
            for (int mt = 0; mt < 2; mt++) LDSM_X4(ah[mt], aHb + aoff[mt]);
#pragma unroll
            for (int p = 0; p < 4; p++)
                asm volatile("ldmatrix.sync.aligned.m8n8.x4.shared.b16 {%0,%1,%2,%3}, [%4];"
                             : "=r"(bh[p * 2][0]), "=r"(bh[p * 2][1]),
                               "=r"(bh[p * 2 + 1][0]), "=r"(bh[p * 2 + 1][1])
                             : "r"(bHb + boff[p]));
#pragma unroll
            for (int mt = 0; mt < 2; mt++)
#pragma unroll
                for (int nt = 0; nt < 8; nt++) MMA16816(acc[mt][nt], ah[mt], bh[nt]);

#pragma unroll
            for (int p = 0; p < 4; p++)
                asm volatile("ldmatrix.sync.aligned.m8n8.x4.shared.b16 {%0,%1,%2,%3}, [%4];"
                             : "=r"(bl[p * 2][0]), "=r"(bl[p * 2][1]),
                               "=r"(bl[p * 2 + 1][0]), "=r"(bl[p * 2 + 1][1])
                             : "r"(bLb + boff[p]));
#pragma unroll
            for (int mt = 0; mt < 2; mt++)
#pragma unroll
                for (int nt = 0; nt < 8; nt++) MMA16816(acc[mt][nt], ah[mt], bl[nt]);

#pragma unroll
            for (int mt = 0; mt < 2; mt++) LDSM_X4(al[mt], aLb + aoff[mt]);
#pragma unroll
            for (int mt = 0; mt < 2; mt++)
#pragma unroll
                for (int nt = 0; nt < 8; nt++) MMA16816(acc[mt][nt], al[mt], bh[nt]);
        }
        st ^= 1;
    }

    if (Cf) {
#pragma unroll
        for (int mt = 0; mt < 2; mt++) {
            const int row = bm + wm + mt * 16 + (l >> 2);
#pragma unroll
            for (int nt = 0; nt < 8; nt++) {
                const int col = bn + wn + nt * 8 + (l & 3) * 2;
                *reinterpret_cast<float2*>(Cf + (size_t)row * Nc + col) =
                    make_float2(acc[mt][nt][0], acc[mt][nt][1]);
                *reinterpret_cast<float2*>(Cf + (size_t)(row + 8) * Nc + col) =
                    make_float2(acc[mt][nt][2], acc[mt][nt][3]);
            }
        }
    } else {
#pragma unroll
        for (int mt = 0; mt < 2; mt++) {
            const int row = bm + wm + mt * 16 + (l >> 2);
#pragma unroll
            for (int nt = 0; nt < 8; nt++) {
                const int col = bn + wn + nt * 8 + (l & 3) * 2;
                uint32_t h0, l0, h1, l1;
                split2(acc[mt][nt][0], acc[mt][nt][1], h0, l0);
                split2(acc[mt][nt][2], acc[mt][nt][3], h1, l1);
                *reinterpret_cast<uint32_t*>(Ch + (size_t)row * Nc + col)       = h0;
                *reinterpret_cast<uint32_t*>(Cl + (size_t)row * Nc + col)       = l0;
                *reinterpret_cast<uint32_t*>(Ch + (size_t)(row + 8) * Nc + col) = h1;
                *reinterpret_cast<uint32_t*>(Cl + (size_t)(row + 8) * Nc + col) = l1;
            }
        }
    }
}

// ---------------- tensor-core attention ----------------
// block = (m, b); 10 warps; per head: warp w handles q-tile w (16 rows x 160 kv).
// S = Qh@Kh + Qh@Kl + Ql@Kh (fp32 acc), full-row softmax, P split bf16,
// O = Ph@Vh + Ph@Vl + Pl@Vh. Bias: map fp32 staged in smem, idx r*si + j*sj.
#define ASTR 40                                   // bf16 row stride (80B) for K/V/Q tiles
#define AT_TILE (Nn * ASTR)                       // 6400 bf16 elems
#define AT_MAP (Nn * Nn)                          // 25600 floats
#define ATTN_SMEM (AT_MAP * 4 + 6 * AT_TILE * 2)  // 102400 + 76800 = 179200 B

__global__ __launch_bounds__(320, 1) void attn_mma(const __nv_bfloat16* __restrict__ qkvh,
                                                   const __nv_bfloat16* __restrict__ qkvl,
                                                   const float* __restrict__ map,
                                                   const float* __restrict__ bw,
                                                   const float* __restrict__ bb,
                                                   __nv_bfloat16* __restrict__ Ah,
                                                   __nv_bfloat16* __restrict__ Al,
                                                   int si, int sj) {
    extern __shared__ char asmem[];
    float* mapS = reinterpret_cast<float*>(asmem);
    __nv_bfloat16* tiles = reinterpret_cast<__nv_bfloat16*>(asmem + AT_MAP * 4);
    __nv_bfloat16* sQh = tiles + 0 * AT_TILE;
    __nv_bfloat16* sQl = tiles + 1 * AT_TILE;
    __nv_bfloat16* sKh = tiles + 2 * AT_TILE;
    __nv_bfloat16* sKl = tiles + 3 * AT_TILE;
    __nv_bfloat16* sVh = tiles + 4 * AT_TILE;
    __nv_bfloat16* sVl = tiles + 5 * AT_TILE;

    const int m = blockIdx.x, b = blockIdx.y;
    const int tid = threadIdx.x, wid = tid >> 5, l = tid & 31;
    const size_t rowbase = ((size_t)b * Nn + m) * Nn;
    const float scale = 0.17677669529663687f;

    // stage bias map (fp32, 25600 elems)
    for (int idx = tid; idx < AT_MAP / 4; idx += 320)
        CP16(smem_u32(mapS + idx * 4), map + (size_t)b * AT_MAP + idx * 4);
    CP_COMMIT;

    const int q0 = wid * 16;
    const int r0 = q0 + (l >> 2), r1 = r0 + 8;
    const int cpair = (l & 3) * 2;

    for (int h = 0; h < Hh; h++) {
        __syncthreads();   // previous head's compute done before overwriting tiles
        // stage Q/K/V hi+lo for head h (row stride 768, head cols)
        for (int idx = tid; idx < Nn * 4; idx += 320) {
            int row = idx >> 2, seg = (idx & 3) * 8;
            size_t gro = (rowbase + row) * 768;
            uint32_t so = (uint32_t)(row * ASTR + seg);
            CP16(smem_u32(sQh + so), qkvh + gro + h * Dd + seg);
            CP16(smem_u32(sQl + so), qkvl + gro + h * Dd + seg);
            CP16(smem_u32(sKh + so), qkvh + gro + 256 + h * Dd + seg);
            CP16(smem_u32(sKl + so), qkvl + gro + 256 + h * Dd + seg);
            CP16(smem_u32(sVh + so), qkvh + gro + 512 + h * Dd + seg);
            CP16(smem_u32(sVl + so), qkvl + gro + 512 + h * Dd + seg);
        }
        CP_COMMIT;
        asm volatile("cp.async.wait_group 0;" ::: "memory");
        __syncthreads();

        const float wv = bw[h], bv = bb[h];

        // ---- load Q a-frags (2 k-chunks, hi+lo) ----
        uint32_t qh[2][4], ql[2][4];
#pragma unroll
        for (int kc = 0; kc < 2; kc++) {
            uint32_t off = (uint32_t)((q0 + (l & 15)) * ASTR) * 2 + ((l >> 4) << 4) + kc * 32;
            LDSM_X4(qh[kc], smem_u32(sQh) + off);
            LDSM_X4(ql[kc], smem_u32(sQl) + off);
        }

        // ---- S = 3-split Q@K^T ----
        float S[20][4];
#pragma unroll
        for (int nt = 0; nt < 20; nt++)
#pragma unroll
            for (int r = 0; r < 4; r++) S[nt][r] = 0.f;

#pragma unroll
        for (int nt = 0; nt < 20; nt++) {
#pragma unroll
            for (int kc = 0; kc < 2; kc++) {
                uint32_t off = (uint32_t)((nt * 8 + (l & 7)) * ASTR) * 2 +
                               (((l >> 3) & 1) << 4) + kc * 32;
                uint32_t bh[2], bl2[2];
                LDSM_X2(bh[0], bh[1], smem_u32(sKh) + off);
                LDSM_X2(bl2[0], bl2[1], smem_u32(sKl) + off);
                MMA16816(S[nt], qh[kc], bh);
                MMA16816(S[nt], qh[kc], bl2);
                MMA16816(S[nt], ql[kc], bh);
            }
        }

        // ---- scale + bias ----
#pragma unroll
        for (int nt = 0; nt < 20; nt++) {
            int j0 = nt * 8 + cpair;
            S[nt][0] = S[nt][0] * scale + mapS[r0 * si + j0 * sj] * wv + bv;
            S[nt][1] = S[nt][1] * scale + mapS[r0 * si + (j0 + 1) * sj] * wv + bv;
            S[nt][2] = S[nt][2] * scale + mapS[r1 * si + j0 * sj] * wv + bv;
            S[nt][3] = S[nt][3] * scale + mapS[r1 * si + (j0 + 1) * sj] * wv + bv;
        }

        // ---- softmax (full row in regs across lane quad) ----
        float m0 = -INFINITY, m1 = -INFINITY;
#pragma unroll
        for (int nt = 0; nt < 20; nt++) {
            m0 = fmaxf(m0, fmaxf(S[nt][0], S[nt][1]));
            m1 = fmaxf(m1, fmaxf(S[nt][2], S[nt][3]));
        }
        m0 = fmaxf(m0, __shfl_xor_sync(0xffffffffu, m0, 1));
        m0 = fmaxf(m0, __shfl_xor_sync(0xffffffffu, m0, 2));
        m1 = fmaxf(m1, __shfl_xor_sync(0xffffffffu, m1, 1));
        m1 = fmaxf(m1, __shfl_xor_sync(0xffffffffu, m1, 2));

        float l0 = 0.f, l1 = 0.f;
#pragma unroll
        for (int nt = 0; nt < 20; nt++) {
            S[nt][0] = __expf(S[nt][0] - m0); l0 += S[nt][0];
            S[nt][1] = __expf(S[nt][1] - m0); l0 += S[nt][1];
            S[nt][2] = __expf(S[nt][2] - m1); l1 += S[nt][2];
            S[nt][3] = __expf(S[nt][3] - m1); l1 += S[nt][3];
        }
        l0 += __shfl_xor_sync(0xffffffffu, l0, 1);
        l0 += __shfl_xor_sync(0xffffffffu, l0, 2);
        l1 += __shfl_xor_sync(0xffffffffu, l1, 1);
        l1 += __shfl_xor_sync(0xffffffffu, l1, 2);

        // ---- O = 3-split P@V ----
        float O[4][4];
#pragma unroll
        for (int nt = 0; nt < 4; nt++)
#pragma unroll
            for (int r = 0; r < 4; r++) O[nt][r] = 0.f;

#pragma unroll
        for (int kc = 0; kc < 10; kc++) {
            uint32_t aPh[4], aPl[4];
            split2(S[kc * 2][0],     S[kc * 2][1],     aPh[0], aPl[0]);
            split2(S[kc * 2][2],     S[kc * 2][3],     aPh[1], aPl[1]);
            split2(S[kc * 2 + 1][0], S[kc * 2 + 1][1], aPh[2], aPl[2]);
            split2(S[kc * 2 + 1][2], S[kc * 2 + 1][3], aPh[3], aPl[3]);

            uint32_t bvh[4][2], bvl[4][2];
#pragma unroll
            for (int dp = 0; dp < 2; dp++) {   // d 0-15, 16-31
                uint32_t off = (uint32_t)((kc * 16 + (l & 15)) * ASTR) * 2 +
                               ((l >> 4) << 4) + dp * 32;
                uint32_t rh[4], rl[4];
                LDSM_X4T(rh, smem_u32(sVh) + off);
                LDSM_X4T(rl, smem_u32(sVl) + off);
                bvh[dp * 2][0] = rh[0]; bvh[dp * 2][1] = rh[1];
                bvh[dp * 2 + 1][0] = rh[2]; bvh[dp * 2 + 1][1] = rh[3];
                bvl[dp * 2][0] = rl[0]; bvl[dp * 2][1] = rl[1];
                bvl[dp * 2 + 1][0] = rl[2]; bvl[dp * 2 + 1][1] = rl[3];
            }
#pragma unroll
            for (int nt = 0; nt < 4; nt++) {
                MMA16816(O[nt], aPh, bvh[nt]);
                MMA16816(O[nt], aPh, bvl[nt]);
                MMA16816(O[nt], aPl, bvh[nt]);
            }
        }

        // ---- normalize + write bf16 hi/lo ----
        const float inv0 = 1.f / l0, inv1 = 1.f / l1;
#pragma unroll
        for (int nt = 0; nt < 4; nt++) {
            int col = h * Dd + nt * 8 + cpair;
            uint32_t h0v, l0v, h1v, l1v;
            split2(O[nt][0] * inv0, O[nt][1] * inv0, h0v, l0v);
            split2(O[nt][2] * inv1, O[nt][3] * inv1, h1v, l1v);
            *reinterpret_cast<uint32_t*>(Ah + (rowbase + r0) * GK + col) = h0v;
            *reinterpret_cast<uint32_t*>(Al + (rowbase + r0) * GK + col) = l0v;
            *reinterpret_cast<uint32_t*>(Ah + (rowbase + r1) * GK + col) = h1v;
            *reinterpret_cast<uint32_t*>(Al + (rowbase + r1) * GK + col) = l1v;
        }
    }
}

// ---------------- Residual + LayerNorm; transposed write; optional bf16 hi/lo emit ----------------
__global__ __launch_bounds__(Cc) void ln_kernel(const float* __restrict__ xin,
                                                const float* __restrict__ proj,
                                                const float* __restrict__ g,
                                                const float* __restrict__ bt,
                                                float* __restrict__ out,
                                                __nv_bfloat16* __restrict__ Ah,
                                                __nv_bfloat16* __restrict__ Al) {
    const int r = blockIdx.x;
    const int c = threadIdx.x;
    const float v = xin[(size_t)r * Cc + c] + proj[(size_t)r * Cc + c];

    float s = v, s2 = v * v;
#pragma unroll
    for (int o = 16; o > 0; o >>= 1) {
        s  += __shfl_down_sync(0xffffffffu, s, o);
        s2 += __shfl_down_sync(0xffffffffu, s2, o);
    }
    __shared__ float ws[8], ws2[8];
    const int w = c >> 5, l = c & 31;
    if (l == 0) { ws[w] = s; ws2[w] = s2; }
    __syncthreads();
    if (w == 0) {
        s  = (l < 8) ? ws[l]  : 0.f;
        s2 = (l < 8) ? ws2[l] : 0.f;
#pragma unroll
        for (int o = 4; o > 0; o >>= 1) {
            s  += __shfl_down_sync(0xffffffffu, s, o);
            s2 += __shfl_down_sync(0xffffffffu, s2, o);
        }
        if (l == 0) { ws[0] = s; ws2[0] = s2; }
    }
    __syncthreads();
    const float mean = ws[0] * (1.f / Cc);
    const float var  = ws2[0] * (1.f / Cc) - mean * mean;
    const float rs   = rsqrtf(var + 1e-5f);

    const int bidx = r / (Nn * Nn);
    const int rem  = r % (Nn * Nn);
    const int mm   = rem / Nn;
    const int ii   = rem % Nn;
    const size_t rt = ((size_t)bidx * Nn + ii) * Nn + mm;
    const float y = (v - mean) * rs * g[c] + bt[c];
    out[rt * Cc + c] = y;
    if (Ah) {
        __nv_bfloat16 hh = __float2bfloat16(y);
        Ah[rt * GK + c] = hh;
        Al[rt * GK + c] = __float2bfloat16(y - __bfloat162float(hh));
    }
}

extern "C" void kernel_launch(void* const* d_in, const int* in_sizes, int n_in,
                              void* d_out, int out_size) {
    const float* pair      = (const float*)d_in[0];
    const float* bulk      = (const float*)d_in[1];
    const float* row_qkv_w = (const float*)d_in[2];
    const float* row_out_w = (const float*)d_in[3];
    const float* row_ln_g  = (const float*)d_in[4];
    const float* row_ln_b  = (const float*)d_in[5];
    const float* row_bw    = (const float*)d_in[6];
    const float* row_bb    = (const float*)d_in[7];
    const float* col_qkv_w = (const float*)d_in[8];
    const float* col_out_w = (const float*)d_in[9];
    const float* col_ln_g  = (const float*)d_in[10];
    const float* col_ln_b  = (const float*)d_in[11];
    const float* col_bw    = (const float*)d_in[12];
    const float* col_bb    = (const float*)d_in[13];
    float* out = (float*)d_out;

    float *proj, *x1;
    __nv_bfloat16 *qkvh, *qkvl, *Ah, *Al, *Bt;
    cudaGetSymbolAddress((void**)&qkvh, g_qkvh);
    cudaGetSymbolAddress((void**)&qkvl, g_qkvl);
    cudaGetSymbolAddress((void**)&proj, g_proj);
    cudaGetSymbolAddress((void**)&x1,   g_x1);
    cudaGetSymbolAddress((void**)&Ah,   g_Ah);
    cudaGetSymbolAddress((void**)&Al,   g_Al);
    cudaGetSymbolAddress((void**)&Bt,   g_Bt);

    cudaFuncSetAttribute(attn_mma, cudaFuncAttributeMaxDynamicSharedMemorySize, ATTN_SMEM);
    cudaFuncSetAttribute(gemm_mma, cudaFuncAttributeMaxDynamicSharedMemorySize, GSMEM);

    const int n4 = ROWS * GK / 4;
    const int gsplitA = (n4 + 255) / 256;
    dim3 gq(768 / 128, ROWS / 128);
    dim3 gp(256 / 128, ROWS / 128);
    dim3 ga(Nn, Bb);

    // ---- pass 1 (row attention): bias(i,j) = map[b,i,j] -> si=Nn, sj=1 ----
    splitB<<<(GK * 768 + 255) / 256, 256>>>(row_qkv_w, Bt, 768);
    splitA<<<gsplitA, 256>>>((const float4*)pair, Ah, Al, n4);
    gemm_mma<<<gq, 256, GSMEM>>>(Ah, Al, Bt, nullptr, qkvh, qkvl, 768);
    attn_mma<<<ga, 320, ATTN_SMEM>>>(qkvh, qkvl, bulk, row_bw, row_bb, Ah, Al, Nn, 1);
    splitB<<<(GK * 256 + 255) / 256, 256>>>(row_out_w, Bt, 256);
    gemm_mma<<<gp, 256, GSMEM>>>(Ah, Al, Bt, proj, nullptr, nullptr, 256);
    ln_kernel<<<ROWS, Cc>>>(pair, proj, row_ln_g, row_ln_b, x1, Ah, Al);

    // ---- pass 2 (column attention): bias(i,j) = map[b,j,i] -> si=1, sj=Nn ----
    splitB<<<(GK * 768 + 255) / 256, 256>>>(col_qkv_w, Bt, 768);
    gemm_mma<<<gq, 256, GSMEM>>>(Ah, Al, Bt, nullptr, qkvh, qkvl, 768);
    attn_mma<<<ga, 320, ATTN_SMEM>>>(qkvh, qkvl, bulk, col_bw, col_bb, Ah, Al, 1, Nn);
    splitB<<<(GK * 256 + 255) / 256, 256>>>(col_out_w, Bt, 256);
    gemm_mma<<<gp, 256, GSMEM>>>(Ah, Al, Bt, proj, nullptr, nullptr, 256);
    ln_kernel<<<ROWS, Cc>>>(x1, proj, col_ln_g, col_ln_b, out, nullptr, nullptr);
}

// round 13
// speedup vs baseline: 1.6229x; 1.0641x over previous
#include <cuda_runtime.h>
#include <cuda_bf16.h>
#include <math.h>
#include <cstdint>

#define Bb 2
#define Nn 160
#define Cc 256
#define Hh 8
#define Dd 32
#define ROWS (Bb*Nn*Nn)   // 51200
#define GK 256            // inner K of all GEMMs

typedef unsigned long long ull;

// ---------------- scratch (__device__ globals; no allocation allowed) ----------------
__device__ __nv_bfloat16 g_qkvh[(size_t)ROWS*768];
__device__ __nv_bfloat16 g_qkvl[(size_t)ROWS*768];
__device__ float g_proj[(size_t)ROWS*Cc];
__device__ float g_x1[(size_t)ROWS*Cc];
__device__ float g_mapT[(size_t)Bb*Nn*Nn];
__device__ __nv_bfloat16 g_Ah[(size_t)ROWS*GK];
__device__ __nv_bfloat16 g_Al[(size_t)ROWS*GK];
__device__ __nv_bfloat16 g_Bt[(size_t)768*2*GK];   // [Nc, 2K]: cols [0,K)=hi, [K,2K)=lo

__device__ __forceinline__ uint32_t smem_u32(const void* p) {
    uint32_t a;
    asm("{ .reg .u64 t; cvta.to.shared.u64 t, %1; cvt.u32.u64 %0, t; }" : "=r"(a) : "l"(p));
    return a;
}
#define CP16(d, s) asm volatile("cp.async.cg.shared.global [%0], [%1], 16;" :: "r"(d), "l"(s))
#define CP_COMMIT  asm volatile("cp.async.commit_group;" ::: "memory")

__device__ __forceinline__ uint32_t bpack(__nv_bfloat16 a, __nv_bfloat16 b) {
    __nv_bfloat162 t(a, b);
    return *reinterpret_cast<uint32_t*>(&t);
}
__device__ __forceinline__ void split2(float x, float y, uint32_t& hi, uint32_t& lo) {
    __nv_bfloat16 hx = __float2bfloat16(x), hy = __float2bfloat16(y);
    hi = bpack(hx, hy);
    lo = bpack(__float2bfloat16(x - __bfloat162float(hx)),
               __float2bfloat16(y - __bfloat162float(hy)));
}

#define MMA16816(d, a, b) \
    asm volatile("mma.sync.aligned.m16n8k16.row.col.f32.bf16.bf16.f32 " \
                 "{%0,%1,%2,%3}, {%4,%5,%6,%7}, {%8,%9}, {%0,%1,%2,%3};" \
                 : "+f"((d)[0]), "+f"((d)[1]), "+f"((d)[2]), "+f"((d)[3]) \
                 : "r"((a)[0]), "r"((a)[1]), "r"((a)[2]), "r"((a)[3]), \
                   "r"((b)[0]), "r"((b)[1]))

#define LDSM_X4(r, addr) \
    asm volatile("ldmatrix.sync.aligned.m8n8.x4.shared.b16 {%0,%1,%2,%3}, [%4];" \
                 : "=r"((r)[0]), "=r"((r)[1]), "=r"((r)[2]), "=r"((r)[3]) : "r"(addr))
#define LDSM_X2(r0, r1, addr) \
    asm volatile("ldmatrix.sync.aligned.m8n8.x2.shared.b16 {%0,%1}, [%2];" \
                 : "=r"(r0), "=r"(r1) : "r"(addr))
#define LDSM_X4T(r, addr) \
    asm volatile("ldmatrix.sync.aligned.m8n8.x4.trans.shared.b16 {%0,%1,%2,%3}, [%4];" \
                 : "=r"((r)[0]), "=r"((r)[1]), "=r"((r)[2]), "=r"((r)[3]) : "r"(addr))

// ---------------- map transpose: mapT[b,i,j] = map[b,j,i] ----------------
__global__ __launch_bounds__(256) void tmap_kernel(const float* __restrict__ m,
                                                   float* __restrict__ mt) {
    __shared__ float tile[32][33];
    const int b = blockIdx.z;
    const int x = blockIdx.x * 32 + threadIdx.x;
    const int ty = threadIdx.y;
#pragma unroll
    for (int dy = 0; dy < 32; dy += 8) {
        int y = blockIdx.y * 32 + ty + dy;
        tile[ty + dy][threadIdx.x] = m[(size_t)b * Nn * Nn + (size_t)y * Nn + x];
    }
    __syncthreads();
    const int xo = blockIdx.y * 32 + threadIdx.x;
#pragma unroll
    for (int dy = 0; dy < 32; dy += 8) {
        int yo = blockIdx.x * 32 + ty + dy;
        mt[(size_t)b * Nn * Nn + (size_t)yo * Nn + xo] = tile[threadIdx.x][ty + dy];
    }
}

// ---------------- split kernels: fp32 -> bf16 hi/lo ----------------
__global__ __launch_bounds__(256) void splitA(const float4* __restrict__ X,
                                              __nv_bfloat16* __restrict__ Ah,
                                              __nv_bfloat16* __restrict__ Al, int n4) {
    int i = blockIdx.x * blockDim.x + threadIdx.x;
    if (i >= n4) return;
    float4 x = X[i];
    uint32_t h0, l0, h1, l1;
    split2(x.x, x.y, h0, l0);
    split2(x.z, x.w, h1, l1);
    reinterpret_cast<uint32_t*>(Ah)[i * 2 + 0] = h0;
    reinterpret_cast<uint32_t*>(Ah)[i * 2 + 1] = h1;
    reinterpret_cast<uint32_t*>(Al)[i * 2 + 0] = l0;
    reinterpret_cast<uint32_t*>(Al)[i * 2 + 1] = l1;
}

__global__ __launch_bounds__(256) void splitB(const float* __restrict__ W,
                                              __nv_bfloat16* __restrict__ Bt, int Nc) {
    int idx = blockIdx.x * blockDim.x + threadIdx.x;
    if (idx >= GK * Nc) return;
    int k = idx / Nc, n = idx % Nc;
    float x = W[idx];
    __nv_bfloat16 h = __float2bfloat16(x);
    Bt[(size_t)n * (2 * GK) + k]      = h;
    Bt[(size_t)n * (2 * GK) + GK + k] = __float2bfloat16(x - __bfloat162float(h));
}

// ---------------- bf16 mma.sync GEMM, k-chunk-major 3-split ----------------
#define SSTR 40
#define GTILE (128 * SSTR)
#define GSTAGE 2
#define NCHUNK (GK / 32)
#define GSMEM (GSTAGE * 4 * GTILE * 2)

__global__ __launch_bounds__(256, 2) void gemm_mma(const __nv_bfloat16* __restrict__ Ah,
                                                const __nv_bfloat16* __restrict__ Al,
                                                const __nv_bfloat16* __restrict__ Bt,
                                                float* __restrict__ Cf,
                                                __nv_bfloat16* __restrict__ Ch,
                                                __nv_bfloat16* __restrict__ Cl, int Nc) {
    extern __shared__ __nv_bfloat16 gsm[];

    const int tid = threadIdx.x;
    const int wid = tid >> 5, l = tid & 31;
    const int wm = (wid & 3) * 32;
    const int wn = (wid >> 2) * 64;
    const int bm = blockIdx.y * 128, bn = blockIdx.x * 128;

    float acc[2][8][4];
#pragma unroll
    for (int mt = 0; mt < 2; mt++)
#pragma unroll
        for (int nt = 0; nt < 8; nt++)
#pragma unroll
            for (int r = 0; r < 4; r++) acc[mt][nt][r] = 0.f;

    auto load_chunk = [&](int c, int st) {
        const int k0 = c * 32;
        __nv_bfloat16* base = gsm + st * 4 * GTILE;
#pragma unroll
        for (int w = 0; w < 2; w++) {
            int idx = tid + w * 256;
            int row = idx >> 2, seg = (idx & 3) * 8;
            uint32_t soff = (uint32_t)(row * SSTR + seg);
            CP16(smem_u32(base + 0 * GTILE + soff),
                 Ah + (size_t)(bm + row) * GK + k0 + seg);
            CP16(smem_u32(base + 1 * GTILE + soff),
                 Al + (size_t)(bm + row) * GK + k0 + seg);
            CP16(smem_u32(base + 2 * GTILE + soff),
                 Bt + (size_t)(bn + row) * (2 * GK) + k0 + seg);
            CP16(smem_u32(base + 3 * GTILE + soff),
                 Bt + (size_t)(bn + row) * (2 * GK) + GK + k0 + seg);
        }
        CP_COMMIT;
    };

    load_chunk(0, 0);

    int st = 0;
    for (int c = 0; c < NCHUNK; c++) {
        asm volatile("cp.async.wait_group 0;" ::: "memory");
        __syncthreads();
        if (c + 1 < NCHUNK) load_chunk(c + 1, st ^ 1);

        const __nv_bfloat16* base = gsm + st * 4 * GTILE;
        const uint32_t aHb = smem_u32(base + 0 * GTILE);
        const uint32_t aLb = smem_u32(base + 1 * GTILE);
        const uint32_t bHb = smem_u32(base + 2 * GTILE);
        const uint32_t bLb = smem_u32(base + 3 * GTILE);

#pragma unroll
        for (int ks = 0; ks < 32; ks += 16) {
            uint32_t ah[2][4], al[2][4], bh[8][2], bl[8][2];
            uint32_t aoff[2], boff[4];
#pragma unroll
            for (int mt = 0; mt < 2; mt++)
                aoff[mt] = (((wm + mt * 16 + (l & 15)) * SSTR) + ks + ((l >> 4) << 3)) * 2;
#pragma unroll
            for (int p = 0; p < 4; p++)
                boff[p] = (((wn + p * 16 + (l & 7) + ((l >> 4) << 3)) * SSTR) +
                           ks + (((l >> 3) & 1) << 3)) * 2;

#pragma unroll
            for (int mt = 0; mt < 2; mt++) LDSM_X4(ah[mt], aHb + aoff[mt]);
#pragma unroll
            for (int p = 0; p < 4; p++)
                asm volatile("ldmatrix.sync.aligned.m8n8.x4.shared.b16 {%0,%1,%2,%3}, [%4];"
                             : "=r"(bh[p * 2][0]), "=r"(bh[p * 2][1]),
                               "=r"(bh[p * 2 + 1][0]), "=r"(bh[p * 2 + 1][1])
                             : "r"(bHb + boff[p]));
#pragma unroll
            for (int mt = 0; mt < 2; mt++)
#pragma unroll
                for (int nt = 0; nt < 8; nt++) MMA16816(acc[mt][nt], ah[mt], bh[nt]);

#pragma unroll
            for (int p = 0; p < 4; p++)
                asm volatile("ldmatrix.sync.aligned.m8n8.x4.shared.b16 {%0,%1,%2,%3}, [%4];"
                             : "=r"(bl[p * 2][0]), "=r"(bl[p * 2][1]),
                               "=r"(bl[p * 2 + 1][0]), "=r"(bl[p * 2 + 1][1])
                             : "r"(bLb + boff[p]));
#pragma unroll
            for (int mt = 0; mt < 2; mt++)
#pragma unroll
                for (int nt = 0; nt < 8; nt++) MMA16816(acc[mt][nt], ah[mt], bl[nt]);

#pragma unroll
            for (int mt = 0; mt < 2; mt++) LDSM_X4(al[mt], aLb + aoff[mt]);
#pragma unroll
            for (int mt = 0; mt < 2; mt++)
#pragma unroll
                for (int nt = 0; nt < 8; nt++) MMA16816(acc[mt][nt], al[mt], bh[nt]);
        }
        st ^= 1;
    }

    if (Cf) {
#pragma unroll
        for (int mt = 0; mt < 2; mt++) {
            const int row = bm + wm + mt * 16 + (l >> 2);
#pragma unroll
            for (int nt = 0; nt < 8; nt++) {
                const int col = bn + wn + nt * 8 + (l & 3) * 2;
                *reinterpret_cast<float2*>(Cf + (size_t)row * Nc + col) =
                    make_float2(acc[mt][nt][0], acc[mt][nt][1]);
                *reinterpret_cast<float2*>(Cf + (size_t)(row + 8) * Nc + col) =
                    make_float2(acc[mt][nt][2], acc[mt][nt][3]);
            }
        }
    } else {
#pragma unroll
        for (int mt = 0; mt < 2; mt++) {
            const int row = bm + wm + mt * 16 + (l >> 2);
#pragma unroll
            for (int nt = 0; nt < 8; nt++) {
                const int col = bn + wn + nt * 8 + (l & 3) * 2;
                uint32_t h0, l0, h1, l1;
                split2(acc[mt][nt][0], acc[mt][nt][1], h0, l0);
                split2(acc[mt][nt][2], acc[mt][nt][3], h1, l1);
                *reinterpret_cast<uint32_t*>(Ch + (size_t)row * Nc + col)       = h0;
                *reinterpret_cast<uint32_t*>(Cl + (size_t)row * Nc + col)       = l0;
                *reinterpret_cast<uint32_t*>(Ch + (size_t)(row + 8) * Nc + col) = h1;
                *reinterpret_cast<uint32_t*>(Cl + (size_t)(row + 8) * Nc + col) = l1;
            }
        }
    }
}

// ---------------- tensor-core attention: double-buffered heads, direct-Q ----------------
// block = (m, b); 10 warps; warp w owns q-tile w. Map pre-oriented in GLOBAL so
// bias(i,j) = mapsrc[b, i, j] (row pass: bulk; col pass: g_mapT).
#define ASTR 40
#define AT_TILE (Nn * ASTR)                       // 6400 bf16
#define MSTR 168                                  // map smem row stride (168%32==8 -> <=2-way)
#define MAP_SM (Nn * MSTR)                        // floats
#define ATTN_SMEM (MAP_SM * 4 + 2 * 4 * AT_TILE * 2)  // 107520 + 102400 = 209920 B

__global__ __launch_bounds__(320, 1) void attn_mma(const __nv_bfloat16* __restrict__ qkvh,
                                                   const __nv_bfloat16* __restrict__ qkvl,
                                                   const float* __restrict__ mapsrc,
                                                   const float* __restrict__ bw,
                                                   const float* __restrict__ bb,
                                                   __nv_bfloat16* __restrict__ Ah,
                                                   __nv_bfloat16* __restrict__ Al) {
    extern __shared__ char asmem[];
    float* mapS = reinterpret_cast<float*>(asmem);
    __nv_bfloat16* tiles = reinterpret_cast<__nv_bfloat16*>(asmem + MAP_SM * 4);
    // per stage st: [Kh][Kl][Vh][Vl]
    auto sKh = [&](int st) { return tiles + st * 4 * AT_TILE + 0 * AT_TILE; };
    auto sKl = [&](int st) { return tiles + st * 4 * AT_TILE + 1 * AT_TILE; };
    auto sVh = [&](int st) { return tiles + st * 4 * AT_TILE + 2 * AT_TILE; };
    auto sVl = [&](int st) { return tiles + st * 4 * AT_TILE + 3 * AT_TILE; };

    const int m = blockIdx.x, b = blockIdx.y;
    const int tid = threadIdx.x, wid = tid >> 5, l = tid & 31;
    const size_t rowbase = ((size_t)b * Nn + m) * Nn;
    const float scale = 0.17677669529663687f;

    // group 0: bias map (160 x 160 fp32, padded rows)
    for (int idx = tid; idx < Nn * 40; idx += 320) {
        int row = idx / 40, c4 = idx % 40;
        CP16(smem_u32(mapS + row * MSTR + c4 * 4),
             mapsrc + (size_t)b * Nn * Nn + (size_t)row * Nn + c4 * 4);
    }
    CP_COMMIT;

    auto load_kv = [&](int h, int st) {
        for (int idx = tid; idx < Nn * 4; idx += 320) {
            int row = idx >> 2, seg = (idx & 3) * 8;
            size_t gro = (rowbase + row) * 768 + 256 + h * Dd;
            uint32_t so = (uint32_t)(row * ASTR + seg);
            CP16(smem_u32(sKh(st) + so), qkvh + gro + seg);
            CP16(smem_u32(sKl(st) + so), qkvl + gro + seg);
            CP16(smem_u32(sVh(st) + so), qkvh + gro + 256 + seg);
            CP16(smem_u32(sVl(st) + so), qkvl + gro + 256 + seg);
        }
        CP_COMMIT;
    };

    load_kv(0, 0);   // group 1

    const int q0 = wid * 16;
    const int r0 = q0 + (l >> 2), r1 = r0 + 8;
    const int cpair = (l & 3) * 2;

    int st = 0;
    for (int h = 0; h < Hh; h++) {
        __syncthreads();                     // stage st^1 free (prev head done)
        if (h + 1 < Hh) load_kv(h + 1, st ^ 1);
        if (h + 1 < Hh) { asm volatile("cp.async.wait_group 1;" ::: "memory"); }
        else            { asm volatile("cp.async.wait_group 0;" ::: "memory"); }
        __syncthreads();

        const float wv = bw[h], bv = bb[h];

        // ---- Q a-frags straight from global (canonical m16n8k16 layout) ----
        uint32_t qh[2][4], ql[2][4];
        {
            const size_t g0 = (rowbase + r0) * 768 + h * Dd;
            const size_t g1 = (rowbase + r1) * 768 + h * Dd;
#pragma unroll
            for (int kc = 0; kc < 2; kc++) {
                int col = kc * 16 + cpair;
                qh[kc][0] = *reinterpret_cast<const uint32_t*>(qkvh + g0 + col);
                qh[kc][1] = *reinterpret_cast<const uint32_t*>(qkvh + g1 + col);
                qh[kc][2] = *reinterpret_cast<const uint32_t*>(qkvh + g0 + col + 8);
                qh[kc][3] = *reinterpret_cast<const uint32_t*>(qkvh + g1 + col + 8);
                ql[kc][0] = *reinterpret_cast<const uint32_t*>(qkvl + g0 + col);
                ql[kc][1] = *reinterpret_cast<const uint32_t*>(qkvl + g1 + col);
                ql[kc][2] = *reinterpret_cast<const uint32_t*>(qkvl + g0 + col + 8);
                ql[kc][3] = *reinterpret_cast<const uint32_t*>(qkvl + g1 + col + 8);
            }
        }

        // ---- S = 3-split Q@K^T ----
        float S[20][4];
#pragma unroll
        for (int nt = 0; nt < 20; nt++)
#pragma unroll
            for (int r = 0; r < 4; r++) S[nt][r] = 0.f;

        const uint32_t kHb = smem_u32(sKh(st)), kLb = smem_u32(sKl(st));
#pragma unroll
        for (int nt = 0; nt < 20; nt++) {
#pragma unroll
            for (int kc = 0; kc < 2; kc++) {
                uint32_t off = (uint32_t)((nt * 8 + (l & 7)) * ASTR) * 2 +
                               (((l >> 3) & 1) << 4) + kc * 32;
                uint32_t bh[2], bl2[2];
                LDSM_X2(bh[0], bh[1], kHb + off);
                LDSM_X2(bl2[0], bl2[1], kLb + off);
                MMA16816(S[nt], qh[kc], bh);
                MMA16816(S[nt], qh[kc], bl2);
                MMA16816(S[nt], ql[kc], bh);
            }
        }

        // ---- scale + bias (map padded stride, <=2-way conflicts) ----
#pragma unroll
        for (int nt = 0; nt < 20; nt++) {
            int j0 = nt * 8 + cpair;
            S[nt][0] = S[nt][0] * scale + mapS[r0 * MSTR + j0]     * wv + bv;
            S[nt][1] = S[nt][1] * scale + mapS[r0 * MSTR + j0 + 1] * wv + bv;
            S[nt][2] = S[nt][2] * scale + mapS[r1 * MSTR + j0]     * wv + bv;
            S[nt][3] = S[nt][3] * scale + mapS[r1 * MSTR + j0 + 1] * wv + bv;
        }

        // ---- softmax ----
        float m0 = -INFINITY, m1 = -INFINITY;
#pragma unroll
        for (int nt = 0; nt < 20; nt++) {
            m0 = fmaxf(m0, fmaxf(S[nt][0], S[nt][1]));
            m1 = fmaxf(m1, fmaxf(S[nt][2], S[nt][3]));
        }
        m0 = fmaxf(m0, __shfl_xor_sync(0xffffffffu, m0, 1));
        m0 = fmaxf(m0, __shfl_xor_sync(0xffffffffu, m0, 2));
        m1 = fmaxf(m1, __shfl_xor_sync(0xffffffffu, m1, 1));
        m1 = fmaxf(m1, __shfl_xor_sync(0xffffffffu, m1, 2));

        float l0 = 0.f, l1 = 0.f;
#pragma unroll
        for (int nt = 0; nt < 20; nt++) {
            S[nt][0] = __expf(S[nt][0] - m0); l0 += S[nt][0];
            S[nt][1] = __expf(S[nt][1] - m0); l0 += S[nt][1];
            S[nt][2] = __expf(S[nt][2] - m1); l1 += S[nt][2];
            S[nt][3] = __expf(S[nt][3] - m1); l1 += S[nt][3];
        }
        l0 += __shfl_xor_sync(0xffffffffu, l0, 1);
        l0 += __shfl_xor_sync(0xffffffffu, l0, 2);
        l1 += __shfl_xor_sync(0xffffffffu, l1, 1);
        l1 += __shfl_xor_sync(0xffffffffu, l1, 2);

        // ---- O = 3-split P@V ----
        float O[4][4];
#pragma unroll
        for (int nt = 0; nt < 4; nt++)
#pragma unroll
            for (int r = 0; r < 4; r++) O[nt][r] = 0.f;

        const uint32_t vHb = smem_u32(sVh(st)), vLb = smem_u32(sVl(st));
#pragma unroll
        for (int kc = 0; kc < 10; kc++) {
            uint32_t aPh[4], aPl[4];
            split2(S[kc * 2][0],     S[kc * 2][1],     aPh[0], aPl[0]);
            split2(S[kc * 2][2],     S[kc * 2][3],     aPh[1], aPl[1]);
            split2(S[kc * 2 + 1][0], S[kc * 2 + 1][1], aPh[2], aPl[2]);
            split2(S[kc * 2 + 1][2], S[kc * 2 + 1][3], aPh[3], aPl[3]);

            uint32_t bvh[4][2], bvl[4][2];
#pragma unroll
            for (int dp = 0; dp < 2; dp++) {
                uint32_t off = (uint32_t)((kc * 16 + (l & 15)) * ASTR) * 2 +
                               ((l >> 4) << 4) + dp * 32;
                uint32_t rh[4], rl[4];
                LDSM_X4T(rh, vHb + off);
                LDSM_X4T(rl, vLb + off);
                bvh[dp * 2][0] = rh[0]; bvh[dp * 2][1] = rh[1];
                bvh[dp * 2 + 1][0] = rh[2]; bvh[dp * 2 + 1][1] = rh[3];
                bvl[dp * 2][0] = rl[0]; bvl[dp * 2][1] = rl[1];
                bvl[dp * 2 + 1][0] = rl[2]; bvl[dp * 2 + 1][1] = rl[3];
            }
#pragma unroll
            for (int nt = 0; nt < 4; nt++) {
                MMA16816(O[nt], aPh, bvh[nt]);
                MMA16816(O[nt], aPh, bvl[nt]);
                MMA16816(O[nt], aPl, bvh[nt]);
            }
        }

        // ---- normalize + write bf16 hi/lo ----
        const float inv0 = 1.f / l0, inv1 = 1.f / l1;
#pragma unroll
        for (int nt = 0; nt < 4; nt++) {
            int col = h * Dd + nt * 8 + cpair;
            uint32_t h0v, l0v, h1v, l1v;
            split2(O[nt][0] * inv0, O[nt][1] * inv0, h0v, l0v);
            split2(O[nt][2] * inv1, O[nt][3] * inv1, h1v, l1v);
            *reinterpret_cast<uint32_t*>(Ah + (rowbase + r0) * GK + col) = h0v;
            *reinterpret_cast<uint32_t*>(Al + (rowbase + r0) * GK + col) = l0v;
            *reinterpret_cast<uint32_t*>(Ah + (rowbase + r1) * GK + col) = h1v;
            *reinterpret_cast<uint32_t*>(Al + (rowbase + r1) * GK + col) = l1v;
        }
        st ^= 1;
    }
}

// ---------------- Residual + LayerNorm; transposed write; optional bf16 hi/lo emit ----------------
__global__ __launch_bounds__(Cc) void ln_kernel(const float* __restrict__ xin,
                                                const float* __restrict__ proj,
                                                const float* __restrict__ g,
                                                const float* __restrict__ bt,
                                                float* __restrict__ out,
                                                __nv_bfloat16* __restrict__ Ah,
                                                __nv_bfloat16* __restrict__ Al) {
    const int r = blockIdx.x;
    const int c = threadIdx.x;
    const float v = xin[(size_t)r * Cc + c] + proj[(size_t)r * Cc + c];

    float s = v, s2 = v * v;
#pragma unroll
    for (int o = 16; o > 0; o >>= 1) {
        s  += __shfl_down_sync(0xffffffffu, s, o);
        s2 += __shfl_down_sync(0xffffffffu, s2, o);
    }
    __shared__ float ws[8], ws2[8];
    const int w = c >> 5, l = c & 31;
    if (l == 0) { ws[w] = s; ws2[w] = s2; }
    __syncthreads();
    if (w == 0) {
        s  = (l < 8) ? ws[l]  : 0.f;
        s2 = (l < 8) ? ws2[l] : 0.f;
#pragma unroll
        for (int o = 4; o > 0; o >>= 1) {
            s  += __shfl_down_sync(0xffffffffu, s, o);
            s2 += __shfl_down_sync(0xffffffffu, s2, o);
        }
        if (l == 0) { ws[0] = s; ws2[0] = s2; }
    }
    __syncthreads();
    const float mean = ws[0] * (1.f / Cc);
    const float var  = ws2[0] * (1.f / Cc) - mean * mean;
    const float rs   = rsqrtf(var + 1e-5f);

    const int bidx = r / (Nn * Nn);
    const int rem  = r % (Nn * Nn);
    const int mm   = rem / Nn;
    const int ii   = rem % Nn;
    const size_t rt = ((size_t)bidx * Nn + ii) * Nn + mm;
    const float y = (v - mean) * rs * g[c] + bt[c];
    out[rt * Cc + c] = y;
    if (Ah) {
        __nv_bfloat16 hh = __float2bfloat16(y);
        Ah[rt * GK + c] = hh;
        Al[rt * GK + c] = __float2bfloat16(y - __bfloat162float(hh));
    }
}

extern "C" void kernel_launch(void* const* d_in, const int* in_sizes, int n_in,
                              void* d_out, int out_size) {
    const float* pair      = (const float*)d_in[0];
    const float* bulk      = (const float*)d_in[1];
    const float* row_qkv_w = (const float*)d_in[2];
    const float* row_out_w = (const float*)d_in[3];
    const float* row_ln_g  = (const float*)d_in[4];
    const float* row_ln_b  = (const float*)d_in[5];
    const float* row_bw    = (const float*)d_in[6];
    const float* row_bb    = (const float*)d_in[7];
    const float* col_qkv_w = (const float*)d_in[8];
    const float* col_out_w = (const float*)d_in[9];
    const float* col_ln_g  = (const float*)d_in[10];
    const float* col_ln_b  = (const float*)d_in[11];
    const float* col_bw    = (const float*)d_in[12];
    const float* col_bb    = (const float*)d_in[13];
    float* out = (float*)d_out;

    float *proj, *x1, *mapT;
    __nv_bfloat16 *qkvh, *qkvl, *Ah, *Al, *Bt;
    cudaGetSymbolAddress((void**)&qkvh, g_qkvh);
    cudaGetSymbolAddress((void**)&qkvl, g_qkvl);
    cudaGetSymbolAddress((void**)&proj, g_proj);
    cudaGetSymbolAddress((void**)&x1,   g_x1);
    cudaGetSymbolAddress((void**)&mapT, g_mapT);
    cudaGetSymbolAddress((void**)&Ah,   g_Ah);
    cudaGetSymbolAddress((void**)&Al,   g_Al);
    cudaGetSymbolAddress((void**)&Bt,   g_Bt);

    cudaFuncSetAttribute(attn_mma, cudaFuncAttributeMaxDynamicSharedMemorySize, ATTN_SMEM);
    cudaFuncSetAttribute(gemm_mma, cudaFuncAttributeMaxDynamicSharedMemorySize, GSMEM);

    const int n4 = ROWS * GK / 4;
    const int gsplitA = (n4 + 255) / 256;
    dim3 gq(768 / 128, ROWS / 128);
    dim3 gp(256 / 128, ROWS / 128);
    dim3 ga(Nn, Bb);
    dim3 gt(Nn / 32, Nn / 32, Bb);

    // column-pass bias source: mapT[b,i,j] = map[b,j,i]
    tmap_kernel<<<gt, dim3(32, 8)>>>(bulk, mapT);

    // ---- pass 1 (row attention): bias(i,j) = map[b,i,j] ----
    splitB<<<(GK * 768 + 255) / 256, 256>>>(row_qkv_w, Bt, 768);
    splitA<<<gsplitA, 256>>>((const float4*)pair, Ah, Al, n4);
    gemm_mma<<<gq, 256, GSMEM>>>(Ah, Al, Bt, nullptr, qkvh, qkvl, 768);
    attn_mma<<<ga, 320, ATTN_SMEM>>>(qkvh, qkvl, bulk, row_bw, row_bb, Ah, Al);
    splitB<<<(GK * 256 + 255) / 256, 256>>>(row_out_w, Bt, 256);
    gemm_mma<<<gp, 256, GSMEM>>>(Ah, Al, Bt, proj, nullptr, nullptr, 256);
    ln_kernel<<<ROWS, Cc>>>(pair, proj, row_ln_g, row_ln_b, x1, Ah, Al);

    // ---- pass 2 (column attention): bias(i,j) = map[b,j,i] = mapT[b,i,j] ----
    splitB<<<(GK * 768 + 255) / 256, 256>>>(col_qkv_w, Bt, 768);
    gemm_mma<<<gq, 256, GSMEM>>>(Ah, Al, Bt, nullptr, qkvh, qkvl, 768);
    attn_mma<<<ga, 320, ATTN_SMEM>>>(qkvh, qkvl, mapT, col_bw, col_bb, Ah, Al);
    splitB<<<(GK * 256 + 255) / 256, 256>>>(col_out_w, Bt, 256);
    gemm_mma<<<gp, 256, GSMEM>>>(Ah, Al, Bt, proj, nullptr, nullptr, 256);
    ln_kernel<<<ROWS, Cc>>>(x1, proj, col_ln_g, col_ln_b, out, nullptr, nullptr);
}

// round 14
// speedup vs baseline: 1.8889x; 1.1639x over previous
#include <cuda_runtime.h>
#include <cuda_bf16.h>
#include <math.h>
#include <cstdint>

#define Bb 2
#define Nn 160
#define Cc 256
#define Hh 8
#define Dd 32
#define ROWS (Bb*Nn*Nn)   // 51200
#define GK 256            // inner K of all GEMMs

typedef unsigned long long ull;

// ---------------- scratch (__device__ globals; no allocation allowed) ----------------
__device__ __nv_bfloat16 g_qkvh[(size_t)ROWS*768];
__device__ __nv_bfloat16 g_qkvl[(size_t)ROWS*768];
__device__ float g_proj[(size_t)ROWS*Cc];
__device__ float g_x1[(size_t)ROWS*Cc];
__device__ float g_mapT[(size_t)Bb*Nn*Nn];
__device__ __nv_bfloat16 g_Ah[(size_t)ROWS*GK];
__device__ __nv_bfloat16 g_Al[(size_t)ROWS*GK];
__device__ __nv_bfloat16 g_Brq[(size_t)768*2*GK];  // row qkv weights [Nc, 2K] hi|lo
__device__ __nv_bfloat16 g_Bro[(size_t)256*2*GK];
__device__ __nv_bfloat16 g_Bcq[(size_t)768*2*GK];
__device__ __nv_bfloat16 g_Bco[(size_t)256*2*GK];

__device__ __forceinline__ uint32_t smem_u32(const void* p) {
    uint32_t a;
    asm("{ .reg .u64 t; cvta.to.shared.u64 t, %1; cvt.u32.u64 %0, t; }" : "=r"(a) : "l"(p));
    return a;
}
#define CP16(d, s) asm volatile("cp.async.cg.shared.global [%0], [%1], 16;" :: "r"(d), "l"(s))
#define CP_COMMIT  asm volatile("cp.async.commit_group;" ::: "memory")

__device__ __forceinline__ uint32_t bpack(__nv_bfloat16 a, __nv_bfloat16 b) {
    __nv_bfloat162 t(a, b);
    return *reinterpret_cast<uint32_t*>(&t);
}
__device__ __forceinline__ void split2(float x, float y, uint32_t& hi, uint32_t& lo) {
    __nv_bfloat16 hx = __float2bfloat16(x), hy = __float2bfloat16(y);
    hi = bpack(hx, hy);
    lo = bpack(__float2bfloat16(x - __bfloat162float(hx)),
               __float2bfloat16(y - __bfloat162float(hy)));
}

#define MMA16816(d, a, b) \
    asm volatile("mma.sync.aligned.m16n8k16.row.col.f32.bf16.bf16.f32 " \
                 "{%0,%1,%2,%3}, {%4,%5,%6,%7}, {%8,%9}, {%0,%1,%2,%3};" \
                 : "+f"((d)[0]), "+f"((d)[1]), "+f"((d)[2]), "+f"((d)[3]) \
                 : "r"((a)[0]), "r"((a)[1]), "r"((a)[2]), "r"((a)[3]), \
                   "r"((b)[0]), "r"((b)[1]))

#define LDSM_X4(r, addr) \
    asm volatile("ldmatrix.sync.aligned.m8n8.x4.shared.b16 {%0,%1,%2,%3}, [%4];" \
                 : "=r"((r)[0]), "=r"((r)[1]), "=r"((r)[2]), "=r"((r)[3]) : "r"(addr))
#define LDSM_X2(r0, r1, addr) \
    asm volatile("ldmatrix.sync.aligned.m8n8.x2.shared.b16 {%0,%1}, [%2];" \
                 : "=r"(r0), "=r"(r1) : "r"(addr))
#define LDSM_X4T(r, addr) \
    asm volatile("ldmatrix.sync.aligned.m8n8.x4.trans.shared.b16 {%0,%1,%2,%3}, [%4];" \
                 : "=r"((r)[0]), "=r"((r)[1]), "=r"((r)[2]), "=r"((r)[3]) : "r"(addr))

// ---------------- map transpose: mapT[b,i,j] = map[b,j,i] ----------------
__global__ __launch_bounds__(256) void tmap_kernel(const float* __restrict__ m,
                                                   float* __restrict__ mt) {
    __shared__ float tile[32][33];
    const int b = blockIdx.z;
    const int x = blockIdx.x * 32 + threadIdx.x;
    const int ty = threadIdx.y;
#pragma unroll
    for (int dy = 0; dy < 32; dy += 8) {
        int y = blockIdx.y * 32 + ty + dy;
        tile[ty + dy][threadIdx.x] = m[(size_t)b * Nn * Nn + (size_t)y * Nn + x];
    }
    __syncthreads();
    const int xo = blockIdx.y * 32 + threadIdx.x;
#pragma unroll
    for (int dy = 0; dy < 32; dy += 8) {
        int yo = blockIdx.x * 32 + ty + dy;
        mt[(size_t)b * Nn * Nn + (size_t)yo * Nn + xo] = tile[threadIdx.x][ty + dy];
    }
}

// ---------------- fused weight split: all 4 weight matrices -> [Nc, 2K] hi|lo ----------------
__device__ __forceinline__ void wsplit_one(const float* W, __nv_bfloat16* Bt, int Nc, int idx) {
    int k = idx / Nc, n = idx % Nc;
    float x = W[idx];
    __nv_bfloat16 h = __float2bfloat16(x);
    Bt[(size_t)n * (2 * GK) + k]      = h;
    Bt[(size_t)n * (2 * GK) + GK + k] = __float2bfloat16(x - __bfloat162float(h));
}
__global__ __launch_bounds__(256) void splitW(const float* __restrict__ wrq,
                                              const float* __restrict__ wro,
                                              const float* __restrict__ wcq,
                                              const float* __restrict__ wco,
                                              __nv_bfloat16* __restrict__ brq,
                                              __nv_bfloat16* __restrict__ bro,
                                              __nv_bfloat16* __restrict__ bcq,
                                              __nv_bfloat16* __restrict__ bco) {
    int idx = blockIdx.x * blockDim.x + threadIdx.x;
    const int NQ = GK * 768, NO = GK * 256;
    if (idx < NQ)                 { wsplit_one(wrq, brq, 768, idx); return; }
    idx -= NQ;
    if (idx < NQ)                 { wsplit_one(wcq, bcq, 768, idx); return; }
    idx -= NQ;
    if (idx < NO)                 { wsplit_one(wro, bro, 256, idx); return; }
    idx -= NO;
    if (idx < NO)                 { wsplit_one(wco, bco, 256, idx); }
}

// ---------------- splitA: fp32 -> bf16 hi/lo ----------------
__global__ __launch_bounds__(256) void splitA(const float4* __restrict__ X,
                                              __nv_bfloat16* __restrict__ Ah,
                                              __nv_bfloat16* __restrict__ Al, int n4) {
    int i = blockIdx.x * blockDim.x + threadIdx.x;
    if (i >= n4) return;
    float4 x = X[i];
    uint32_t h0, l0, h1, l1;
    split2(x.x, x.y, h0, l0);
    split2(x.z, x.w, h1, l1);
    reinterpret_cast<uint32_t*>(Ah)[i * 2 + 0] = h0;
    reinterpret_cast<uint32_t*>(Ah)[i * 2 + 1] = h1;
    reinterpret_cast<uint32_t*>(Al)[i * 2 + 0] = l0;
    reinterpret_cast<uint32_t*>(Al)[i * 2 + 1] = l1;
}

// ---------------- bf16 mma.sync GEMM, k-chunk-major 3-split ----------------
#define SSTR 40
#define GTILE (128 * SSTR)
#define GSTAGE 2
#define NCHUNK (GK / 32)
#define GSMEM (GSTAGE * 4 * GTILE * 2)

__global__ __launch_bounds__(256, 2) void gemm_mma(const __nv_bfloat16* __restrict__ Ah,
                                                const __nv_bfloat16* __restrict__ Al,
                                                const __nv_bfloat16* __restrict__ Bt,
                                                float* __restrict__ Cf,
                                                __nv_bfloat16* __restrict__ Ch,
                                                __nv_bfloat16* __restrict__ Cl, int Nc) {
    extern __shared__ __nv_bfloat16 gsm[];

    const int tid = threadIdx.x;
    const int wid = tid >> 5, l = tid & 31;
    const int wm = (wid & 3) * 32;
    const int wn = (wid >> 2) * 64;
    const int bm = blockIdx.y * 128, bn = blockIdx.x * 128;

    float acc[2][8][4];
#pragma unroll
    for (int mt = 0; mt < 2; mt++)
#pragma unroll
        for (int nt = 0; nt < 8; nt++)
#pragma unroll
            for (int r = 0; r < 4; r++) acc[mt][nt][r] = 0.f;

    auto load_chunk = [&](int c, int st) {
        const int k0 = c * 32;
        __nv_bfloat16* base = gsm + st * 4 * GTILE;
#pragma unroll
        for (int w = 0; w < 2; w++) {
            int idx = tid + w * 256;
            int row = idx >> 2, seg = (idx & 3) * 8;
            uint32_t soff = (uint32_t)(row * SSTR + seg);
            CP16(smem_u32(base + 0 * GTILE + soff),
                 Ah + (size_t)(bm + row) * GK + k0 + seg);
            CP16(smem_u32(base + 1 * GTILE + soff),
                 Al + (size_t)(bm + row) * GK + k0 + seg);
            CP16(smem_u32(base + 2 * GTILE + soff),
                 Bt + (size_t)(bn + row) * (2 * GK) + k0 + seg);
            CP16(smem_u32(base + 3 * GTILE + soff),
                 Bt + (size_t)(bn + row) * (2 * GK) + GK + k0 + seg);
        }
        CP_COMMIT;
    };

    load_chunk(0, 0);

    int st = 0;
    for (int c = 0; c < NCHUNK; c++) {
        asm volatile("cp.async.wait_group 0;" ::: "memory");
        __syncthreads();
        if (c + 1 < NCHUNK) load_chunk(c + 1, st ^ 1);

        const __nv_bfloat16* base = gsm + st * 4 * GTILE;
        const uint32_t aHb = smem_u32(base + 0 * GTILE);
        const uint32_t aLb = smem_u32(base + 1 * GTILE);
        const uint32_t bHb = smem_u32(base + 2 * GTILE);
        const uint32_t bLb = smem_u32(base + 3 * GTILE);

#pragma unroll
        for (int ks = 0; ks < 32; ks += 16) {
            uint32_t ah[2][4], al[2][4], bh[8][2], bl[8][2];
            uint32_t aoff[2], boff[4];
#pragma unroll
            for (int mt = 0; mt < 2; mt++)
                aoff[mt] = (((wm + mt * 16 + (l & 15)) * SSTR) + ks + ((l >> 4) << 3)) * 2;
#pragma unroll
            for (int p = 0; p < 4; p++)
                boff[p] = (((wn + p * 16 + (l & 7) + ((l >> 4) << 3)) * SSTR) +
                           ks + (((l >> 3) & 1) << 3)) * 2;

#pragma unroll
            for (int mt = 0; mt < 2; mt++) LDSM_X4(ah[mt], aHb + aoff[mt]);
#pragma unroll
            for (int p = 0; p < 4; p++)
                asm volatile("ldmatrix.sync.aligned.m8n8.x4.shared.b16 {%0,%1,%2,%3}, [%4];"
                             : "=r"(bh[p * 2][0]), "=r"(bh[p * 2][1]),
                               "=r"(bh[p * 2 + 1][0]), "=r"(bh[p * 2 + 1][1])
                             : "r"(bHb + boff[p]));
#pragma unroll
            for (int mt = 0; mt < 2; mt++)
#pragma unroll
                for (int nt = 0; nt < 8; nt++) MMA16816(acc[mt][nt], ah[mt], bh[nt]);

#pragma unroll
            for (int p = 0; p < 4; p++)
                asm volatile("ldmatrix.sync.aligned.m8n8.x4.shared.b16 {%0,%1,%2,%3}, [%4];"
                             : "=r"(bl[p * 2][0]), "=r"(bl[p * 2][1]),
                               "=r"(bl[p * 2 + 1][0]), "=r"(bl[p * 2 + 1][1])
                             : "r"(bLb + boff[p]));
#pragma unroll
            for (int mt = 0; mt < 2; mt++)
#pragma unroll
                for (int nt = 0; nt < 8; nt++) MMA16816(acc[mt][nt], ah[mt], bl[nt]);

#pragma unroll
            for (int mt = 0; mt < 2; mt++) LDSM_X4(al[mt], aLb + aoff[mt]);
#pragma unroll
            for (int mt = 0; mt < 2; mt++)
#pragma unroll
                for (int nt = 0; nt < 8; nt++) MMA16816(acc[mt][nt], al[mt], bh[nt]);
        }
        st ^= 1;
    }

    if (Cf) {
#pragma unroll
        for (int mt = 0; mt < 2; mt++) {
            const int row = bm + wm + mt * 16 + (l >> 2);
#pragma unroll
            for (int nt = 0; nt < 8; nt++) {
                const int col = bn + wn + nt * 8 + (l & 3) * 2;
                *reinterpret_cast<float2*>(Cf + (size_t)row * Nc + col) =
                    make_float2(acc[mt][nt][0], acc[mt][nt][1]);
                *reinterpret_cast<float2*>(Cf + (size_t)(row + 8) * Nc + col) =
                    make_float2(acc[mt][nt][2], acc[mt][nt][3]);
            }
        }
    } else {
#pragma unroll
        for (int mt = 0; mt < 2; mt++) {
            const int row = bm + wm + mt * 16 + (l >> 2);
#pragma unroll
            for (int nt = 0; nt < 8; nt++) {
                const int col = bn + wn + nt * 8 + (l & 3) * 2;
                uint32_t h0, l0, h1, l1;
                split2(acc[mt][nt][0], acc[mt][nt][1], h0, l0);
                split2(acc[mt][nt][2], acc[mt][nt][3], h1, l1);
                *reinterpret_cast<uint32_t*>(Ch + (size_t)row * Nc + col)       = h0;
                *reinterpret_cast<uint32_t*>(Cl + (size_t)row * Nc + col)       = l0;
                *reinterpret_cast<uint32_t*>(Ch + (size_t)(row + 8) * Nc + col) = h1;
                *reinterpret_cast<uint32_t*>(Cl + (size_t)(row + 8) * Nc + col) = l1;
            }
        }
    }
}

// ---------------- tensor-core attention: 2 heads per block (wave-quantization fix) ----------------
#define ASTR 40
#define AT_TILE (Nn * ASTR)
#define MSTR 168
#define MAP_SM (Nn * MSTR)
#define ATTN_SMEM (MAP_SM * 4 + 2 * 4 * AT_TILE * 2)

__global__ __launch_bounds__(320, 1) void attn_mma(const __nv_bfloat16* __restrict__ qkvh,
                                                   const __nv_bfloat16* __restrict__ qkvl,
                                                   const float* __restrict__ mapsrc,
                                                   const float* __restrict__ bw,
                                                   const float* __restrict__ bb,
                                                   __nv_bfloat16* __restrict__ Ah,
                                                   __nv_bfloat16* __restrict__ Al) {
    extern __shared__ char asmem[];
    float* mapS = reinterpret_cast<float*>(asmem);
    __nv_bfloat16* tiles = reinterpret_cast<__nv_bfloat16*>(asmem + MAP_SM * 4);
    auto sKh = [&](int st) { return tiles + st * 4 * AT_TILE + 0 * AT_TILE; };
    auto sKl = [&](int st) { return tiles + st * 4 * AT_TILE + 1 * AT_TILE; };
    auto sVh = [&](int st) { return tiles + st * 4 * AT_TILE + 2 * AT_TILE; };
    auto sVl = [&](int st) { return tiles + st * 4 * AT_TILE + 3 * AT_TILE; };

    const int m = blockIdx.x, b = blockIdx.y;
    const int hbase = blockIdx.z * 2;
    const int tid = threadIdx.x, wid = tid >> 5, l = tid & 31;
    const size_t rowbase = ((size_t)b * Nn + m) * Nn;
    const float scale = 0.17677669529663687f;

    // group 0: bias map
    for (int idx = tid; idx < Nn * 40; idx += 320) {
        int row = idx / 40, c4 = idx % 40;
        CP16(smem_u32(mapS + row * MSTR + c4 * 4),
             mapsrc + (size_t)b * Nn * Nn + (size_t)row * Nn + c4 * 4);
    }
    CP_COMMIT;

    auto load_kv = [&](int h, int st) {
        for (int idx = tid; idx < Nn * 4; idx += 320) {
            int row = idx >> 2, seg = (idx & 3) * 8;
            size_t gro = (rowbase + row) * 768 + 256 + h * Dd;
            uint32_t so = (uint32_t)(row * ASTR + seg);
            CP16(smem_u32(sKh(st) + so), qkvh + gro + seg);
            CP16(smem_u32(sKl(st) + so), qkvl + gro + seg);
            CP16(smem_u32(sVh(st) + so), qkvh + gro + 256 + seg);
            CP16(smem_u32(sVl(st) + so), qkvl + gro + 256 + seg);
        }
        CP_COMMIT;
    };

    load_kv(hbase, 0);

    const int q0 = wid * 16;
    const int r0 = q0 + (l >> 2), r1 = r0 + 8;
    const int cpair = (l & 3) * 2;

    for (int e = 0; e < 2; e++) {
        const int h = hbase + e, st = e;
        if (e == 0) {
            load_kv(hbase + 1, 1);
            asm volatile("cp.async.wait_group 1;" ::: "memory");
        } else {
            asm volatile("cp.async.wait_group 0;" ::: "memory");
        }
        __syncthreads();

        const float wv = bw[h], bv = bb[h];

        // ---- Q a-frags straight from global ----
        uint32_t qh[2][4], ql[2][4];
        {
            const size_t g0 = (rowbase + r0) * 768 + h * Dd;
            const size_t g1 = (rowbase + r1) * 768 + h * Dd;
#pragma unroll
            for (int kc = 0; kc < 2; kc++) {
                int col = kc * 16 + cpair;
                qh[kc][0] = *reinterpret_cast<const uint32_t*>(qkvh + g0 + col);
                qh[kc][1] = *reinterpret_cast<const uint32_t*>(qkvh + g1 + col);
                qh[kc][2] = *reinterpret_cast<const uint32_t*>(qkvh + g0 + col + 8);
                qh[kc][3] = *reinterpret_cast<const uint32_t*>(qkvh + g1 + col + 8);
                ql[kc][0] = *reinterpret_cast<const uint32_t*>(qkvl + g0 + col);
                ql[kc][1] = *reinterpret_cast<const uint32_t*>(qkvl + g1 + col);
                ql[kc][2] = *reinterpret_cast<const uint32_t*>(qkvl + g0 + col + 8);
                ql[kc][3] = *reinterpret_cast<const uint32_t*>(qkvl + g1 + col + 8);
            }
        }

        // ---- S = 3-split Q@K^T ----
        float S[20][4];
#pragma unroll
        for (int nt = 0; nt < 20; nt++)
#pragma unroll
            for (int r = 0; r < 4; r++) S[nt][r] = 0.f;

        const uint32_t kHb = smem_u32(sKh(st)), kLb = smem_u32(sKl(st));
#pragma unroll
        for (int nt = 0; nt < 20; nt++) {
#pragma unroll
            for (int kc = 0; kc < 2; kc++) {
                uint32_t off = (uint32_t)((nt * 8 + (l & 7)) * ASTR) * 2 +
                               (((l >> 3) & 1) << 4) + kc * 32;
                uint32_t bh[2], bl2[2];
                LDSM_X2(bh[0], bh[1], kHb + off);
                LDSM_X2(bl2[0], bl2[1], kLb + off);
                MMA16816(S[nt], qh[kc], bh);
                MMA16816(S[nt], qh[kc], bl2);
                MMA16816(S[nt], ql[kc], bh);
            }
        }

        // ---- scale + bias ----
#pragma unroll
        for (int nt = 0; nt < 20; nt++) {
            int j0 = nt * 8 + cpair;
            S[nt][0] = S[nt][0] * scale + mapS[r0 * MSTR + j0]     * wv + bv;
            S[nt][1] = S[nt][1] * scale + mapS[r0 * MSTR + j0 + 1] * wv + bv;
            S[nt][2] = S[nt][2] * scale + mapS[r1 * MSTR + j0]     * wv + bv;
            S[nt][3] = S[nt][3] * scale + mapS[r1 * MSTR + j0 + 1] * wv + bv;
        }

        // ---- softmax ----
        float m0 = -INFINITY, m1 = -INFINITY;
#pragma unroll
        for (int nt = 0; nt < 20; nt++) {
            m0 = fmaxf(m0, fmaxf(S[nt][0], S[nt][1]));
            m1 = fmaxf(m1, fmaxf(S[nt][2], S[nt][3]));
        }
        m0 = fmaxf(m0, __shfl_xor_sync(0xffffffffu, m0, 1));
        m0 = fmaxf(m0, __shfl_xor_sync(0xffffffffu, m0, 2));
        m1 = fmaxf(m1, __shfl_xor_sync(0xffffffffu, m1, 1));
        m1 = fmaxf(m1, __shfl_xor_sync(0xffffffffu, m1, 2));

        float l0 = 0.f, l1 = 0.f;
#pragma unroll
        for (int nt = 0; nt < 20; nt++) {
            S[nt][0] = __expf(S[nt][0] - m0); l0 += S[nt][0];
            S[nt][1] = __expf(S[nt][1] - m0); l0 += S[nt][1];
            S[nt][2] = __expf(S[nt][2] - m1); l1 += S[nt][2];
            S[nt][3] = __expf(S[nt][3] - m1); l1 += S[nt][3];
        }
        l0 += __shfl_xor_sync(0xffffffffu, l0, 1);
        l0 += __shfl_xor_sync(0xffffffffu, l0, 2);
        l1 += __shfl_xor_sync(0xffffffffu, l1, 1);
        l1 += __shfl_xor_sync(0xffffffffu, l1, 2);

        // ---- O = 3-split P@V ----
        float O[4][4];
#pragma unroll
        for (int nt = 0; nt < 4; nt++)
#pragma unroll
            for (int r = 0; r < 4; r++) O[nt][r] = 0.f;

        const uint32_t vHb = smem_u32(sVh(st)), vLb = smem_u32(sVl(st));
#pragma unroll
        for (int kc = 0; kc < 10; kc++) {
            uint32_t aPh[4], aPl[4];
            split2(S[kc * 2][0],     S[kc * 2][1],     aPh[0], aPl[0]);
            split2(S[kc * 2][2],     S[kc * 2][3],     aPh[1], aPl[1]);
            split2(S[kc * 2 + 1][0], S[kc * 2 + 1][1], aPh[2], aPl[2]);
            split2(S[kc * 2 + 1][2], S[kc * 2 + 1][3], aPh[3], aPl[3]);

            uint32_t bvh[4][2], bvl[4][2];
#pragma unroll
            for (int dp = 0; dp < 2; dp++) {
                uint32_t off = (uint32_t)((kc * 16 + (l & 15)) * ASTR) * 2 +
                               ((l >> 4) << 4) + dp * 32;
                uint32_t rh[4], rl[4];
                LDSM_X4T(rh, vHb + off);
                LDSM_X4T(rl, vLb + off);
                bvh[dp * 2][0] = rh[0]; bvh[dp * 2][1] = rh[1];
                bvh[dp * 2 + 1][0] = rh[2]; bvh[dp * 2 + 1][1] = rh[3];
                bvl[dp * 2][0] = rl[0]; bvl[dp * 2][1] = rl[1];
                bvl[dp * 2 + 1][0] = rl[2]; bvl[dp * 2 + 1][1] = rl[3];
            }
#pragma unroll
            for (int nt = 0; nt < 4; nt++) {
                MMA16816(O[nt], aPh, bvh[nt]);
                MMA16816(O[nt], aPh, bvl[nt]);
                MMA16816(O[nt], aPl, bvh[nt]);
            }
        }

        // ---- normalize + write bf16 hi/lo ----
        const float inv0 = 1.f / l0, inv1 = 1.f / l1;
#pragma unroll
        for (int nt = 0; nt < 4; nt++) {
            int col = h * Dd + nt * 8 + cpair;
            uint32_t h0v, l0v, h1v, l1v;
            split2(O[nt][0] * inv0, O[nt][1] * inv0, h0v, l0v);
            split2(O[nt][2] * inv1, O[nt][3] * inv1, h1v, l1v);
            *reinterpret_cast<uint32_t*>(Ah + (rowbase + r0) * GK + col) = h0v;
            *reinterpret_cast<uint32_t*>(Al + (rowbase + r0) * GK + col) = l0v;
            *reinterpret_cast<uint32_t*>(Ah + (rowbase + r1) * GK + col) = h1v;
            *reinterpret_cast<uint32_t*>(Al + (rowbase + r1) * GK + col) = l1v;
        }
        if (e == 0) __syncthreads();
    }
}

// ---------------- Residual + LayerNorm: warp-per-row, no smem/syncs ----------------
__global__ __launch_bounds__(256) void ln_kernel(const float* __restrict__ xin,
                                                const float* __restrict__ proj,
                                                const float* __restrict__ g,
                                                const float* __restrict__ bt,
                                                float* __restrict__ out,
                                                __nv_bfloat16* __restrict__ Ah,
                                                __nv_bfloat16* __restrict__ Al) {
    const int wid = threadIdx.x >> 5, l = threadIdx.x & 31;
    const int r = blockIdx.x * 8 + wid;

    const float4* x4 = reinterpret_cast<const float4*>(xin + (size_t)r * Cc);
    const float4* p4 = reinterpret_cast<const float4*>(proj + (size_t)r * Cc);
    float4 v[2];
    float s = 0.f, s2 = 0.f;
#pragma unroll
    for (int k = 0; k < 2; k++) {
        float4 a = x4[l + k * 32], p = p4[l + k * 32];
        v[k] = make_float4(a.x + p.x, a.y + p.y, a.z + p.z, a.w + p.w);
        s  += v[k].x + v[k].y + v[k].z + v[k].w;
        s2 += v[k].x * v[k].x + v[k].y * v[k].y + v[k].z * v[k].z + v[k].w * v[k].w;
    }
#pragma unroll
    for (int o = 16; o > 0; o >>= 1) {
        s  += __shfl_xor_sync(0xffffffffu, s, o);
        s2 += __shfl_xor_sync(0xffffffffu, s2, o);
    }
    const float mean = s * (1.f / Cc);
    const float var  = s2 * (1.f / Cc) - mean * mean;
    const float rs   = rsqrtf(var + 1e-5f);

    const int bidx = r / (Nn * Nn);
    const int rem  = r % (Nn * Nn);
    const int mm   = rem / Nn;
    const int ii   = rem % Nn;
    const size_t rt = ((size_t)bidx * Nn + ii) * Nn + mm;

    const float4* g4 = reinterpret_cast<const float4*>(g);
    const float4* b4 = reinterpret_cast<const float4*>(bt);
    float4* o4 = reinterpret_cast<float4*>(out + rt * Cc);
#pragma unroll
    for (int k = 0; k < 2; k++) {
        float4 gg = g4[l + k * 32], bb2 = b4[l + k * 32];
        float4 y;
        y.x = (v[k].x - mean) * rs * gg.x + bb2.x;
        y.y = (v[k].y - mean) * rs * gg.y + bb2.y;
        y.z = (v[k].z - mean) * rs * gg.z + bb2.z;
        y.w = (v[k].w - mean) * rs * gg.w + bb2.w;
        o4[l + k * 32] = y;
        if (Ah) {
            uint32_t h0, l0, h1, l1;
            split2(y.x, y.y, h0, l0);
            split2(y.z, y.w, h1, l1);
            *reinterpret_cast<uint2*>(Ah + rt * GK + (l + k * 32) * 4) = make_uint2(h0, h1);
            *reinterpret_cast<uint2*>(Al + rt * GK + (l + k * 32) * 4) = make_uint2(l0, l1);
        }
    }
}

extern "C" void kernel_launch(void* const* d_in, const int* in_sizes, int n_in,
                              void* d_out, int out_size) {
    const float* pair      = (const float*)d_in[0];
    const float* bulk      = (const float*)d_in[1];
    const float* row_qkv_w = (const float*)d_in[2];
    const float* row_out_w = (const float*)d_in[3];
    const float* row_ln_g  = (const float*)d_in[4];
    const float* row_ln_b  = (const float*)d_in[5];
    const float* row_bw    = (const float*)d_in[6];
    const float* row_bb    = (const float*)d_in[7];
    const float* col_qkv_w = (const float*)d_in[8];
    const float* col_out_w = (const float*)d_in[9];
    const float* col_ln_g  = (const float*)d_in[10];
    const float* col_ln_b  = (const float*)d_in[11];
    const float* col_bw    = (const float*)d_in[12];
    const float* col_bb    = (const float*)d_in[13];
    float* out = (float*)d_out;

    float *proj, *x1, *mapT;
    __nv_bfloat16 *qkvh, *qkvl, *Ah, *Al, *Brq, *Bro, *Bcq, *Bco;
    cudaGetSymbolAddress((void**)&qkvh, g_qkvh);
    cudaGetSymbolAddress((void**)&qkvl, g_qkvl);
    cudaGetSymbolAddress((void**)&proj, g_proj);
    cudaGetSymbolAddress((void**)&x1,   g_x1);
    cudaGetSymbolAddress((void**)&mapT, g_mapT);
    cudaGetSymbolAddress((void**)&Ah,   g_Ah);
    cudaGetSymbolAddress((void**)&Al,   g_Al);
    cudaGetSymbolAddress((void**)&Brq,  g_Brq);
    cudaGetSymbolAddress((void**)&Bro,  g_Bro);
    cudaGetSymbolAddress((void**)&Bcq,  g_Bcq);
    cudaGetSymbolAddress((void**)&Bco,  g_Bco);

    cudaFuncSetAttribute(attn_mma, cudaFuncAttributeMaxDynamicSharedMemorySize, ATTN_SMEM);
    cudaFuncSetAttribute(gemm_mma, cudaFuncAttributeMaxDynamicSharedMemorySize, GSMEM);

    const int n4 = ROWS * GK / 4;
    const int gsplitA = (n4 + 255) / 256;
    const int nsplitW = 2 * GK * 768 + 2 * GK * 256;
    dim3 gq(768 / 128, ROWS / 128);
    dim3 gp(256 / 128, ROWS / 128);
    dim3 ga(Nn, Bb, Hh / 2);
    dim3 gt(Nn / 32, Nn / 32, Bb);

    // ---- prologue: all splits + map transpose ----
    splitW<<<(nsplitW + 255) / 256, 256>>>(row_qkv_w, row_out_w, col_qkv_w, col_out_w,
                                           Brq, Bro, Bcq, Bco);
    tmap_kernel<<<gt, dim3(32, 8)>>>(bulk, mapT);
    splitA<<<gsplitA, 256>>>((const float4*)pair, Ah, Al, n4);

    // ---- pass 1 (row attention): bias(i,j) = map[b,i,j] ----
    gemm_mma<<<gq, 256, GSMEM>>>(Ah, Al, Brq, nullptr, qkvh, qkvl, 768);
    attn_mma<<<ga, 320, ATTN_SMEM>>>(qkvh, qkvl, bulk, row_bw, row_bb, Ah, Al);
    gemm_mma<<<gp, 256, GSMEM>>>(Ah, Al, Bro, proj, nullptr, nullptr, 256);
    ln_kernel<<<ROWS / 8, 256>>>(pair, proj, row_ln_g, row_ln_b, x1, Ah, Al);

    // ---- pass 2 (column attention): bias(i,j) = map[b,j,i] = mapT[b,i,j] ----
    gemm_mma<<<gq, 256, GSMEM>>>(Ah, Al, Bcq, nullptr, qkvh, qkvl, 768);
    attn_mma<<<ga, 320, ATTN_SMEM>>>(qkvh, qkvl, mapT, col_bw, col_bb, Ah, Al);
    gemm_mma<<<gp, 256, GSMEM>>>(Ah, Al, Bco, proj, nullptr, nullptr, 256);
    ln_kernel<<<ROWS / 8, 256>>>(x1, proj, col_ln_g, col_ln_b, out, nullptr, nullptr);
}